// round 2
// baseline (speedup 1.0000x reference)
#include <cuda_runtime.h>

#define NDIM 512
#define DDIM 128
#define NN (NDIM*NDIM)

// Scratch (allocation-free rule: __device__ globals)
__device__ float g_L[(size_t)DDIM * NN];   // [c][i][k]
__device__ float g_R[(size_t)DDIM * NN];   // [c][j][k]
__device__ float g_T[(size_t)DDIM * NN];   // [c][i][j]

__device__ __forceinline__ float sigmoidf_(float x) {
    return 1.0f / (1.0f + __expf(-x));
}

__device__ __forceinline__ void outer4(float acc[4][4], float4 a, float4 b) {
    float av[4] = {a.x, a.y, a.z, a.w};
    float bv[4] = {b.x, b.y, b.z, b.w};
    #pragma unroll
    for (int i = 0; i < 4; i++)
        #pragma unroll
        for (int j = 0; j < 4; j++)
            acc[i][j] = fmaf(av[i], bv[j], acc[i][j]);
}

// ---------------------------------------------------------------------------
// Kernel 1: LN1 + lrp/gate projections + sigmoid gating -> g_L, g_R
// Block: 256 threads, 64 Z-rows. smem: s_z[64][132] + 3 x [128][68]
// ---------------------------------------------------------------------------
#define K1_SMEM (138240)

__global__ __launch_bounds__(256, 1)
void k1_proj(const float* __restrict__ Z, const float* __restrict__ mask,
             const float* __restrict__ ln1w, const float* __restrict__ ln1b,
             const float* __restrict__ lrpw, const float* __restrict__ lrpb,
             const float* __restrict__ gatew, const float* __restrict__ gateb)
{
    extern __shared__ float sm[];
    float* s_z  = sm;                  // [64][132] row-major
    float* s_zt = sm + 64 * 132;       // [128][68] transposed (k, row)
    float* s_wl = s_zt + 128 * 68;     // [128][68] (k, c)
    float* s_wg = s_wl + 128 * 68;     // [128][68]

    const int tid = threadIdx.x;
    const int r0 = blockIdx.x * 64;

    // Load Z tile (64 rows x 128)
    for (int idx = tid; idx < 64 * 32; idx += 256) {
        int rr = idx >> 5, kq = idx & 31;
        float4 v = reinterpret_cast<const float4*>(Z + (size_t)(r0 + rr) * DDIM)[kq];
        float* p = &s_z[rr * 132 + kq * 4];
        p[0] = v.x; p[1] = v.y; p[2] = v.z; p[3] = v.w;
    }
    __syncthreads();

    // LayerNorm per row (one warp per 8 rows)
    {
        int warp = tid >> 5, lane = tid & 31;
        for (int rr = warp * 8; rr < warp * 8 + 8; rr++) {
            float* row = &s_z[rr * 132];
            float4 v = *reinterpret_cast<float4*>(&row[lane * 4]);
            float s  = v.x + v.y + v.z + v.w;
            float s2 = v.x * v.x + v.y * v.y + v.z * v.z + v.w * v.w;
            #pragma unroll
            for (int o = 16; o; o >>= 1) {
                s  += __shfl_xor_sync(0xffffffffu, s, o);
                s2 += __shfl_xor_sync(0xffffffffu, s2, o);
            }
            float m = s * 0.0078125f;
            float var = fmaf(-m, m, s2 * 0.0078125f);
            float rstd = rsqrtf(var + 1e-5f);
            #pragma unroll
            for (int q = 0; q < 4; q++) {
                int k = lane * 4 + q;
                row[k] = (row[k] - m) * rstd * ln1w[k] + ln1b[k];
            }
        }
    }
    __syncthreads();

    // Transpose normalized z -> s_zt[k][row]
    for (int idx = tid; idx < 64 * 32; idx += 256) {
        int rr = idx >> 5, kq = idx & 31;
        float4 v = *reinterpret_cast<float4*>(&s_z[rr * 132 + kq * 4]);
        s_zt[(kq * 4 + 0) * 68 + rr] = v.x;
        s_zt[(kq * 4 + 1) * 68 + rr] = v.y;
        s_zt[(kq * 4 + 2) * 68 + rr] = v.z;
        s_zt[(kq * 4 + 3) * 68 + rr] = v.w;
    }

    const int tx = tid & 15, ty = tid >> 4;
    float maskv[4];
    #pragma unroll
    for (int i = 0; i < 4; i++) maskv[i] = mask[r0 + ty * 4 + i];

    for (int ct = 0; ct < 4; ct++) {   // 4 tiles of 64 output channels (256 total)
        __syncthreads();
        // Load weight tiles transposed: (c rows, k) -> s_w*[k][c]
        for (int idx = tid; idx < 64 * 32; idx += 256) {
            int cc = idx >> 5, kq = idx & 31;
            float4 wl = reinterpret_cast<const float4*>(lrpw  + (size_t)(ct * 64 + cc) * DDIM)[kq];
            float4 wg = reinterpret_cast<const float4*>(gatew + (size_t)(ct * 64 + cc) * DDIM)[kq];
            s_wl[(kq * 4 + 0) * 68 + cc] = wl.x;
            s_wl[(kq * 4 + 1) * 68 + cc] = wl.y;
            s_wl[(kq * 4 + 2) * 68 + cc] = wl.z;
            s_wl[(kq * 4 + 3) * 68 + cc] = wl.w;
            s_wg[(kq * 4 + 0) * 68 + cc] = wg.x;
            s_wg[(kq * 4 + 1) * 68 + cc] = wg.y;
            s_wg[(kq * 4 + 2) * 68 + cc] = wg.z;
            s_wg[(kq * 4 + 3) * 68 + cc] = wg.w;
        }
        __syncthreads();

        float accl[4][4] = {}, accg[4][4] = {};
        #pragma unroll 8
        for (int k = 0; k < 128; k++) {
            float4 a  = *reinterpret_cast<float4*>(&s_zt[k * 68 + ty * 4]);
            float4 bl = *reinterpret_cast<float4*>(&s_wl[k * 68 + tx * 4]);
            float4 bg = *reinterpret_cast<float4*>(&s_wg[k * 68 + tx * 4]);
            outer4(accl, a, bl);
            outer4(accg, a, bg);
        }

        #pragma unroll
        for (int i = 0; i < 4; i++) {
            size_t r = (size_t)r0 + ty * 4 + i;
            #pragma unroll
            for (int j = 0; j < 4; j++) {
                int c = ct * 64 + tx * 4 + j;
                float g = sigmoidf_(accg[i][j] + gateb[c]);
                float val = (accl[i][j] + lrpb[c]) * maskv[i] * g;
                if (c < 128) g_L[(size_t)c * NN + r] = val;
                else         g_R[(size_t)(c - 128) * NN + r] = val;
            }
        }
    }
}

// ---------------------------------------------------------------------------
// Kernel 2: per-channel GEMM  T_c = L_c @ R_c^T   (128 x [512x512x512])
// grid (8,8,128), block 256, tile 64x64, K-tile 32, thread 4x4
// ---------------------------------------------------------------------------
__global__ __launch_bounds__(256, 2)
void k2_tri()
{
    __shared__ float s_a[32][68];
    __shared__ float s_b[32][68];
    const int c = blockIdx.z;
    const float* A = g_L + (size_t)c * NN;
    const float* B = g_R + (size_t)c * NN;
    float* Tc = g_T + (size_t)c * NN;
    const int i0 = blockIdx.x * 64, j0 = blockIdx.y * 64;
    const int tid = threadIdx.x, tx = tid & 15, ty = tid >> 4;

    float acc[4][4] = {};
    for (int k0 = 0; k0 < 512; k0 += 32) {
        __syncthreads();
        for (int idx = tid; idx < 512; idx += 256) {
            int rr = idx >> 3, kq = idx & 7;
            float4 va = reinterpret_cast<const float4*>(A + (size_t)(i0 + rr) * NDIM + k0)[kq];
            float4 vb = reinterpret_cast<const float4*>(B + (size_t)(j0 + rr) * NDIM + k0)[kq];
            s_a[kq * 4 + 0][rr] = va.x; s_a[kq * 4 + 1][rr] = va.y;
            s_a[kq * 4 + 2][rr] = va.z; s_a[kq * 4 + 3][rr] = va.w;
            s_b[kq * 4 + 0][rr] = vb.x; s_b[kq * 4 + 1][rr] = vb.y;
            s_b[kq * 4 + 2][rr] = vb.z; s_b[kq * 4 + 3][rr] = vb.w;
        }
        __syncthreads();
        #pragma unroll 8
        for (int k = 0; k < 32; k++) {
            float4 a = *reinterpret_cast<const float4*>(&s_a[k][ty * 4]);
            float4 b = *reinterpret_cast<const float4*>(&s_b[k][tx * 4]);
            outer4(acc, a, b);
        }
    }
    #pragma unroll
    for (int i = 0; i < 4; i++) {
        float4 o = make_float4(acc[i][0], acc[i][1], acc[i][2], acc[i][3]);
        *reinterpret_cast<float4*>(&Tc[(size_t)(i0 + ty * 4 + i) * NDIM + j0 + tx * 4]) = o;
    }
}

// ---------------------------------------------------------------------------
// Kernel 3: gather tri rows, LN2, og/op matmuls, gated residual epilogue
// Block: 256 threads, 64 rows. smem: s_t[64][132] + 4 x [128][68]
// ---------------------------------------------------------------------------
#define K3_SMEM (173056)

__global__ __launch_bounds__(256, 1)
void k3_out(const float* __restrict__ ogw, const float* __restrict__ ogb,
            const float* __restrict__ ln2w, const float* __restrict__ ln2b,
            const float* __restrict__ opw, const float* __restrict__ outb,
            float* __restrict__ out)
{
    extern __shared__ float sm[];
    float* s_t  = sm;                  // [64][132] tri rows, row-major
    float* s_tt = sm + 64 * 132;       // [128][68] tri transposed (c, row)
    float* s_zt = s_tt + 128 * 68;     // [128][68] LN2(tri) transposed
    float* s_wo = s_zt + 128 * 68;     // [128][68] og_w (c, d)
    float* s_wp = s_wo + 128 * 68;     // [128][68] op_w (c, d)

    const int tid = threadIdx.x;
    const int r0 = blockIdx.x * 64;

    // Gather tri tile: s_t[rr][c] = T[c][r0+rr]
    for (int idx = tid; idx < 64 * 128; idx += 256) {
        int cch = idx >> 6, rr = idx & 63;
        s_t[rr * 132 + cch] = g_T[(size_t)cch * NN + r0 + rr];
    }
    __syncthreads();

    // LN2 per row; fill transposed buffers
    {
        int warp = tid >> 5, lane = tid & 31;
        for (int rr = warp * 8; rr < warp * 8 + 8; rr++) {
            float* row = &s_t[rr * 132];
            float4 v = *reinterpret_cast<float4*>(&row[lane * 4]);
            float s  = v.x + v.y + v.z + v.w;
            float s2 = v.x * v.x + v.y * v.y + v.z * v.z + v.w * v.w;
            #pragma unroll
            for (int o = 16; o; o >>= 1) {
                s  += __shfl_xor_sync(0xffffffffu, s, o);
                s2 += __shfl_xor_sync(0xffffffffu, s2, o);
            }
            float m = s * 0.0078125f;
            float var = fmaf(-m, m, s2 * 0.0078125f);
            float rstd = rsqrtf(var + 1e-5f);
            #pragma unroll
            for (int q = 0; q < 4; q++) {
                int cch = lane * 4 + q;
                float t = row[cch];
                s_tt[cch * 68 + rr] = t;
                s_zt[cch * 68 + rr] = (t - m) * rstd * ln2w[cch] + ln2b[cch];
            }
        }
    }

    const int tx = tid & 15, ty = tid >> 4;

    for (int dt = 0; dt < 2; dt++) {   // two 64-col tiles over 128 outputs
        __syncthreads();
        for (int idx = tid; idx < 64 * 32; idx += 256) {
            int dd = idx >> 5, kq = idx & 31;
            float4 wo = reinterpret_cast<const float4*>(ogw + (size_t)(dt * 64 + dd) * DDIM)[kq];
            float4 wp = reinterpret_cast<const float4*>(opw + (size_t)(dt * 64 + dd) * DDIM)[kq];
            s_wo[(kq * 4 + 0) * 68 + dd] = wo.x;
            s_wo[(kq * 4 + 1) * 68 + dd] = wo.y;
            s_wo[(kq * 4 + 2) * 68 + dd] = wo.z;
            s_wo[(kq * 4 + 3) * 68 + dd] = wo.w;
            s_wp[(kq * 4 + 0) * 68 + dd] = wp.x;
            s_wp[(kq * 4 + 1) * 68 + dd] = wp.y;
            s_wp[(kq * 4 + 2) * 68 + dd] = wp.z;
            s_wp[(kq * 4 + 3) * 68 + dd] = wp.w;
        }
        __syncthreads();

        float accg[4][4] = {}, accz[4][4] = {};
        #pragma unroll 8
        for (int k = 0; k < 128; k++) {
            float4 at = *reinterpret_cast<float4*>(&s_tt[k * 68 + ty * 4]);
            float4 az = *reinterpret_cast<float4*>(&s_zt[k * 68 + ty * 4]);
            float4 wo = *reinterpret_cast<float4*>(&s_wo[k * 68 + tx * 4]);
            float4 wp = *reinterpret_cast<float4*>(&s_wp[k * 68 + tx * 4]);
            outer4(accg, at, wo);
            outer4(accz, az, wp);
        }

        #pragma unroll
        for (int i = 0; i < 4; i++) {
            int rloc = ty * 4 + i;
            size_t r = (size_t)r0 + rloc;
            #pragma unroll
            for (int j = 0; j < 4; j++) {
                int d = dt * 64 + tx * 4 + j;
                float tval = s_t[rloc * 132 + d];
                float go = sigmoidf_(accg[i][j] + ogb[d]);
                out[r * DDIM + d] = tval + go * (accz[i][j] + outb[d]);
            }
        }
    }
}

// ---------------------------------------------------------------------------
extern "C" void kernel_launch(void* const* d_in, const int* in_sizes, int n_in,
                              void* d_out, int out_size)
{
    const float* Z     = (const float*)d_in[0];   // [1,512,512,128]
    const float* mask  = (const float*)d_in[1];   // [1,512,512]
    const float* ln1w  = (const float*)d_in[2];
    const float* ln1b  = (const float*)d_in[3];
    const float* lrpw  = (const float*)d_in[4];   // [256,128]
    const float* lrpb  = (const float*)d_in[5];
    const float* gatew = (const float*)d_in[6];   // [256,128]
    const float* gateb = (const float*)d_in[7];
    const float* ogw   = (const float*)d_in[8];   // [128,128]
    const float* ogb   = (const float*)d_in[9];
    const float* ln2w  = (const float*)d_in[10];
    const float* ln2b  = (const float*)d_in[11];
    const float* opw   = (const float*)d_in[12];  // [128,128]
    const float* outb  = (const float*)d_in[13];
    float* out = (float*)d_out;

    cudaFuncSetAttribute(k1_proj, cudaFuncAttributeMaxDynamicSharedMemorySize, K1_SMEM);
    cudaFuncSetAttribute(k3_out,  cudaFuncAttributeMaxDynamicSharedMemorySize, K3_SMEM);

    k1_proj<<<NN / 64, 256, K1_SMEM>>>(Z, mask, ln1w, ln1b, lrpw, lrpb, gatew, gateb);

    dim3 g2(8, 8, 128);
    k2_tri<<<g2, 256>>>();

    k3_out<<<NN / 64, 256, K3_SMEM>>>(ogw, ogb, ln2w, ln2b, opw, outb, out);
}

// round 4
// speedup vs baseline: 1.0672x; 1.0672x over previous
#include <cuda_runtime.h>
#include <cuda_bf16.h>
#include <cstdint>

#define NDIM 512
#define DDIM 128
#define NN (NDIM*NDIM)

// Scratch (allocation-free rule: __device__ globals)
__device__ __nv_bfloat16 g_Lhi[(size_t)DDIM * NN];   // [c][i][k]
__device__ __nv_bfloat16 g_Llo[(size_t)DDIM * NN];
__device__ __nv_bfloat16 g_Rhi[(size_t)DDIM * NN];   // [c][j][k]
__device__ __nv_bfloat16 g_Rlo[(size_t)DDIM * NN];
__device__ float g_T[(size_t)DDIM * NN];             // [c][i][j]

__device__ __forceinline__ float sigmoidf_(float x) {
    return 1.0f / (1.0f + __expf(-x));
}

__device__ __forceinline__ void outer4(float acc[4][4], float4 a, float4 b) {
    float av[4] = {a.x, a.y, a.z, a.w};
    float bv[4] = {b.x, b.y, b.z, b.w};
    #pragma unroll
    for (int i = 0; i < 4; i++)
        #pragma unroll
        for (int j = 0; j < 4; j++)
            acc[i][j] = fmaf(av[i], bv[j], acc[i][j]);
}

__device__ __forceinline__ uint32_t smem_u32(const void* p) {
    uint32_t a;
    asm("{ .reg .u64 t; cvta.to.shared.u64 t, %1; cvt.u32.u64 %0, t; }" : "=r"(a) : "l"(p));
    return a;
}

// ---------------------------------------------------------------------------
// Kernel 1: LN1 + lrp/gate projections + sigmoid gating -> split-bf16 L/R
// ---------------------------------------------------------------------------
#define K1_SMEM (138240)

__global__ __launch_bounds__(256, 1)
void k1_proj(const float* __restrict__ Z, const float* __restrict__ mask,
             const float* __restrict__ ln1w, const float* __restrict__ ln1b,
             const float* __restrict__ lrpw, const float* __restrict__ lrpb,
             const float* __restrict__ gatew, const float* __restrict__ gateb)
{
    extern __shared__ float sm[];
    float* s_z  = sm;                  // [64][132] row-major
    float* s_zt = sm + 64 * 132;       // [128][68] transposed (k, row)
    float* s_wl = s_zt + 128 * 68;     // [128][68] (k, c)
    float* s_wg = s_wl + 128 * 68;     // [128][68]

    const int tid = threadIdx.x;
    const int r0 = blockIdx.x * 64;

    for (int idx = tid; idx < 64 * 32; idx += 256) {
        int rr = idx >> 5, kq = idx & 31;
        float4 v = reinterpret_cast<const float4*>(Z + (size_t)(r0 + rr) * DDIM)[kq];
        float* p = &s_z[rr * 132 + kq * 4];
        p[0] = v.x; p[1] = v.y; p[2] = v.z; p[3] = v.w;
    }
    __syncthreads();

    {
        int warp = tid >> 5, lane = tid & 31;
        for (int rr = warp * 8; rr < warp * 8 + 8; rr++) {
            float* row = &s_z[rr * 132];
            float4 v = *reinterpret_cast<float4*>(&row[lane * 4]);
            float s  = v.x + v.y + v.z + v.w;
            float s2 = v.x * v.x + v.y * v.y + v.z * v.z + v.w * v.w;
            #pragma unroll
            for (int o = 16; o; o >>= 1) {
                s  += __shfl_xor_sync(0xffffffffu, s, o);
                s2 += __shfl_xor_sync(0xffffffffu, s2, o);
            }
            float m = s * 0.0078125f;
            float var = fmaf(-m, m, s2 * 0.0078125f);
            float rstd = rsqrtf(var + 1e-5f);
            #pragma unroll
            for (int q = 0; q < 4; q++) {
                int k = lane * 4 + q;
                row[k] = (row[k] - m) * rstd * ln1w[k] + ln1b[k];
            }
        }
    }
    __syncthreads();

    for (int idx = tid; idx < 64 * 32; idx += 256) {
        int rr = idx >> 5, kq = idx & 31;
        float4 v = *reinterpret_cast<float4*>(&s_z[rr * 132 + kq * 4]);
        s_zt[(kq * 4 + 0) * 68 + rr] = v.x;
        s_zt[(kq * 4 + 1) * 68 + rr] = v.y;
        s_zt[(kq * 4 + 2) * 68 + rr] = v.z;
        s_zt[(kq * 4 + 3) * 68 + rr] = v.w;
    }

    const int tx = tid & 15, ty = tid >> 4;
    float maskv[4];
    #pragma unroll
    for (int i = 0; i < 4; i++) maskv[i] = mask[r0 + ty * 4 + i];

    for (int ct = 0; ct < 4; ct++) {
        __syncthreads();
        for (int idx = tid; idx < 64 * 32; idx += 256) {
            int cc = idx >> 5, kq = idx & 31;
            float4 wl = reinterpret_cast<const float4*>(lrpw  + (size_t)(ct * 64 + cc) * DDIM)[kq];
            float4 wg = reinterpret_cast<const float4*>(gatew + (size_t)(ct * 64 + cc) * DDIM)[kq];
            s_wl[(kq * 4 + 0) * 68 + cc] = wl.x;
            s_wl[(kq * 4 + 1) * 68 + cc] = wl.y;
            s_wl[(kq * 4 + 2) * 68 + cc] = wl.z;
            s_wl[(kq * 4 + 3) * 68 + cc] = wl.w;
            s_wg[(kq * 4 + 0) * 68 + cc] = wg.x;
            s_wg[(kq * 4 + 1) * 68 + cc] = wg.y;
            s_wg[(kq * 4 + 2) * 68 + cc] = wg.z;
            s_wg[(kq * 4 + 3) * 68 + cc] = wg.w;
        }
        __syncthreads();

        float accl[4][4] = {}, accg[4][4] = {};
        #pragma unroll 8
        for (int k = 0; k < 128; k++) {
            float4 a  = *reinterpret_cast<float4*>(&s_zt[k * 68 + ty * 4]);
            float4 bl = *reinterpret_cast<float4*>(&s_wl[k * 68 + tx * 4]);
            float4 bg = *reinterpret_cast<float4*>(&s_wg[k * 68 + tx * 4]);
            outer4(accl, a, bl);
            outer4(accg, a, bg);
        }

        #pragma unroll
        for (int i = 0; i < 4; i++) {
            size_t r = (size_t)r0 + ty * 4 + i;
            #pragma unroll
            for (int j = 0; j < 4; j++) {
                int c = ct * 64 + tx * 4 + j;
                float g = sigmoidf_(accg[i][j] + gateb[c]);
                float val = (accl[i][j] + lrpb[c]) * maskv[i] * g;
                __nv_bfloat16 hi = __float2bfloat16(val);
                __nv_bfloat16 lo = __float2bfloat16(val - __bfloat162float(hi));
                if (c < 128) {
                    g_Lhi[(size_t)c * NN + r] = hi;
                    g_Llo[(size_t)c * NN + r] = lo;
                } else {
                    g_Rhi[(size_t)(c - 128) * NN + r] = hi;
                    g_Rlo[(size_t)(c - 128) * NN + r] = lo;
                }
            }
        }
    }
}

// ---------------------------------------------------------------------------
// Kernel 2: split-bf16 mma.sync GEMM  T_c = L_c @ R_c^T
// grid (4,4,128), 256 threads (8 warps, 4x2), CTA tile 128x128, K-chunk 64,
// 2-stage cp.async pipeline. SW128 swizzled smem, ldmatrix fragments.
// ---------------------------------------------------------------------------
#define PLANE 16384                       // 128 rows x 128 bytes
#define STAGE (4 * PLANE)                 // Ah, Al, Bh, Bl
#define K2_SMEM (2 * STAGE)               // 131072

__device__ __forceinline__ uint32_t sw128(uint32_t bo) {
    return bo ^ ((bo >> 3) & 0x70);
}

__device__ __forceinline__ void cp16(uint32_t dst, const void* src) {
    asm volatile("cp.async.cg.shared.global [%0], [%1], 16;" :: "r"(dst), "l"(src) : "memory");
}
#define CP_COMMIT() asm volatile("cp.async.commit_group;" ::: "memory")
#define CP_WAIT0()  asm volatile("cp.async.wait_group 0;" ::: "memory")

__device__ __forceinline__ void ldm_x4(uint32_t r[4], uint32_t addr) {
    asm volatile("ldmatrix.sync.aligned.m8n8.x4.shared.b16 {%0,%1,%2,%3}, [%4];"
        : "=r"(r[0]), "=r"(r[1]), "=r"(r[2]), "=r"(r[3]) : "r"(addr));
}

__device__ __forceinline__ void mma16816(float c[4], const uint32_t a[4],
                                         uint32_t b0, uint32_t b1) {
    asm volatile("mma.sync.aligned.m16n8k16.row.col.f32.bf16.bf16.f32 "
        "{%0,%1,%2,%3}, {%4,%5,%6,%7}, {%8,%9}, {%0,%1,%2,%3};"
        : "+f"(c[0]), "+f"(c[1]), "+f"(c[2]), "+f"(c[3])
        : "r"(a[0]), "r"(a[1]), "r"(a[2]), "r"(a[3]), "r"(b0), "r"(b1));
}

__device__ __forceinline__ void k2_prefetch(uint32_t sbase, int stage,
    const __nv_bfloat16* Ah, const __nv_bfloat16* Al,
    const __nv_bfloat16* Bh, const __nv_bfloat16* Bl,
    int i0, int j0, int k0, int tid)
{
    const __nv_bfloat16* srcs[4] = {Ah, Al, Bh, Bl};
    const int bases[4] = {i0, i0, j0, j0};
    uint32_t st = sbase + stage * STAGE;
    #pragma unroll
    for (int p = 0; p < 4; p++) {
        const __nv_bfloat16* s = srcs[p];
        int rb = bases[p];
        #pragma unroll
        for (int it = 0; it < 4; it++) {
            int idx = it * 256 + tid;            // 1024 chunks of 16B
            int r = idx >> 3, q = idx & 7;
            uint32_t dst = st + p * PLANE + sw128((uint32_t)(r * 128 + q * 16));
            cp16(dst, s + (size_t)(rb + r) * NDIM + k0 + q * 8);
        }
    }
}

__global__ __launch_bounds__(256, 1)
void k2_tri_mma()
{
    extern __shared__ __align__(1024) char smc[];
    const uint32_t sbase = smem_u32(smc);
    const int tid = threadIdx.x;
    const int warp = tid >> 5;
    const uint32_t lane = tid & 31;
    const int c = blockIdx.z;
    const int i0 = blockIdx.x * 128, j0 = blockIdx.y * 128;

    const __nv_bfloat16* __restrict__ Ah = g_Lhi + (size_t)c * NN;
    const __nv_bfloat16* __restrict__ Al = g_Llo + (size_t)c * NN;
    const __nv_bfloat16* __restrict__ Bh = g_Rhi + (size_t)c * NN;
    const __nv_bfloat16* __restrict__ Bl = g_Rlo + (size_t)c * NN;
    float* __restrict__ Tc = g_T + (size_t)c * NN;

    const int wm = (warp >> 1) * 32;     // warp row base within tile
    const int wn = (warp & 1) * 64;      // warp col base within tile

    // ldmatrix lane-address components
    const uint32_t a_row = (lane & 7) + ((lane >> 3) & 1) * 8;  // within 16-row group
    const uint32_t a_kb  = (lane >> 4) * 16;                    // byte offset within k16
    const uint32_t b_row = (lane & 7) + ((lane >> 4) & 1) * 8;  // within 16-n group
    const uint32_t b_kb  = ((lane >> 3) & 1) * 16;

    float acc[2][8][4];
    #pragma unroll
    for (int mt = 0; mt < 2; mt++)
        #pragma unroll
        for (int nt = 0; nt < 8; nt++)
            #pragma unroll
            for (int q = 0; q < 4; q++) acc[mt][nt][q] = 0.0f;

    k2_prefetch(sbase, 0, Ah, Al, Bh, Bl, i0, j0, 0, tid);
    CP_COMMIT();

    #pragma unroll 1
    for (int ch = 0; ch < 8; ch++) {
        CP_WAIT0();
        __syncthreads();
        if (ch + 1 < 8) {
            k2_prefetch(sbase, (ch + 1) & 1, Ah, Al, Bh, Bl, i0, j0, (ch + 1) * 64, tid);
            CP_COMMIT();
        }
        uint32_t st = sbase + (ch & 1) * STAGE;
        uint32_t sAh = st, sAl = st + PLANE, sBh = st + 2 * PLANE, sBl = st + 3 * PLANE;

        #pragma unroll
        for (int ks = 0; ks < 4; ks++) {
            uint32_t kb = ks * 32;
            uint32_t ah[2][4], al[2][4];
            #pragma unroll
            for (int mt = 0; mt < 2; mt++) {
                uint32_t bo = (uint32_t)((wm + mt * 16 + a_row) * 128) + kb + a_kb;
                uint32_t sw = sw128(bo);
                ldm_x4(ah[mt], sAh + sw);
                ldm_x4(al[mt], sAl + sw);
            }
            #pragma unroll
            for (int ng = 0; ng < 4; ng++) {
                uint32_t bo = (uint32_t)((wn + ng * 16 + b_row) * 128) + kb + b_kb;
                uint32_t sw = sw128(bo);
                uint32_t bh[4], bl[4];
                ldm_x4(bh, sBh + sw);
                ldm_x4(bl, sBl + sw);
                #pragma unroll
                for (int mt = 0; mt < 2; mt++) {
                    #pragma unroll
                    for (int h = 0; h < 2; h++) {
                        float* cc = acc[mt][ng * 2 + h];
                        mma16816(cc, ah[mt], bh[h * 2], bh[h * 2 + 1]);
                        mma16816(cc, ah[mt], bl[h * 2], bl[h * 2 + 1]);
                        mma16816(cc, al[mt], bh[h * 2], bh[h * 2 + 1]);
                    }
                }
            }
        }
        __syncthreads();
    }

    // epilogue: accumulator -> g_T
    const int rbase = i0 + wm + (int)(lane >> 2);
    const int cbase = j0 + wn + 2 * (int)(lane & 3);
    #pragma unroll
    for (int mt = 0; mt < 2; mt++) {
        #pragma unroll
        for (int nt = 0; nt < 8; nt++) {
            float* cc = acc[mt][nt];
            int col = cbase + nt * 8;
            int r1 = rbase + mt * 16;
            *reinterpret_cast<float2*>(&Tc[(size_t)r1 * NDIM + col])       = make_float2(cc[0], cc[1]);
            *reinterpret_cast<float2*>(&Tc[(size_t)(r1 + 8) * NDIM + col]) = make_float2(cc[2], cc[3]);
        }
    }
}

// ---------------------------------------------------------------------------
// Kernel 3: gather tri rows, LN2, og/op matmuls, gated residual epilogue
// ---------------------------------------------------------------------------
#define K3_SMEM (173056)

__global__ __launch_bounds__(256, 1)
void k3_out(const float* __restrict__ ogw, const float* __restrict__ ogb,
            const float* __restrict__ ln2w, const float* __restrict__ ln2b,
            const float* __restrict__ opw, const float* __restrict__ outb,
            float* __restrict__ out)
{
    extern __shared__ float sm[];
    float* s_t  = sm;                  // [64][132]
    float* s_tt = sm + 64 * 132;       // [128][68]
    float* s_zt = s_tt + 128 * 68;     // [128][68]
    float* s_wo = s_zt + 128 * 68;     // [128][68]
    float* s_wp = s_wo + 128 * 68;     // [128][68]

    const int tid = threadIdx.x;
    const int r0 = blockIdx.x * 64;

    for (int idx = tid; idx < 64 * 128; idx += 256) {
        int cch = idx >> 6, rr = idx & 63;
        s_t[rr * 132 + cch] = g_T[(size_t)cch * NN + r0 + rr];
    }
    __syncthreads();

    {
        int warp = tid >> 5, lane = tid & 31;
        for (int rr = warp * 8; rr < warp * 8 + 8; rr++) {
            float* row = &s_t[rr * 132];
            float4 v = *reinterpret_cast<float4*>(&row[lane * 4]);
            float s  = v.x + v.y + v.z + v.w;
            float s2 = v.x * v.x + v.y * v.y + v.z * v.z + v.w * v.w;
            #pragma unroll
            for (int o = 16; o; o >>= 1) {
                s  += __shfl_xor_sync(0xffffffffu, s, o);
                s2 += __shfl_xor_sync(0xffffffffu, s2, o);
            }
            float m = s * 0.0078125f;
            float var = fmaf(-m, m, s2 * 0.0078125f);
            float rstd = rsqrtf(var + 1e-5f);
            #pragma unroll
            for (int q = 0; q < 4; q++) {
                int cch = lane * 4 + q;
                float t = row[cch];
                s_tt[cch * 68 + rr] = t;
                s_zt[cch * 68 + rr] = (t - m) * rstd * ln2w[cch] + ln2b[cch];
            }
        }
    }

    const int tx = tid & 15, ty = tid >> 4;

    for (int dt = 0; dt < 2; dt++) {
        __syncthreads();
        for (int idx = tid; idx < 64 * 32; idx += 256) {
            int dd = idx >> 5, kq = idx & 31;
            float4 wo = reinterpret_cast<const float4*>(ogw + (size_t)(dt * 64 + dd) * DDIM)[kq];
            float4 wp = reinterpret_cast<const float4*>(opw + (size_t)(dt * 64 + dd) * DDIM)[kq];
            s_wo[(kq * 4 + 0) * 68 + dd] = wo.x;
            s_wo[(kq * 4 + 1) * 68 + dd] = wo.y;
            s_wo[(kq * 4 + 2) * 68 + dd] = wo.z;
            s_wo[(kq * 4 + 3) * 68 + dd] = wo.w;
            s_wp[(kq * 4 + 0) * 68 + dd] = wp.x;
            s_wp[(kq * 4 + 1) * 68 + dd] = wp.y;
            s_wp[(kq * 4 + 2) * 68 + dd] = wp.z;
            s_wp[(kq * 4 + 3) * 68 + dd] = wp.w;
        }
        __syncthreads();

        float accg[4][4] = {}, accz[4][4] = {};
        #pragma unroll 8
        for (int k = 0; k < 128; k++) {
            float4 at = *reinterpret_cast<float4*>(&s_tt[k * 68 + ty * 4]);
            float4 az = *reinterpret_cast<float4*>(&s_zt[k * 68 + ty * 4]);
            float4 wo = *reinterpret_cast<float4*>(&s_wo[k * 68 + tx * 4]);
            float4 wp = *reinterpret_cast<float4*>(&s_wp[k * 68 + tx * 4]);
            outer4(accg, at, wo);
            outer4(accz, az, wp);
        }

        #pragma unroll
        for (int i = 0; i < 4; i++) {
            int rloc = ty * 4 + i;
            size_t r = (size_t)r0 + rloc;
            #pragma unroll
            for (int j = 0; j < 4; j++) {
                int d = dt * 64 + tx * 4 + j;
                float tval = s_t[rloc * 132 + d];
                float go = sigmoidf_(accg[i][j] + ogb[d]);
                out[r * DDIM + d] = tval + go * (accz[i][j] + outb[d]);
            }
        }
    }
}

// ---------------------------------------------------------------------------
extern "C" void kernel_launch(void* const* d_in, const int* in_sizes, int n_in,
                              void* d_out, int out_size)
{
    const float* Z     = (const float*)d_in[0];
    const float* mask  = (const float*)d_in[1];
    const float* ln1w  = (const float*)d_in[2];
    const float* ln1b  = (const float*)d_in[3];
    const float* lrpw  = (const float*)d_in[4];
    const float* lrpb  = (const float*)d_in[5];
    const float* gatew = (const float*)d_in[6];
    const float* gateb = (const float*)d_in[7];
    const float* ogw   = (const float*)d_in[8];
    const float* ogb   = (const float*)d_in[9];
    const float* ln2w  = (const float*)d_in[10];
    const float* ln2b  = (const float*)d_in[11];
    const float* opw   = (const float*)d_in[12];
    const float* outb  = (const float*)d_in[13];
    float* out = (float*)d_out;

    cudaFuncSetAttribute(k1_proj,    cudaFuncAttributeMaxDynamicSharedMemorySize, K1_SMEM);
    cudaFuncSetAttribute(k2_tri_mma, cudaFuncAttributeMaxDynamicSharedMemorySize, K2_SMEM);
    cudaFuncSetAttribute(k3_out,     cudaFuncAttributeMaxDynamicSharedMemorySize, K3_SMEM);

    k1_proj<<<NN / 64, 256, K1_SMEM>>>(Z, mask, ln1w, ln1b, lrpw, lrpb, gatew, gateb);

    dim3 g2(4, 4, 128);
    k2_tri_mma<<<g2, 256, K2_SMEM>>>();

    k3_out<<<NN / 64, 256, K3_SMEM>>>(ogw, ogb, ln2w, ln2b, opw, outb, out);
}

// round 5
// speedup vs baseline: 1.8890x; 1.7700x over previous
#include <cuda_runtime.h>
#include <cuda_bf16.h>
#include <cstdint>

#define NDIM 512
#define DDIM 128
#define NN (NDIM*NDIM)

// Scratch (allocation-free rule: __device__ globals)
__device__ __nv_bfloat16 g_Lhi[(size_t)DDIM * NN];   // [c][i][k]
__device__ __nv_bfloat16 g_Llo[(size_t)DDIM * NN];
__device__ __nv_bfloat16 g_Rhi[(size_t)DDIM * NN];   // [c][j][k]
__device__ __nv_bfloat16 g_Rlo[(size_t)DDIM * NN];
__device__ float g_T[(size_t)DDIM * NN];             // [c][i][j]
// split-bf16 weights for stage-1 (prepped by k0)
__device__ __nv_bfloat16 g_Wl_hi[256 * 128];
__device__ __nv_bfloat16 g_Wl_lo[256 * 128];
__device__ __nv_bfloat16 g_Wg_hi[256 * 128];
__device__ __nv_bfloat16 g_Wg_lo[256 * 128];

__device__ __forceinline__ float sigmoidf_(float x) {
    return 1.0f / (1.0f + __expf(-x));
}

__device__ __forceinline__ void outer4(float acc[4][4], float4 a, float4 b) {
    float av[4] = {a.x, a.y, a.z, a.w};
    float bv[4] = {b.x, b.y, b.z, b.w};
    #pragma unroll
    for (int i = 0; i < 4; i++)
        #pragma unroll
        for (int j = 0; j < 4; j++)
            acc[i][j] = fmaf(av[i], bv[j], acc[i][j]);
}

__device__ __forceinline__ uint32_t smem_u32(const void* p) {
    uint32_t a;
    asm("{ .reg .u64 t; cvta.to.shared.u64 t, %1; cvt.u32.u64 %0, t; }" : "=r"(a) : "l"(p));
    return a;
}

__device__ __forceinline__ uint32_t sw128(uint32_t bo) {
    return bo ^ ((bo >> 3) & 0x70);
}

__device__ __forceinline__ void cp16(uint32_t dst, const void* src) {
    asm volatile("cp.async.cg.shared.global [%0], [%1], 16;" :: "r"(dst), "l"(src) : "memory");
}
#define CP_COMMIT() asm volatile("cp.async.commit_group;" ::: "memory")
#define CP_WAIT0()  asm volatile("cp.async.wait_group 0;" ::: "memory")

__device__ __forceinline__ void ldm_x4(uint32_t r[4], uint32_t addr) {
    asm volatile("ldmatrix.sync.aligned.m8n8.x4.shared.b16 {%0,%1,%2,%3}, [%4];"
        : "=r"(r[0]), "=r"(r[1]), "=r"(r[2]), "=r"(r[3]) : "r"(addr));
}

__device__ __forceinline__ void mma16816(float c[4], const uint32_t a[4],
                                         uint32_t b0, uint32_t b1) {
    asm volatile("mma.sync.aligned.m16n8k16.row.col.f32.bf16.bf16.f32 "
        "{%0,%1,%2,%3}, {%4,%5,%6,%7}, {%8,%9}, {%0,%1,%2,%3};"
        : "+f"(c[0]), "+f"(c[1]), "+f"(c[2]), "+f"(c[3])
        : "r"(a[0]), "r"(a[1]), "r"(a[2]), "r"(a[3]), "r"(b0), "r"(b1));
}

__device__ __forceinline__ uint32_t pack_split(float v) {
    __nv_bfloat16 hi = __float2bfloat16(v);
    __nv_bfloat16 lo = __float2bfloat16(v - __bfloat162float(hi));
    uint32_t h = *reinterpret_cast<unsigned short*>(&hi);
    uint32_t l = *reinterpret_cast<unsigned short*>(&lo);
    return h | (l << 16);
}

// ---------------------------------------------------------------------------
// Kernel 0: split weights into hi/lo bf16 planes
// ---------------------------------------------------------------------------
__global__ void k0_wprep(const float* __restrict__ lrpw, const float* __restrict__ gatew)
{
    int i = blockIdx.x * blockDim.x + threadIdx.x;
    if (i < 256 * 128) {
        float v = lrpw[i];
        __nv_bfloat16 h = __float2bfloat16(v);
        g_Wl_hi[i] = h;
        g_Wl_lo[i] = __float2bfloat16(v - __bfloat162float(h));
        v = gatew[i];
        h = __float2bfloat16(v);
        g_Wg_hi[i] = h;
        g_Wg_lo[i] = __float2bfloat16(v - __bfloat162float(h));
    }
}

// ---------------------------------------------------------------------------
// Kernel 1 (HMMA): LN1 + lrp/gate projections + sigmoid gating -> split L/R
// grid 2048, 256 threads (8 warps 4x2). 128 Z-rows per CTA, K=128.
// smem: A planes (hi/lo x 2 kchunks) 64KB | W planes 8x8KB | stage 33.8KB
// ---------------------------------------------------------------------------
#define K1_A_OFF   0
#define K1_W_OFF   65536
#define K1_ST_OFF  131072
#define K1_SMEM    164864

__global__ __launch_bounds__(256, 1)
void k1_mma(const float* __restrict__ Z, const float* __restrict__ mask,
            const float* __restrict__ ln1w, const float* __restrict__ ln1b,
            const float* __restrict__ lrpb, const float* __restrict__ gateb)
{
    extern __shared__ __align__(1024) char smc[];
    const uint32_t sbase = smem_u32(smc);
    uint32_t* stage = reinterpret_cast<uint32_t*>(smc + K1_ST_OFF);

    const int tid = threadIdx.x;
    const int warp = tid >> 5;
    const uint32_t lane = tid & 31;
    const int r0 = blockIdx.x * 128;

    // ---- Phase A: load Z rows, LN1, split-bf16 into swizzled A planes ----
    {
        const int k4 = lane * 4;
        const int kc = lane >> 4;                 // k-chunk (0/1)
        const uint32_t kb = (lane & 15) * 8;      // byte offset within 128B chunk row
        float4 w4 = *reinterpret_cast<const float4*>(ln1w + k4);
        float4 b4 = *reinterpret_cast<const float4*>(ln1b + k4);
        #pragma unroll 1
        for (int rr = 0; rr < 16; rr++) {
            int rloc = warp * 16 + rr;
            float4 v = *reinterpret_cast<const float4*>(Z + (size_t)(r0 + rloc) * DDIM + k4);
            float s  = v.x + v.y + v.z + v.w;
            float s2 = v.x * v.x + v.y * v.y + v.z * v.z + v.w * v.w;
            #pragma unroll
            for (int o = 16; o; o >>= 1) {
                s  += __shfl_xor_sync(0xffffffffu, s, o);
                s2 += __shfl_xor_sync(0xffffffffu, s2, o);
            }
            float m = s * 0.0078125f;
            float var = fmaf(-m, m, s2 * 0.0078125f);
            float rstd = rsqrtf(var + 1e-5f);
            float zn[4] = {
                (v.x - m) * rstd * w4.x + b4.x,
                (v.y - m) * rstd * w4.y + b4.y,
                (v.z - m) * rstd * w4.z + b4.z,
                (v.w - m) * rstd * w4.w + b4.w };
            uint32_t hip[2], lop[2];
            #pragma unroll
            for (int q = 0; q < 2; q++) {
                __nv_bfloat16 h0 = __float2bfloat16(zn[q*2]);
                __nv_bfloat16 h1 = __float2bfloat16(zn[q*2+1]);
                __nv_bfloat16 l0 = __float2bfloat16(zn[q*2]   - __bfloat162float(h0));
                __nv_bfloat16 l1 = __float2bfloat16(zn[q*2+1] - __bfloat162float(h1));
                hip[q] = (uint32_t)*reinterpret_cast<unsigned short*>(&h0) |
                         ((uint32_t)*reinterpret_cast<unsigned short*>(&h1) << 16);
                lop[q] = (uint32_t)*reinterpret_cast<unsigned short*>(&l0) |
                         ((uint32_t)*reinterpret_cast<unsigned short*>(&l1) << 16);
            }
            uint32_t sw = sw128((uint32_t)(rloc * 128) + kb);
            *reinterpret_cast<uint2*>(smc + K1_A_OFF + (0*2 + kc) * 16384 + sw) = make_uint2(hip[0], hip[1]);
            *reinterpret_cast<uint2*>(smc + K1_A_OFF + (1*2 + kc) * 16384 + sw) = make_uint2(lop[0], lop[1]);
        }
    }
    __syncthreads();

    const int wm = (warp >> 1) * 32;     // warp row base (0..96)
    const int wn = (warp & 1) * 32;      // warp col base (0/32) within 64-c tile

    const uint32_t a_row = (lane & 7) + ((lane >> 3) & 1) * 8;
    const uint32_t a_kb  = (lane >> 4) * 16;
    const uint32_t b_row = (lane & 7) + ((lane >> 4) & 1) * 8;
    const uint32_t b_kb  = ((lane >> 3) & 1) * 16;

    const __nv_bfloat16* wtab[4] = { g_Wl_hi, g_Wl_lo, g_Wg_hi, g_Wg_lo };

    #pragma unroll 1
    for (int ct = 0; ct < 4; ct++) {
        const int cbase = ct * 64;

        // ---- load W tiles (8 planes of 64x128B) via cp.async ----
        #pragma unroll
        for (int it = 0; it < 16; it++) {
            int u = it * 256 + tid;
            int p = u >> 9; int idx = u & 511;
            int row = idx >> 3, q = idx & 7;
            int shl = p >> 1, kc = p & 1;
            const __nv_bfloat16* src = wtab[shl] + (size_t)(cbase + row) * 128 + kc * 64 + q * 8;
            cp16(sbase + K1_W_OFF + p * 8192 + sw128((uint32_t)(row * 128 + q * 16)), src);
        }
        CP_COMMIT();
        CP_WAIT0();
        __syncthreads();

        // ---- MMA: accl / accg over K=128 ----
        float accl[2][4][4], accg[2][4][4];
        #pragma unroll
        for (int mt = 0; mt < 2; mt++)
            #pragma unroll
            for (int nt = 0; nt < 4; nt++)
                #pragma unroll
                for (int q = 0; q < 4; q++) { accl[mt][nt][q] = 0.f; accg[mt][nt][q] = 0.f; }

        #pragma unroll
        for (int kc = 0; kc < 2; kc++) {
            #pragma unroll
            for (int ks = 0; ks < 4; ks++) {
                uint32_t kb = ks * 32;
                uint32_t ah[2][4], al[2][4];
                #pragma unroll
                for (int mt = 0; mt < 2; mt++) {
                    uint32_t sw = sw128((uint32_t)((wm + mt * 16 + a_row) * 128) + kb + a_kb);
                    ldm_x4(ah[mt], sbase + K1_A_OFF + (0*2 + kc) * 16384 + sw);
                    ldm_x4(al[mt], sbase + K1_A_OFF + (1*2 + kc) * 16384 + sw);
                }
                #pragma unroll
                for (int ng = 0; ng < 2; ng++) {
                    uint32_t sw = sw128((uint32_t)((wn + ng * 16 + b_row) * 128) + kb + b_kb);
                    uint32_t wlh[4], wll[4], wgh[4], wgl[4];
                    ldm_x4(wlh, sbase + K1_W_OFF + (0 + kc) * 8192 + sw);
                    ldm_x4(wll, sbase + K1_W_OFF + (2 + kc) * 8192 + sw);
                    ldm_x4(wgh, sbase + K1_W_OFF + (4 + kc) * 8192 + sw);
                    ldm_x4(wgl, sbase + K1_W_OFF + (6 + kc) * 8192 + sw);
                    #pragma unroll
                    for (int mt = 0; mt < 2; mt++) {
                        #pragma unroll
                        for (int h = 0; h < 2; h++) {
                            float* cl = accl[mt][ng * 2 + h];
                            float* cg = accg[mt][ng * 2 + h];
                            mma16816(cl, ah[mt], wlh[h*2], wlh[h*2+1]);
                            mma16816(cl, ah[mt], wll[h*2], wll[h*2+1]);
                            mma16816(cl, al[mt], wlh[h*2], wlh[h*2+1]);
                            mma16816(cg, ah[mt], wgh[h*2], wgh[h*2+1]);
                            mma16816(cg, ah[mt], wgl[h*2], wgl[h*2+1]);
                            mma16816(cg, al[mt], wgh[h*2], wgh[h*2+1]);
                        }
                    }
                }
            }
        }

        // ---- epilogue: gate, pack hi|lo, stage [c][r] ----
        #pragma unroll
        for (int mt = 0; mt < 2; mt++) {
            int rl0 = wm + mt * 16 + (int)(lane >> 2);
            float m0 = mask[r0 + rl0];
            float m1 = mask[r0 + rl0 + 8];
            #pragma unroll
            for (int nt = 0; nt < 4; nt++) {
                int cl0 = wn + nt * 8 + 2 * (int)(lane & 3);
                float lb0 = lrpb[cbase + cl0],  lb1 = lrpb[cbase + cl0 + 1];
                float gb0 = gateb[cbase + cl0], gb1 = gateb[cbase + cl0 + 1];
                float* vl = accl[mt][nt];
                float* vg = accg[mt][nt];
                stage[(cl0    ) * 132 + rl0    ] = pack_split((vl[0] + lb0) * m0 * sigmoidf_(vg[0] + gb0));
                stage[(cl0 + 1) * 132 + rl0    ] = pack_split((vl[1] + lb1) * m0 * sigmoidf_(vg[1] + gb1));
                stage[(cl0    ) * 132 + rl0 + 8] = pack_split((vl[2] + lb0) * m1 * sigmoidf_(vg[2] + gb0));
                stage[(cl0 + 1) * 132 + rl0 + 8] = pack_split((vl[3] + lb1) * m1 * sigmoidf_(vg[3] + gb1));
            }
        }
        __syncthreads();

        // ---- writeout: coalesced per-channel 128-r segments ----
        {
            int c_loc = tid >> 2;
            int seg = tid & 3;
            int cg = cbase + c_loc;
            __nv_bfloat16* hiP = (cg < 128) ? (g_Lhi + (size_t)cg * NN) : (g_Rhi + (size_t)(cg - 128) * NN);
            __nv_bfloat16* loP = (cg < 128) ? (g_Llo + (size_t)cg * NN) : (g_Rlo + (size_t)(cg - 128) * NN);
            int rb = seg * 32;
            const uint32_t* srow = &stage[c_loc * 132 + rb];
            #pragma unroll
            for (int blk = 0; blk < 4; blk++) {
                uint32_t hw[4], lw[4];
                #pragma unroll
                for (int q = 0; q < 4; q++) {
                    uint32_t p0 = srow[blk * 8 + q * 2];
                    uint32_t p1 = srow[blk * 8 + q * 2 + 1];
                    hw[q] = (p0 & 0xffffu) | (p1 << 16);
                    lw[q] = (p0 >> 16) | (p1 & 0xffff0000u);
                }
                *reinterpret_cast<uint4*>(hiP + r0 + rb + blk * 8) = make_uint4(hw[0], hw[1], hw[2], hw[3]);
                *reinterpret_cast<uint4*>(loP + r0 + rb + blk * 8) = make_uint4(lw[0], lw[1], lw[2], lw[3]);
            }
        }
        __syncthreads();
    }
}

// ---------------------------------------------------------------------------
// Kernel 2: split-bf16 mma.sync GEMM  T_c = L_c @ R_c^T
// ---------------------------------------------------------------------------
#define PLANE 16384
#define STAGE (4 * PLANE)
#define K2_SMEM (2 * STAGE)

__device__ __forceinline__ void k2_prefetch(uint32_t sbase, int stage_i,
    const __nv_bfloat16* Ah, const __nv_bfloat16* Al,
    const __nv_bfloat16* Bh, const __nv_bfloat16* Bl,
    int i0, int j0, int k0, int tid)
{
    const __nv_bfloat16* srcs[4] = {Ah, Al, Bh, Bl};
    const int bases[4] = {i0, i0, j0, j0};
    uint32_t st = sbase + stage_i * STAGE;
    #pragma unroll
    for (int p = 0; p < 4; p++) {
        const __nv_bfloat16* s = srcs[p];
        int rb = bases[p];
        #pragma unroll
        for (int it = 0; it < 4; it++) {
            int idx = it * 256 + tid;
            int r = idx >> 3, q = idx & 7;
            uint32_t dst = st + p * PLANE + sw128((uint32_t)(r * 128 + q * 16));
            cp16(dst, s + (size_t)(rb + r) * NDIM + k0 + q * 8);
        }
    }
}

__global__ __launch_bounds__(256, 1)
void k2_tri_mma()
{
    extern __shared__ __align__(1024) char smc[];
    const uint32_t sbase = smem_u32(smc);
    const int tid = threadIdx.x;
    const int warp = tid >> 5;
    const uint32_t lane = tid & 31;
    const int c = blockIdx.z;
    const int i0 = blockIdx.x * 128, j0 = blockIdx.y * 128;

    const __nv_bfloat16* __restrict__ Ah = g_Lhi + (size_t)c * NN;
    const __nv_bfloat16* __restrict__ Al = g_Llo + (size_t)c * NN;
    const __nv_bfloat16* __restrict__ Bh = g_Rhi + (size_t)c * NN;
    const __nv_bfloat16* __restrict__ Bl = g_Rlo + (size_t)c * NN;
    float* __restrict__ Tc = g_T + (size_t)c * NN;

    const int wm = (warp >> 1) * 32;
    const int wn = (warp & 1) * 64;

    const uint32_t a_row = (lane & 7) + ((lane >> 3) & 1) * 8;
    const uint32_t a_kb  = (lane >> 4) * 16;
    const uint32_t b_row = (lane & 7) + ((lane >> 4) & 1) * 8;
    const uint32_t b_kb  = ((lane >> 3) & 1) * 16;

    float acc[2][8][4];
    #pragma unroll
    for (int mt = 0; mt < 2; mt++)
        #pragma unroll
        for (int nt = 0; nt < 8; nt++)
            #pragma unroll
            for (int q = 0; q < 4; q++) acc[mt][nt][q] = 0.0f;

    k2_prefetch(sbase, 0, Ah, Al, Bh, Bl, i0, j0, 0, tid);
    CP_COMMIT();

    #pragma unroll 1
    for (int ch = 0; ch < 8; ch++) {
        CP_WAIT0();
        __syncthreads();
        if (ch + 1 < 8) {
            k2_prefetch(sbase, (ch + 1) & 1, Ah, Al, Bh, Bl, i0, j0, (ch + 1) * 64, tid);
            CP_COMMIT();
        }
        uint32_t st = sbase + (ch & 1) * STAGE;
        uint32_t sAh = st, sAl = st + PLANE, sBh = st + 2 * PLANE, sBl = st + 3 * PLANE;

        #pragma unroll
        for (int ks = 0; ks < 4; ks++) {
            uint32_t kb = ks * 32;
            uint32_t ah[2][4], al[2][4];
            #pragma unroll
            for (int mt = 0; mt < 2; mt++) {
                uint32_t sw = sw128((uint32_t)((wm + mt * 16 + a_row) * 128) + kb + a_kb);
                ldm_x4(ah[mt], sAh + sw);
                ldm_x4(al[mt], sAl + sw);
            }
            #pragma unroll
            for (int ng = 0; ng < 4; ng++) {
                uint32_t sw = sw128((uint32_t)((wn + ng * 16 + b_row) * 128) + kb + b_kb);
                uint32_t bh[4], bl[4];
                ldm_x4(bh, sBh + sw);
                ldm_x4(bl, sBl + sw);
                #pragma unroll
                for (int mt = 0; mt < 2; mt++) {
                    #pragma unroll
                    for (int h = 0; h < 2; h++) {
                        float* cc = acc[mt][ng * 2 + h];
                        mma16816(cc, ah[mt], bh[h * 2], bh[h * 2 + 1]);
                        mma16816(cc, ah[mt], bl[h * 2], bl[h * 2 + 1]);
                        mma16816(cc, al[mt], bh[h * 2], bh[h * 2 + 1]);
                    }
                }
            }
        }
        __syncthreads();
    }

    const int rbase = i0 + wm + (int)(lane >> 2);
    const int cbase = j0 + wn + 2 * (int)(lane & 3);
    #pragma unroll
    for (int mt = 0; mt < 2; mt++) {
        #pragma unroll
        for (int nt = 0; nt < 8; nt++) {
            float* cc = acc[mt][nt];
            int col = cbase + nt * 8;
            int r1 = rbase + mt * 16;
            *reinterpret_cast<float2*>(&Tc[(size_t)r1 * NDIM + col])       = make_float2(cc[0], cc[1]);
            *reinterpret_cast<float2*>(&Tc[(size_t)(r1 + 8) * NDIM + col]) = make_float2(cc[2], cc[3]);
        }
    }
}

// ---------------------------------------------------------------------------
// Kernel 3: gather tri rows, LN2, og/op matmuls, gated residual epilogue
// ---------------------------------------------------------------------------
#define K3_SMEM (173056)

__global__ __launch_bounds__(256, 1)
void k3_out(const float* __restrict__ ogw, const float* __restrict__ ogb,
            const float* __restrict__ ln2w, const float* __restrict__ ln2b,
            const float* __restrict__ opw, const float* __restrict__ outb,
            float* __restrict__ out)
{
    extern __shared__ float sm[];
    float* s_t  = sm;
    float* s_tt = sm + 64 * 132;
    float* s_zt = s_tt + 128 * 68;
    float* s_wo = s_zt + 128 * 68;
    float* s_wp = s_wo + 128 * 68;

    const int tid = threadIdx.x;
    const int r0 = blockIdx.x * 64;

    for (int idx = tid; idx < 64 * 128; idx += 256) {
        int cch = idx >> 6, rr = idx & 63;
        s_t[rr * 132 + cch] = g_T[(size_t)cch * NN + r0 + rr];
    }
    __syncthreads();

    {
        int warp = tid >> 5, lane = tid & 31;
        for (int rr = warp * 8; rr < warp * 8 + 8; rr++) {
            float* row = &s_t[rr * 132];
            float4 v = *reinterpret_cast<float4*>(&row[lane * 4]);
            float s  = v.x + v.y + v.z + v.w;
            float s2 = v.x * v.x + v.y * v.y + v.z * v.z + v.w * v.w;
            #pragma unroll
            for (int o = 16; o; o >>= 1) {
                s  += __shfl_xor_sync(0xffffffffu, s, o);
                s2 += __shfl_xor_sync(0xffffffffu, s2, o);
            }
            float m = s * 0.0078125f;
            float var = fmaf(-m, m, s2 * 0.0078125f);
            float rstd = rsqrtf(var + 1e-5f);
            #pragma unroll
            for (int q = 0; q < 4; q++) {
                int cch = lane * 4 + q;
                float t = row[cch];
                s_tt[cch * 68 + rr] = t;
                s_zt[cch * 68 + rr] = (t - m) * rstd * ln2w[cch] + ln2b[cch];
            }
        }
    }

    const int tx = tid & 15, ty = tid >> 4;

    for (int dt = 0; dt < 2; dt++) {
        __syncthreads();
        for (int idx = tid; idx < 64 * 32; idx += 256) {
            int dd = idx >> 5, kq = idx & 31;
            float4 wo = reinterpret_cast<const float4*>(ogw + (size_t)(dt * 64 + dd) * DDIM)[kq];
            float4 wp = reinterpret_cast<const float4*>(opw + (size_t)(dt * 64 + dd) * DDIM)[kq];
            s_wo[(kq * 4 + 0) * 68 + dd] = wo.x;
            s_wo[(kq * 4 + 1) * 68 + dd] = wo.y;
            s_wo[(kq * 4 + 2) * 68 + dd] = wo.z;
            s_wo[(kq * 4 + 3) * 68 + dd] = wo.w;
            s_wp[(kq * 4 + 0) * 68 + dd] = wp.x;
            s_wp[(kq * 4 + 1) * 68 + dd] = wp.y;
            s_wp[(kq * 4 + 2) * 68 + dd] = wp.z;
            s_wp[(kq * 4 + 3) * 68 + dd] = wp.w;
        }
        __syncthreads();

        float accg[4][4] = {}, accz[4][4] = {};
        #pragma unroll 8
        for (int k = 0; k < 128; k++) {
            float4 at = *reinterpret_cast<float4*>(&s_tt[k * 68 + ty * 4]);
            float4 az = *reinterpret_cast<float4*>(&s_zt[k * 68 + ty * 4]);
            float4 wo = *reinterpret_cast<float4*>(&s_wo[k * 68 + tx * 4]);
            float4 wp = *reinterpret_cast<float4*>(&s_wp[k * 68 + tx * 4]);
            outer4(accg, at, wo);
            outer4(accz, az, wp);
        }

        #pragma unroll
        for (int i = 0; i < 4; i++) {
            int rloc = ty * 4 + i;
            size_t r = (size_t)r0 + rloc;
            #pragma unroll
            for (int j = 0; j < 4; j++) {
                int d = dt * 64 + tx * 4 + j;
                float tval = s_t[rloc * 132 + d];
                float go = sigmoidf_(accg[i][j] + ogb[d]);
                out[r * DDIM + d] = tval + go * (accz[i][j] + outb[d]);
            }
        }
    }
}

// ---------------------------------------------------------------------------
extern "C" void kernel_launch(void* const* d_in, const int* in_sizes, int n_in,
                              void* d_out, int out_size)
{
    const float* Z     = (const float*)d_in[0];
    const float* mask  = (const float*)d_in[1];
    const float* ln1w  = (const float*)d_in[2];
    const float* ln1b  = (const float*)d_in[3];
    const float* lrpw  = (const float*)d_in[4];
    const float* lrpb  = (const float*)d_in[5];
    const float* gatew = (const float*)d_in[6];
    const float* gateb = (const float*)d_in[7];
    const float* ogw   = (const float*)d_in[8];
    const float* ogb   = (const float*)d_in[9];
    const float* ln2w  = (const float*)d_in[10];
    const float* ln2b  = (const float*)d_in[11];
    const float* opw   = (const float*)d_in[12];
    const float* outb  = (const float*)d_in[13];
    float* out = (float*)d_out;

    cudaFuncSetAttribute(k1_mma,     cudaFuncAttributeMaxDynamicSharedMemorySize, K1_SMEM);
    cudaFuncSetAttribute(k2_tri_mma, cudaFuncAttributeMaxDynamicSharedMemorySize, K2_SMEM);
    cudaFuncSetAttribute(k3_out,     cudaFuncAttributeMaxDynamicSharedMemorySize, K3_SMEM);

    k0_wprep<<<128, 256>>>(lrpw, gatew);

    k1_mma<<<NN / 128, 256, K1_SMEM>>>(Z, mask, ln1w, ln1b, lrpb, gateb);

    dim3 g2(4, 4, 128);
    k2_tri_mma<<<g2, 256, K2_SMEM>>>();

    k3_out<<<NN / 64, 256, K3_SMEM>>>(ogw, ogb, ln2w, ln2b, opw, outb, out);
}

// round 6
// speedup vs baseline: 3.0282x; 1.6031x over previous
#include <cuda_runtime.h>
#include <cuda_bf16.h>
#include <cstdint>

#define NDIM 512
#define DDIM 128
#define NN (NDIM*NDIM)

// Scratch (allocation-free rule: __device__ globals)
__device__ __nv_bfloat16 g_Lhi[(size_t)DDIM * NN];   // [c][i][k]
__device__ __nv_bfloat16 g_Llo[(size_t)DDIM * NN];
__device__ __nv_bfloat16 g_Rhi[(size_t)DDIM * NN];   // [c][j][k]
__device__ __nv_bfloat16 g_Rlo[(size_t)DDIM * NN];
__device__ float g_T[(size_t)DDIM * NN];             // [c][i][j]
// split-bf16 weights for stage-1 (prepped by k0)
__device__ __nv_bfloat16 g_Wl_hi[256 * 128];
__device__ __nv_bfloat16 g_Wl_lo[256 * 128];
__device__ __nv_bfloat16 g_Wg_hi[256 * 128];
__device__ __nv_bfloat16 g_Wg_lo[256 * 128];
// bf16 weights for stage-2 (og / op)
__device__ __nv_bfloat16 g_Wo_bf[128 * 128];
__device__ __nv_bfloat16 g_Wp_bf[128 * 128];

__device__ __forceinline__ float sigmoidf_(float x) {
    return 1.0f / (1.0f + __expf(-x));
}

__device__ __forceinline__ uint32_t smem_u32(const void* p) {
    uint32_t a;
    asm("{ .reg .u64 t; cvta.to.shared.u64 t, %1; cvt.u32.u64 %0, t; }" : "=r"(a) : "l"(p));
    return a;
}

__device__ __forceinline__ uint32_t sw128(uint32_t bo) {
    return bo ^ ((bo >> 3) & 0x70);
}

__device__ __forceinline__ void cp16(uint32_t dst, const void* src) {
    asm volatile("cp.async.cg.shared.global [%0], [%1], 16;" :: "r"(dst), "l"(src) : "memory");
}
#define CP_COMMIT() asm volatile("cp.async.commit_group;" ::: "memory")
#define CP_WAIT0()  asm volatile("cp.async.wait_group 0;" ::: "memory")

__device__ __forceinline__ void ldm_x4(uint32_t r[4], uint32_t addr) {
    asm volatile("ldmatrix.sync.aligned.m8n8.x4.shared.b16 {%0,%1,%2,%3}, [%4];"
        : "=r"(r[0]), "=r"(r[1]), "=r"(r[2]), "=r"(r[3]) : "r"(addr));
}

__device__ __forceinline__ void mma16816(float c[4], const uint32_t a[4],
                                         uint32_t b0, uint32_t b1) {
    asm volatile("mma.sync.aligned.m16n8k16.row.col.f32.bf16.bf16.f32 "
        "{%0,%1,%2,%3}, {%4,%5,%6,%7}, {%8,%9}, {%0,%1,%2,%3};"
        : "+f"(c[0]), "+f"(c[1]), "+f"(c[2]), "+f"(c[3])
        : "r"(a[0]), "r"(a[1]), "r"(a[2]), "r"(a[3]), "r"(b0), "r"(b1));
}

__device__ __forceinline__ uint32_t pack_split(float v) {
    __nv_bfloat16 hi = __float2bfloat16(v);
    __nv_bfloat16 lo = __float2bfloat16(v - __bfloat162float(hi));
    uint32_t h = *reinterpret_cast<unsigned short*>(&hi);
    uint32_t l = *reinterpret_cast<unsigned short*>(&lo);
    return h | (l << 16);
}

__device__ __forceinline__ uint32_t pack_bf2(float a, float b) {
    __nv_bfloat16 h0 = __float2bfloat16(a);
    __nv_bfloat16 h1 = __float2bfloat16(b);
    return (uint32_t)*reinterpret_cast<unsigned short*>(&h0) |
           ((uint32_t)*reinterpret_cast<unsigned short*>(&h1) << 16);
}

// ---------------------------------------------------------------------------
// Kernel 0: split weights into hi/lo bf16 planes (+ og/op bf16)
// ---------------------------------------------------------------------------
__global__ void k0_wprep(const float* __restrict__ lrpw, const float* __restrict__ gatew,
                         const float* __restrict__ ogw,  const float* __restrict__ opw)
{
    int i = blockIdx.x * blockDim.x + threadIdx.x;
    if (i < 256 * 128) {
        float v = lrpw[i];
        __nv_bfloat16 h = __float2bfloat16(v);
        g_Wl_hi[i] = h;
        g_Wl_lo[i] = __float2bfloat16(v - __bfloat162float(h));
        v = gatew[i];
        h = __float2bfloat16(v);
        g_Wg_hi[i] = h;
        g_Wg_lo[i] = __float2bfloat16(v - __bfloat162float(h));
    }
    if (i < 128 * 128) {
        g_Wo_bf[i] = __float2bfloat16(ogw[i]);
        g_Wp_bf[i] = __float2bfloat16(opw[i]);
    }
}

// ---------------------------------------------------------------------------
// Kernel 1 (HMMA): LN1 + lrp/gate projections + sigmoid gating -> split L/R
// ---------------------------------------------------------------------------
#define K1_A_OFF   0
#define K1_W_OFF   65536
#define K1_ST_OFF  131072
#define K1_SMEM    164864

__global__ __launch_bounds__(256, 1)
void k1_mma(const float* __restrict__ Z, const float* __restrict__ mask,
            const float* __restrict__ ln1w, const float* __restrict__ ln1b,
            const float* __restrict__ lrpb, const float* __restrict__ gateb)
{
    extern __shared__ __align__(1024) char smc[];
    const uint32_t sbase = smem_u32(smc);
    uint32_t* stage = reinterpret_cast<uint32_t*>(smc + K1_ST_OFF);

    const int tid = threadIdx.x;
    const int warp = tid >> 5;
    const uint32_t lane = tid & 31;
    const int r0 = blockIdx.x * 128;

    // ---- Phase A: load Z rows, LN1, split-bf16 into swizzled A planes ----
    {
        const int k4 = lane * 4;
        const int kc = lane >> 4;
        const uint32_t kb = (lane & 15) * 8;
        float4 w4 = *reinterpret_cast<const float4*>(ln1w + k4);
        float4 b4 = *reinterpret_cast<const float4*>(ln1b + k4);
        #pragma unroll 1
        for (int rr = 0; rr < 16; rr++) {
            int rloc = warp * 16 + rr;
            float4 v = *reinterpret_cast<const float4*>(Z + (size_t)(r0 + rloc) * DDIM + k4);
            float s  = v.x + v.y + v.z + v.w;
            float s2 = v.x * v.x + v.y * v.y + v.z * v.z + v.w * v.w;
            #pragma unroll
            for (int o = 16; o; o >>= 1) {
                s  += __shfl_xor_sync(0xffffffffu, s, o);
                s2 += __shfl_xor_sync(0xffffffffu, s2, o);
            }
            float m = s * 0.0078125f;
            float var = fmaf(-m, m, s2 * 0.0078125f);
            float rstd = rsqrtf(var + 1e-5f);
            float zn[4] = {
                (v.x - m) * rstd * w4.x + b4.x,
                (v.y - m) * rstd * w4.y + b4.y,
                (v.z - m) * rstd * w4.z + b4.z,
                (v.w - m) * rstd * w4.w + b4.w };
            uint32_t hip[2], lop[2];
            #pragma unroll
            for (int q = 0; q < 2; q++) {
                __nv_bfloat16 h0 = __float2bfloat16(zn[q*2]);
                __nv_bfloat16 h1 = __float2bfloat16(zn[q*2+1]);
                __nv_bfloat16 l0 = __float2bfloat16(zn[q*2]   - __bfloat162float(h0));
                __nv_bfloat16 l1 = __float2bfloat16(zn[q*2+1] - __bfloat162float(h1));
                hip[q] = (uint32_t)*reinterpret_cast<unsigned short*>(&h0) |
                         ((uint32_t)*reinterpret_cast<unsigned short*>(&h1) << 16);
                lop[q] = (uint32_t)*reinterpret_cast<unsigned short*>(&l0) |
                         ((uint32_t)*reinterpret_cast<unsigned short*>(&l1) << 16);
            }
            uint32_t sw = sw128((uint32_t)(rloc * 128) + kb);
            *reinterpret_cast<uint2*>(smc + K1_A_OFF + (0*2 + kc) * 16384 + sw) = make_uint2(hip[0], hip[1]);
            *reinterpret_cast<uint2*>(smc + K1_A_OFF + (1*2 + kc) * 16384 + sw) = make_uint2(lop[0], lop[1]);
        }
    }
    __syncthreads();

    const int wm = (warp >> 1) * 32;
    const int wn = (warp & 1) * 32;

    const uint32_t a_row = (lane & 7) + ((lane >> 3) & 1) * 8;
    const uint32_t a_kb  = (lane >> 4) * 16;
    const uint32_t b_row = (lane & 7) + ((lane >> 4) & 1) * 8;
    const uint32_t b_kb  = ((lane >> 3) & 1) * 16;

    const __nv_bfloat16* wtab[4] = { g_Wl_hi, g_Wl_lo, g_Wg_hi, g_Wg_lo };

    #pragma unroll 1
    for (int ct = 0; ct < 4; ct++) {
        const int cbase = ct * 64;

        #pragma unroll
        for (int it = 0; it < 16; it++) {
            int u = it * 256 + tid;
            int p = u >> 9; int idx = u & 511;
            int row = idx >> 3, q = idx & 7;
            int shl = p >> 1, kc = p & 1;
            const __nv_bfloat16* src = wtab[shl] + (size_t)(cbase + row) * 128 + kc * 64 + q * 8;
            cp16(sbase + K1_W_OFF + p * 8192 + sw128((uint32_t)(row * 128 + q * 16)), src);
        }
        CP_COMMIT();
        CP_WAIT0();
        __syncthreads();

        float accl[2][4][4], accg[2][4][4];
        #pragma unroll
        for (int mt = 0; mt < 2; mt++)
            #pragma unroll
            for (int nt = 0; nt < 4; nt++)
                #pragma unroll
                for (int q = 0; q < 4; q++) { accl[mt][nt][q] = 0.f; accg[mt][nt][q] = 0.f; }

        #pragma unroll
        for (int kc = 0; kc < 2; kc++) {
            #pragma unroll
            for (int ks = 0; ks < 4; ks++) {
                uint32_t kb = ks * 32;
                uint32_t ah[2][4], al[2][4];
                #pragma unroll
                for (int mt = 0; mt < 2; mt++) {
                    uint32_t sw = sw128((uint32_t)((wm + mt * 16 + a_row) * 128) + kb + a_kb);
                    ldm_x4(ah[mt], sbase + K1_A_OFF + (0*2 + kc) * 16384 + sw);
                    ldm_x4(al[mt], sbase + K1_A_OFF + (1*2 + kc) * 16384 + sw);
                }
                #pragma unroll
                for (int ng = 0; ng < 2; ng++) {
                    uint32_t sw = sw128((uint32_t)((wn + ng * 16 + b_row) * 128) + kb + b_kb);
                    uint32_t wlh[4], wll[4], wgh[4], wgl[4];
                    ldm_x4(wlh, sbase + K1_W_OFF + (0 + kc) * 8192 + sw);
                    ldm_x4(wll, sbase + K1_W_OFF + (2 + kc) * 8192 + sw);
                    ldm_x4(wgh, sbase + K1_W_OFF + (4 + kc) * 8192 + sw);
                    ldm_x4(wgl, sbase + K1_W_OFF + (6 + kc) * 8192 + sw);
                    #pragma unroll
                    for (int mt = 0; mt < 2; mt++) {
                        #pragma unroll
                        for (int h = 0; h < 2; h++) {
                            float* cl = accl[mt][ng * 2 + h];
                            float* cg = accg[mt][ng * 2 + h];
                            mma16816(cl, ah[mt], wlh[h*2], wlh[h*2+1]);
                            mma16816(cl, ah[mt], wll[h*2], wll[h*2+1]);
                            mma16816(cl, al[mt], wlh[h*2], wlh[h*2+1]);
                            mma16816(cg, ah[mt], wgh[h*2], wgh[h*2+1]);
                            mma16816(cg, ah[mt], wgl[h*2], wgl[h*2+1]);
                            mma16816(cg, al[mt], wgh[h*2], wgh[h*2+1]);
                        }
                    }
                }
            }
        }

        #pragma unroll
        for (int mt = 0; mt < 2; mt++) {
            int rl0 = wm + mt * 16 + (int)(lane >> 2);
            float m0 = mask[r0 + rl0];
            float m1 = mask[r0 + rl0 + 8];
            #pragma unroll
            for (int nt = 0; nt < 4; nt++) {
                int cl0 = wn + nt * 8 + 2 * (int)(lane & 3);
                float lb0 = lrpb[cbase + cl0],  lb1 = lrpb[cbase + cl0 + 1];
                float gb0 = gateb[cbase + cl0], gb1 = gateb[cbase + cl0 + 1];
                float* vl = accl[mt][nt];
                float* vg = accg[mt][nt];
                stage[(cl0    ) * 132 + rl0    ] = pack_split((vl[0] + lb0) * m0 * sigmoidf_(vg[0] + gb0));
                stage[(cl0 + 1) * 132 + rl0    ] = pack_split((vl[1] + lb1) * m0 * sigmoidf_(vg[1] + gb1));
                stage[(cl0    ) * 132 + rl0 + 8] = pack_split((vl[2] + lb0) * m1 * sigmoidf_(vg[2] + gb0));
                stage[(cl0 + 1) * 132 + rl0 + 8] = pack_split((vl[3] + lb1) * m1 * sigmoidf_(vg[3] + gb1));
            }
        }
        __syncthreads();

        {
            int c_loc = tid >> 2;
            int seg = tid & 3;
            int cg = cbase + c_loc;
            __nv_bfloat16* hiP = (cg < 128) ? (g_Lhi + (size_t)cg * NN) : (g_Rhi + (size_t)(cg - 128) * NN);
            __nv_bfloat16* loP = (cg < 128) ? (g_Llo + (size_t)cg * NN) : (g_Rlo + (size_t)(cg - 128) * NN);
            int rb = seg * 32;
            const uint32_t* srow = &stage[c_loc * 132 + rb];
            #pragma unroll
            for (int blk = 0; blk < 4; blk++) {
                uint32_t hw[4], lw[4];
                #pragma unroll
                for (int q = 0; q < 4; q++) {
                    uint32_t p0 = srow[blk * 8 + q * 2];
                    uint32_t p1 = srow[blk * 8 + q * 2 + 1];
                    hw[q] = (p0 & 0xffffu) | (p1 << 16);
                    lw[q] = (p0 >> 16) | (p1 & 0xffff0000u);
                }
                *reinterpret_cast<uint4*>(hiP + r0 + rb + blk * 8) = make_uint4(hw[0], hw[1], hw[2], hw[3]);
                *reinterpret_cast<uint4*>(loP + r0 + rb + blk * 8) = make_uint4(lw[0], lw[1], lw[2], lw[3]);
            }
        }
        __syncthreads();
    }
}

// ---------------------------------------------------------------------------
// Kernel 2: split-bf16 mma.sync GEMM  T_c = L_c @ R_c^T
// ---------------------------------------------------------------------------
#define PLANE 16384
#define STAGE (4 * PLANE)
#define K2_SMEM (2 * STAGE)

__device__ __forceinline__ void k2_prefetch(uint32_t sbase, int stage_i,
    const __nv_bfloat16* Ah, const __nv_bfloat16* Al,
    const __nv_bfloat16* Bh, const __nv_bfloat16* Bl,
    int i0, int j0, int k0, int tid)
{
    const __nv_bfloat16* srcs[4] = {Ah, Al, Bh, Bl};
    const int bases[4] = {i0, i0, j0, j0};
    uint32_t st = sbase + stage_i * STAGE;
    #pragma unroll
    for (int p = 0; p < 4; p++) {
        const __nv_bfloat16* s = srcs[p];
        int rb = bases[p];
        #pragma unroll
        for (int it = 0; it < 4; it++) {
            int idx = it * 256 + tid;
            int r = idx >> 3, q = idx & 7;
            uint32_t dst = st + p * PLANE + sw128((uint32_t)(r * 128 + q * 16));
            cp16(dst, s + (size_t)(rb + r) * NDIM + k0 + q * 8);
        }
    }
}

__global__ __launch_bounds__(256, 1)
void k2_tri_mma()
{
    extern __shared__ __align__(1024) char smc[];
    const uint32_t sbase = smem_u32(smc);
    const int tid = threadIdx.x;
    const int warp = tid >> 5;
    const uint32_t lane = tid & 31;
    const int c = blockIdx.z;
    const int i0 = blockIdx.x * 128, j0 = blockIdx.y * 128;

    const __nv_bfloat16* __restrict__ Ah = g_Lhi + (size_t)c * NN;
    const __nv_bfloat16* __restrict__ Al = g_Llo + (size_t)c * NN;
    const __nv_bfloat16* __restrict__ Bh = g_Rhi + (size_t)c * NN;
    const __nv_bfloat16* __restrict__ Bl = g_Rlo + (size_t)c * NN;
    float* __restrict__ Tc = g_T + (size_t)c * NN;

    const int wm = (warp >> 1) * 32;
    const int wn = (warp & 1) * 64;

    const uint32_t a_row = (lane & 7) + ((lane >> 3) & 1) * 8;
    const uint32_t a_kb  = (lane >> 4) * 16;
    const uint32_t b_row = (lane & 7) + ((lane >> 4) & 1) * 8;
    const uint32_t b_kb  = ((lane >> 3) & 1) * 16;

    float acc[2][8][4];
    #pragma unroll
    for (int mt = 0; mt < 2; mt++)
        #pragma unroll
        for (int nt = 0; nt < 8; nt++)
            #pragma unroll
            for (int q = 0; q < 4; q++) acc[mt][nt][q] = 0.0f;

    k2_prefetch(sbase, 0, Ah, Al, Bh, Bl, i0, j0, 0, tid);
    CP_COMMIT();

    #pragma unroll 1
    for (int ch = 0; ch < 8; ch++) {
        CP_WAIT0();
        __syncthreads();
        if (ch + 1 < 8) {
            k2_prefetch(sbase, (ch + 1) & 1, Ah, Al, Bh, Bl, i0, j0, (ch + 1) * 64, tid);
            CP_COMMIT();
        }
        uint32_t st = sbase + (ch & 1) * STAGE;
        uint32_t sAh = st, sAl = st + PLANE, sBh = st + 2 * PLANE, sBl = st + 3 * PLANE;

        #pragma unroll
        for (int ks = 0; ks < 4; ks++) {
            uint32_t kb = ks * 32;
            uint32_t ah[2][4], al[2][4];
            #pragma unroll
            for (int mt = 0; mt < 2; mt++) {
                uint32_t sw = sw128((uint32_t)((wm + mt * 16 + a_row) * 128) + kb + a_kb);
                ldm_x4(ah[mt], sAh + sw);
                ldm_x4(al[mt], sAl + sw);
            }
            #pragma unroll
            for (int ng = 0; ng < 4; ng++) {
                uint32_t sw = sw128((uint32_t)((wn + ng * 16 + b_row) * 128) + kb + b_kb);
                uint32_t bh[4], bl[4];
                ldm_x4(bh, sBh + sw);
                ldm_x4(bl, sBl + sw);
                #pragma unroll
                for (int mt = 0; mt < 2; mt++) {
                    #pragma unroll
                    for (int h = 0; h < 2; h++) {
                        float* cc = acc[mt][ng * 2 + h];
                        mma16816(cc, ah[mt], bh[h * 2], bh[h * 2 + 1]);
                        mma16816(cc, ah[mt], bl[h * 2], bl[h * 2 + 1]);
                        mma16816(cc, al[mt], bh[h * 2], bh[h * 2 + 1]);
                    }
                }
            }
        }
        __syncthreads();
    }

    const int rbase = i0 + wm + (int)(lane >> 2);
    const int cbase = j0 + wn + 2 * (int)(lane & 3);
    #pragma unroll
    for (int mt = 0; mt < 2; mt++) {
        #pragma unroll
        for (int nt = 0; nt < 8; nt++) {
            float* cc = acc[mt][nt];
            int col = cbase + nt * 8;
            int r1 = rbase + mt * 16;
            *reinterpret_cast<float2*>(&Tc[(size_t)r1 * NDIM + col])       = make_float2(cc[0], cc[1]);
            *reinterpret_cast<float2*>(&Tc[(size_t)(r1 + 8) * NDIM + col]) = make_float2(cc[2], cc[3]);
        }
    }
}

// ---------------------------------------------------------------------------
// Kernel 3 (HMMA): gather tri, LN2, og/op matmuls (bf16), gated residual
// grid 2048, 256 threads. smem: s_t fp32 [128][132] | A planes | W planes
// ---------------------------------------------------------------------------
#define K3_T_OFF   0
#define K3_A_OFF   67584
#define K3_W_OFF   (67584 + 65536)
#define K3_SMEM    (67584 + 65536 + 65536)   // 198656

__global__ __launch_bounds__(256, 1)
void k3_mma(const float* __restrict__ ogb, const float* __restrict__ ln2w,
            const float* __restrict__ ln2b, const float* __restrict__ outb,
            float* __restrict__ out)
{
    extern __shared__ __align__(1024) char smc[];
    const uint32_t sbase = smem_u32(smc);
    float* s_t = reinterpret_cast<float*>(smc + K3_T_OFF);   // [128][132]

    const int tid = threadIdx.x;
    const int warp = tid >> 5;
    const uint32_t lane = tid & 31;
    const int r0 = blockIdx.x * 128;

    // ---- W planes via cp.async (og: planes 0,1 | op: planes 2,3) ----
    #pragma unroll
    for (int it = 0; it < 16; it++) {
        int u = it * 256 + tid;
        int p = u >> 10; int idx = u & 1023;     // p: 0..3, idx: 0..1023
        int row = idx >> 3, q = idx & 7;
        int pl = p >> 1, kc = p & 1;
        const __nv_bfloat16* src = (pl == 0 ? g_Wo_bf : g_Wp_bf) + (size_t)row * 128 + kc * 64 + q * 8;
        cp16(sbase + K3_W_OFF + p * 16384 + sw128((uint32_t)(row * 128 + q * 16)), src);
    }
    CP_COMMIT();

    // ---- gather g_T [c][r] -> s_t [r][132] fp32 ----
    #pragma unroll 1
    for (int it = 0; it < 16; it++) {
        int u = it * 256 + tid;
        int cch = u >> 5;                 // 0..127
        int q = u & 31;                   // float4 chunk
        float4 v = *reinterpret_cast<const float4*>(g_T + (size_t)cch * NN + r0 + q * 4);
        s_t[(q * 4 + 0) * 132 + cch] = v.x;
        s_t[(q * 4 + 1) * 132 + cch] = v.y;
        s_t[(q * 4 + 2) * 132 + cch] = v.z;
        s_t[(q * 4 + 3) * 132 + cch] = v.w;
    }
    __syncthreads();

    // ---- LN2 per row; emit bf16 A planes (raw tri + LN2(tri)) ----
    {
        const int c4 = lane * 4;
        const int kc = lane >> 4;
        const uint32_t kb = (lane & 15) * 8;
        float4 w4 = *reinterpret_cast<const float4*>(ln2w + c4);
        float4 b4 = *reinterpret_cast<const float4*>(ln2b + c4);
        #pragma unroll 1
        for (int rr = 0; rr < 16; rr++) {
            int rloc = warp * 16 + rr;
            float4 v = *reinterpret_cast<float4*>(&s_t[rloc * 132 + c4]);
            float s  = v.x + v.y + v.z + v.w;
            float s2 = v.x * v.x + v.y * v.y + v.z * v.z + v.w * v.w;
            #pragma unroll
            for (int o = 16; o; o >>= 1) {
                s  += __shfl_xor_sync(0xffffffffu, s, o);
                s2 += __shfl_xor_sync(0xffffffffu, s2, o);
            }
            float m = s * 0.0078125f;
            float var = fmaf(-m, m, s2 * 0.0078125f);
            float rstd = rsqrtf(var + 1e-5f);
            float zn[4] = {
                (v.x - m) * rstd * w4.x + b4.x,
                (v.y - m) * rstd * w4.y + b4.y,
                (v.z - m) * rstd * w4.z + b4.z,
                (v.w - m) * rstd * w4.w + b4.w };
            uint32_t sw = sw128((uint32_t)(rloc * 128) + kb);
            // plane 0: raw tri (gate matmul), plane 1: LN2(tri) (op matmul)
            *reinterpret_cast<uint2*>(smc + K3_A_OFF + (0*2 + kc) * 16384 + sw) =
                make_uint2(pack_bf2(v.x, v.y), pack_bf2(v.z, v.w));
            *reinterpret_cast<uint2*>(smc + K3_A_OFF + (1*2 + kc) * 16384 + sw) =
                make_uint2(pack_bf2(zn[0], zn[1]), pack_bf2(zn[2], zn[3]));
        }
    }
    CP_WAIT0();
    __syncthreads();

    // ---- MMA: accg (gate) / accz (op) over K=128 ----
    const int wm = (warp >> 1) * 32;
    const int wn = (warp & 1) * 64;

    const uint32_t a_row = (lane & 7) + ((lane >> 3) & 1) * 8;
    const uint32_t a_kb  = (lane >> 4) * 16;
    const uint32_t b_row = (lane & 7) + ((lane >> 4) & 1) * 8;
    const uint32_t b_kb  = ((lane >> 3) & 1) * 16;

    float accg[2][8][4], accz[2][8][4];
    #pragma unroll
    for (int mt = 0; mt < 2; mt++)
        #pragma unroll
        for (int nt = 0; nt < 8; nt++)
            #pragma unroll
            for (int q = 0; q < 4; q++) { accg[mt][nt][q] = 0.f; accz[mt][nt][q] = 0.f; }

    #pragma unroll
    for (int kc = 0; kc < 2; kc++) {
        #pragma unroll
        for (int ks = 0; ks < 4; ks++) {
            uint32_t kb = ks * 32;
            uint32_t ag[2][4], az[2][4];
            #pragma unroll
            for (int mt = 0; mt < 2; mt++) {
                uint32_t sw = sw128((uint32_t)((wm + mt * 16 + a_row) * 128) + kb + a_kb);
                ldm_x4(ag[mt], sbase + K3_A_OFF + (0*2 + kc) * 16384 + sw);
                ldm_x4(az[mt], sbase + K3_A_OFF + (1*2 + kc) * 16384 + sw);
            }
            #pragma unroll
            for (int ng = 0; ng < 4; ng++) {
                uint32_t sw = sw128((uint32_t)((wn + ng * 16 + b_row) * 128) + kb + b_kb);
                uint32_t wo[4], wp[4];
                ldm_x4(wo, sbase + K3_W_OFF + (0*2 + kc) * 16384 + sw);
                ldm_x4(wp, sbase + K3_W_OFF + (1*2 + kc) * 16384 + sw);
                #pragma unroll
                for (int mt = 0; mt < 2; mt++) {
                    #pragma unroll
                    for (int h = 0; h < 2; h++) {
                        mma16816(accg[mt][ng * 2 + h], ag[mt], wo[h*2], wo[h*2+1]);
                        mma16816(accz[mt][ng * 2 + h], az[mt], wp[h*2], wp[h*2+1]);
                    }
                }
            }
        }
    }

    // ---- epilogue: out = tri + sigmoid(accg+ogb)*(accz+outb) ----
    #pragma unroll
    for (int mt = 0; mt < 2; mt++) {
        int rl0 = wm + mt * 16 + (int)(lane >> 2);
        #pragma unroll
        for (int nt = 0; nt < 8; nt++) {
            int d = wn + nt * 8 + 2 * (int)(lane & 3);
            float ob0 = ogb[d],  ob1 = ogb[d + 1];
            float ub0 = outb[d], ub1 = outb[d + 1];
            float* cg = accg[mt][nt];
            float* cz = accz[mt][nt];
            float2 t0 = *reinterpret_cast<float2*>(&s_t[rl0 * 132 + d]);
            float2 t1 = *reinterpret_cast<float2*>(&s_t[(rl0 + 8) * 132 + d]);
            float2 o0, o1;
            o0.x = t0.x + sigmoidf_(cg[0] + ob0) * (cz[0] + ub0);
            o0.y = t0.y + sigmoidf_(cg[1] + ob1) * (cz[1] + ub1);
            o1.x = t1.x + sigmoidf_(cg[2] + ob0) * (cz[2] + ub0);
            o1.y = t1.y + sigmoidf_(cg[3] + ob1) * (cz[3] + ub1);
            *reinterpret_cast<float2*>(&out[(size_t)(r0 + rl0) * DDIM + d])     = o0;
            *reinterpret_cast<float2*>(&out[(size_t)(r0 + rl0 + 8) * DDIM + d]) = o1;
        }
    }
}

// ---------------------------------------------------------------------------
extern "C" void kernel_launch(void* const* d_in, const int* in_sizes, int n_in,
                              void* d_out, int out_size)
{
    const float* Z     = (const float*)d_in[0];
    const float* mask  = (const float*)d_in[1];
    const float* ln1w  = (const float*)d_in[2];
    const float* ln1b  = (const float*)d_in[3];
    const float* lrpw  = (const float*)d_in[4];
    const float* lrpb  = (const float*)d_in[5];
    const float* gatew = (const float*)d_in[6];
    const float* gateb = (const float*)d_in[7];
    const float* ogw   = (const float*)d_in[8];
    const float* ogb   = (const float*)d_in[9];
    const float* ln2w  = (const float*)d_in[10];
    const float* ln2b  = (const float*)d_in[11];
    const float* opw   = (const float*)d_in[12];
    const float* outb  = (const float*)d_in[13];
    float* out = (float*)d_out;

    cudaFuncSetAttribute(k1_mma,     cudaFuncAttributeMaxDynamicSharedMemorySize, K1_SMEM);
    cudaFuncSetAttribute(k2_tri_mma, cudaFuncAttributeMaxDynamicSharedMemorySize, K2_SMEM);
    cudaFuncSetAttribute(k3_mma,     cudaFuncAttributeMaxDynamicSharedMemorySize, K3_SMEM);

    k0_wprep<<<128, 256>>>(lrpw, gatew, ogw, opw);

    k1_mma<<<NN / 128, 256, K1_SMEM>>>(Z, mask, ln1w, ln1b, lrpb, gateb);

    dim3 g2(4, 4, 128);
    k2_tri_mma<<<g2, 256, K2_SMEM>>>();

    k3_mma<<<NN / 128, 256, K3_SMEM>>>(ogb, ln2w, ln2b, outb, out);
}

// round 7
// speedup vs baseline: 3.1621x; 1.0442x over previous
#include <cuda_runtime.h>
#include <cuda_bf16.h>
#include <cstdint>

#define NDIM 512
#define DDIM 128
#define NN (NDIM*NDIM)

// Scratch (allocation-free rule: __device__ globals)
__device__ __nv_bfloat16 g_Lhi[(size_t)DDIM * NN];   // [c][i][k]
__device__ __nv_bfloat16 g_Llo[(size_t)DDIM * NN];
__device__ __nv_bfloat16 g_Rhi[(size_t)DDIM * NN];   // [c][j][k]
__device__ __nv_bfloat16 g_Rlo[(size_t)DDIM * NN];
__device__ float g_T[(size_t)DDIM * NN];             // [c][i][j]
// split-bf16 weights for stage-1 (prepped by k0)
__device__ __nv_bfloat16 g_Wl_hi[256 * 128];
__device__ __nv_bfloat16 g_Wl_lo[256 * 128];
__device__ __nv_bfloat16 g_Wg_hi[256 * 128];
// bf16 weights for stage-2 (og / op)
__device__ __nv_bfloat16 g_Wo_bf[128 * 128];
__device__ __nv_bfloat16 g_Wp_bf[128 * 128];

__device__ __forceinline__ float sigmoidf_(float x) {
    return 1.0f / (1.0f + __expf(-x));
}

__device__ __forceinline__ uint32_t smem_u32(const void* p) {
    uint32_t a;
    asm("{ .reg .u64 t; cvta.to.shared.u64 t, %1; cvt.u32.u64 %0, t; }" : "=r"(a) : "l"(p));
    return a;
}

__device__ __forceinline__ uint32_t sw128(uint32_t bo) {
    return bo ^ ((bo >> 3) & 0x70);
}

__device__ __forceinline__ void cp16(uint32_t dst, const void* src) {
    asm volatile("cp.async.cg.shared.global [%0], [%1], 16;" :: "r"(dst), "l"(src) : "memory");
}
#define CP_COMMIT() asm volatile("cp.async.commit_group;" ::: "memory")
#define CP_WAIT0()  asm volatile("cp.async.wait_group 0;" ::: "memory")
#define CP_WAIT1()  asm volatile("cp.async.wait_group 1;" ::: "memory")

__device__ __forceinline__ void ldm_x4(uint32_t r[4], uint32_t addr) {
    asm volatile("ldmatrix.sync.aligned.m8n8.x4.shared.b16 {%0,%1,%2,%3}, [%4];"
        : "=r"(r[0]), "=r"(r[1]), "=r"(r[2]), "=r"(r[3]) : "r"(addr));
}

__device__ __forceinline__ void mma16816(float c[4], const uint32_t a[4],
                                         uint32_t b0, uint32_t b1) {
    asm volatile("mma.sync.aligned.m16n8k16.row.col.f32.bf16.bf16.f32 "
        "{%0,%1,%2,%3}, {%4,%5,%6,%7}, {%8,%9}, {%0,%1,%2,%3};"
        : "+f"(c[0]), "+f"(c[1]), "+f"(c[2]), "+f"(c[3])
        : "r"(a[0]), "r"(a[1]), "r"(a[2]), "r"(a[3]), "r"(b0), "r"(b1));
}

__device__ __forceinline__ uint32_t pack_split(float v) {
    __nv_bfloat16 hi = __float2bfloat16(v);
    __nv_bfloat16 lo = __float2bfloat16(v - __bfloat162float(hi));
    uint32_t h = *reinterpret_cast<unsigned short*>(&hi);
    uint32_t l = *reinterpret_cast<unsigned short*>(&lo);
    return h | (l << 16);
}

__device__ __forceinline__ uint32_t pack_bf2(float a, float b) {
    __nv_bfloat16 h0 = __float2bfloat16(a);
    __nv_bfloat16 h1 = __float2bfloat16(b);
    return (uint32_t)*reinterpret_cast<unsigned short*>(&h0) |
           ((uint32_t)*reinterpret_cast<unsigned short*>(&h1) << 16);
}

// ---------------------------------------------------------------------------
// Kernel 0: weight prep (split lrp, bf16 gate/og/op)
// ---------------------------------------------------------------------------
__global__ void k0_wprep(const float* __restrict__ lrpw, const float* __restrict__ gatew,
                         const float* __restrict__ ogw,  const float* __restrict__ opw)
{
    int i = blockIdx.x * blockDim.x + threadIdx.x;
    if (i < 256 * 128) {
        float v = lrpw[i];
        __nv_bfloat16 h = __float2bfloat16(v);
        g_Wl_hi[i] = h;
        g_Wl_lo[i] = __float2bfloat16(v - __bfloat162float(h));
        g_Wg_hi[i] = __float2bfloat16(gatew[i]);
    }
    if (i < 128 * 128) {
        g_Wo_bf[i] = __float2bfloat16(ogw[i]);
        g_Wp_bf[i] = __float2bfloat16(opw[i]);
    }
}

// ---------------------------------------------------------------------------
// Kernel 1 (HMMA): LN1 + lrp (3-prod) / gate (1-prod) + gating -> split L/R
// ---------------------------------------------------------------------------
#define K1_A_OFF   0
#define K1_W_OFF   65536
#define K1_ST_OFF  114688
#define K1_SMEM    148480

__global__ __launch_bounds__(256, 1)
void k1_mma(const float* __restrict__ Z, const float* __restrict__ mask,
            const float* __restrict__ ln1w, const float* __restrict__ ln1b,
            const float* __restrict__ lrpb, const float* __restrict__ gateb)
{
    extern __shared__ __align__(1024) char smc[];
    const uint32_t sbase = smem_u32(smc);
    uint32_t* stage = reinterpret_cast<uint32_t*>(smc + K1_ST_OFF);

    const int tid = threadIdx.x;
    const int warp = tid >> 5;
    const uint32_t lane = tid & 31;
    const int r0 = blockIdx.x * 128;

    // ---- Phase A: load Z rows, LN1, split-bf16 into swizzled A planes ----
    {
        const int k4 = lane * 4;
        const int kc = lane >> 4;
        const uint32_t kb = (lane & 15) * 8;
        float4 w4 = *reinterpret_cast<const float4*>(ln1w + k4);
        float4 b4 = *reinterpret_cast<const float4*>(ln1b + k4);
        #pragma unroll 1
        for (int rr = 0; rr < 16; rr++) {
            int rloc = warp * 16 + rr;
            float4 v = *reinterpret_cast<const float4*>(Z + (size_t)(r0 + rloc) * DDIM + k4);
            float s  = v.x + v.y + v.z + v.w;
            float s2 = v.x * v.x + v.y * v.y + v.z * v.z + v.w * v.w;
            #pragma unroll
            for (int o = 16; o; o >>= 1) {
                s  += __shfl_xor_sync(0xffffffffu, s, o);
                s2 += __shfl_xor_sync(0xffffffffu, s2, o);
            }
            float m = s * 0.0078125f;
            float var = fmaf(-m, m, s2 * 0.0078125f);
            float rstd = rsqrtf(var + 1e-5f);
            float zn[4] = {
                (v.x - m) * rstd * w4.x + b4.x,
                (v.y - m) * rstd * w4.y + b4.y,
                (v.z - m) * rstd * w4.z + b4.z,
                (v.w - m) * rstd * w4.w + b4.w };
            uint32_t hip[2], lop[2];
            #pragma unroll
            for (int q = 0; q < 2; q++) {
                __nv_bfloat16 h0 = __float2bfloat16(zn[q*2]);
                __nv_bfloat16 h1 = __float2bfloat16(zn[q*2+1]);
                __nv_bfloat16 l0 = __float2bfloat16(zn[q*2]   - __bfloat162float(h0));
                __nv_bfloat16 l1 = __float2bfloat16(zn[q*2+1] - __bfloat162float(h1));
                hip[q] = (uint32_t)*reinterpret_cast<unsigned short*>(&h0) |
                         ((uint32_t)*reinterpret_cast<unsigned short*>(&h1) << 16);
                lop[q] = (uint32_t)*reinterpret_cast<unsigned short*>(&l0) |
                         ((uint32_t)*reinterpret_cast<unsigned short*>(&l1) << 16);
            }
            uint32_t sw = sw128((uint32_t)(rloc * 128) + kb);
            *reinterpret_cast<uint2*>(smc + K1_A_OFF + (0*2 + kc) * 16384 + sw) = make_uint2(hip[0], hip[1]);
            *reinterpret_cast<uint2*>(smc + K1_A_OFF + (1*2 + kc) * 16384 + sw) = make_uint2(lop[0], lop[1]);
        }
    }
    __syncthreads();

    const int wm = (warp >> 1) * 32;
    const int wn = (warp & 1) * 32;

    const uint32_t a_row = (lane & 7) + ((lane >> 3) & 1) * 8;
    const uint32_t a_kb  = (lane >> 4) * 16;
    const uint32_t b_row = (lane & 7) + ((lane >> 4) & 1) * 8;
    const uint32_t b_kb  = ((lane >> 3) & 1) * 16;

    const __nv_bfloat16* wtab[3] = { g_Wl_hi, g_Wl_lo, g_Wg_hi };

    #pragma unroll 1
    for (int ct = 0; ct < 4; ct++) {
        const int cbase = ct * 64;

        // ---- load 6 W planes (3 mats x 2 kc) via cp.async ----
        #pragma unroll
        for (int it = 0; it < 12; it++) {
            int u = it * 256 + tid;
            int p = u >> 9; int idx = u & 511;
            int row = idx >> 3, q = idx & 7;
            int shl = p >> 1, kc = p & 1;
            const __nv_bfloat16* src = wtab[shl] + (size_t)(cbase + row) * 128 + kc * 64 + q * 8;
            cp16(sbase + K1_W_OFF + p * 8192 + sw128((uint32_t)(row * 128 + q * 16)), src);
        }
        CP_COMMIT();
        CP_WAIT0();
        __syncthreads();

        float accl[2][4][4], accg[2][4][4];
        #pragma unroll
        for (int mt = 0; mt < 2; mt++)
            #pragma unroll
            for (int nt = 0; nt < 4; nt++)
                #pragma unroll
                for (int q = 0; q < 4; q++) { accl[mt][nt][q] = 0.f; accg[mt][nt][q] = 0.f; }

        #pragma unroll
        for (int kc = 0; kc < 2; kc++) {
            #pragma unroll
            for (int ks = 0; ks < 4; ks++) {
                uint32_t kb = ks * 32;
                uint32_t ah[2][4], al[2][4];
                #pragma unroll
                for (int mt = 0; mt < 2; mt++) {
                    uint32_t sw = sw128((uint32_t)((wm + mt * 16 + a_row) * 128) + kb + a_kb);
                    ldm_x4(ah[mt], sbase + K1_A_OFF + (0*2 + kc) * 16384 + sw);
                    ldm_x4(al[mt], sbase + K1_A_OFF + (1*2 + kc) * 16384 + sw);
                }
                #pragma unroll
                for (int ng = 0; ng < 2; ng++) {
                    uint32_t sw = sw128((uint32_t)((wn + ng * 16 + b_row) * 128) + kb + b_kb);
                    uint32_t wlh[4], wll[4], wgh[4];
                    ldm_x4(wlh, sbase + K1_W_OFF + (0 + kc) * 8192 + sw);
                    ldm_x4(wll, sbase + K1_W_OFF + (2 + kc) * 8192 + sw);
                    ldm_x4(wgh, sbase + K1_W_OFF + (4 + kc) * 8192 + sw);
                    #pragma unroll
                    for (int mt = 0; mt < 2; mt++) {
                        #pragma unroll
                        for (int h = 0; h < 2; h++) {
                            float* cl = accl[mt][ng * 2 + h];
                            float* cg = accg[mt][ng * 2 + h];
                            mma16816(cl, ah[mt], wlh[h*2], wlh[h*2+1]);
                            mma16816(cl, ah[mt], wll[h*2], wll[h*2+1]);
                            mma16816(cl, al[mt], wlh[h*2], wlh[h*2+1]);
                            mma16816(cg, ah[mt], wgh[h*2], wgh[h*2+1]);
                        }
                    }
                }
            }
        }

        #pragma unroll
        for (int mt = 0; mt < 2; mt++) {
            int rl0 = wm + mt * 16 + (int)(lane >> 2);
            float m0 = mask[r0 + rl0];
            float m1 = mask[r0 + rl0 + 8];
            #pragma unroll
            for (int nt = 0; nt < 4; nt++) {
                int cl0 = wn + nt * 8 + 2 * (int)(lane & 3);
                float lb0 = lrpb[cbase + cl0],  lb1 = lrpb[cbase + cl0 + 1];
                float gb0 = gateb[cbase + cl0], gb1 = gateb[cbase + cl0 + 1];
                float* vl = accl[mt][nt];
                float* vg = accg[mt][nt];
                stage[(cl0    ) * 132 + rl0    ] = pack_split((vl[0] + lb0) * m0 * sigmoidf_(vg[0] + gb0));
                stage[(cl0 + 1) * 132 + rl0    ] = pack_split((vl[1] + lb1) * m0 * sigmoidf_(vg[1] + gb1));
                stage[(cl0    ) * 132 + rl0 + 8] = pack_split((vl[2] + lb0) * m1 * sigmoidf_(vg[2] + gb0));
                stage[(cl0 + 1) * 132 + rl0 + 8] = pack_split((vl[3] + lb1) * m1 * sigmoidf_(vg[3] + gb1));
            }
        }
        __syncthreads();

        {
            int c_loc = tid >> 2;
            int seg = tid & 3;
            int cg = cbase + c_loc;
            __nv_bfloat16* hiP = (cg < 128) ? (g_Lhi + (size_t)cg * NN) : (g_Rhi + (size_t)(cg - 128) * NN);
            __nv_bfloat16* loP = (cg < 128) ? (g_Llo + (size_t)cg * NN) : (g_Rlo + (size_t)(cg - 128) * NN);
            int rb = seg * 32;
            const uint32_t* srow = &stage[c_loc * 132 + rb];
            #pragma unroll
            for (int blk = 0; blk < 4; blk++) {
                uint32_t hw[4], lw[4];
                #pragma unroll
                for (int q = 0; q < 4; q++) {
                    uint32_t p0 = srow[blk * 8 + q * 2];
                    uint32_t p1 = srow[blk * 8 + q * 2 + 1];
                    hw[q] = (p0 & 0xffffu) | (p1 << 16);
                    lw[q] = (p0 >> 16) | (p1 & 0xffff0000u);
                }
                *reinterpret_cast<uint4*>(hiP + r0 + rb + blk * 8) = make_uint4(hw[0], hw[1], hw[2], hw[3]);
                *reinterpret_cast<uint4*>(loP + r0 + rb + blk * 8) = make_uint4(lw[0], lw[1], lw[2], lw[3]);
            }
        }
        __syncthreads();
    }
}

// ---------------------------------------------------------------------------
// Kernel 2: split-bf16 mma.sync GEMM  T_c = L_c @ R_c^T   (3-stage pipeline)
// ---------------------------------------------------------------------------
#define PLANE 16384
#define STAGE (4 * PLANE)
#define K2_SMEM (3 * STAGE)   // 196608

__device__ __forceinline__ void k2_prefetch(uint32_t sbase, int stage_i,
    const __nv_bfloat16* Ah, const __nv_bfloat16* Al,
    const __nv_bfloat16* Bh, const __nv_bfloat16* Bl,
    int i0, int j0, int k0, int tid)
{
    const __nv_bfloat16* srcs[4] = {Ah, Al, Bh, Bl};
    const int bases[4] = {i0, i0, j0, j0};
    uint32_t st = sbase + stage_i * STAGE;
    #pragma unroll
    for (int p = 0; p < 4; p++) {
        const __nv_bfloat16* s = srcs[p];
        int rb = bases[p];
        #pragma unroll
        for (int it = 0; it < 4; it++) {
            int idx = it * 256 + tid;
            int r = idx >> 3, q = idx & 7;
            uint32_t dst = st + p * PLANE + sw128((uint32_t)(r * 128 + q * 16));
            cp16(dst, s + (size_t)(rb + r) * NDIM + k0 + q * 8);
        }
    }
}

__global__ __launch_bounds__(256, 1)
void k2_tri_mma()
{
    extern __shared__ __align__(1024) char smc[];
    const uint32_t sbase = smem_u32(smc);
    const int tid = threadIdx.x;
    const int warp = tid >> 5;
    const uint32_t lane = tid & 31;
    const int c = blockIdx.z;
    const int i0 = blockIdx.x * 128, j0 = blockIdx.y * 128;

    const __nv_bfloat16* __restrict__ Ah = g_Lhi + (size_t)c * NN;
    const __nv_bfloat16* __restrict__ Al = g_Llo + (size_t)c * NN;
    const __nv_bfloat16* __restrict__ Bh = g_Rhi + (size_t)c * NN;
    const __nv_bfloat16* __restrict__ Bl = g_Rlo + (size_t)c * NN;
    float* __restrict__ Tc = g_T + (size_t)c * NN;

    const int wm = (warp >> 1) * 32;
    const int wn = (warp & 1) * 64;

    const uint32_t a_row = (lane & 7) + ((lane >> 3) & 1) * 8;
    const uint32_t a_kb  = (lane >> 4) * 16;
    const uint32_t b_row = (lane & 7) + ((lane >> 4) & 1) * 8;
    const uint32_t b_kb  = ((lane >> 3) & 1) * 16;

    float acc[2][8][4];
    #pragma unroll
    for (int mt = 0; mt < 2; mt++)
        #pragma unroll
        for (int nt = 0; nt < 8; nt++)
            #pragma unroll
            for (int q = 0; q < 4; q++) acc[mt][nt][q] = 0.0f;

    k2_prefetch(sbase, 0, Ah, Al, Bh, Bl, i0, j0, 0, tid);
    CP_COMMIT();
    k2_prefetch(sbase, 1, Ah, Al, Bh, Bl, i0, j0, 64, tid);
    CP_COMMIT();

    #pragma unroll 1
    for (int ch = 0; ch < 8; ch++) {
        if (ch == 7) { CP_WAIT0(); } else { CP_WAIT1(); }
        __syncthreads();
        if (ch + 2 < 8) {
            k2_prefetch(sbase, (ch + 2) % 3, Ah, Al, Bh, Bl, i0, j0, (ch + 2) * 64, tid);
            CP_COMMIT();
        }
        uint32_t st = sbase + (ch % 3) * STAGE;
        uint32_t sAh = st, sAl = st + PLANE, sBh = st + 2 * PLANE, sBl = st + 3 * PLANE;

        #pragma unroll
        for (int ks = 0; ks < 4; ks++) {
            uint32_t kb = ks * 32;
            uint32_t ah[2][4], al[2][4];
            #pragma unroll
            for (int mt = 0; mt < 2; mt++) {
                uint32_t sw = sw128((uint32_t)((wm + mt * 16 + a_row) * 128) + kb + a_kb);
                ldm_x4(ah[mt], sAh + sw);
                ldm_x4(al[mt], sAl + sw);
            }
            #pragma unroll
            for (int ng = 0; ng < 4; ng++) {
                uint32_t sw = sw128((uint32_t)((wn + ng * 16 + b_row) * 128) + kb + b_kb);
                uint32_t bh[4], bl[4];
                ldm_x4(bh, sBh + sw);
                ldm_x4(bl, sBl + sw);
                #pragma unroll
                for (int mt = 0; mt < 2; mt++) {
                    #pragma unroll
                    for (int h = 0; h < 2; h++) {
                        float* cc = acc[mt][ng * 2 + h];
                        mma16816(cc, ah[mt], bh[h * 2], bh[h * 2 + 1]);
                        mma16816(cc, ah[mt], bl[h * 2], bl[h * 2 + 1]);
                        mma16816(cc, al[mt], bh[h * 2], bh[h * 2 + 1]);
                    }
                }
            }
        }
    }

    const int rbase = i0 + wm + (int)(lane >> 2);
    const int cbase = j0 + wn + 2 * (int)(lane & 3);
    #pragma unroll
    for (int mt = 0; mt < 2; mt++) {
        #pragma unroll
        for (int nt = 0; nt < 8; nt++) {
            float* cc = acc[mt][nt];
            int col = cbase + nt * 8;
            int r1 = rbase + mt * 16;
            *reinterpret_cast<float2*>(&Tc[(size_t)r1 * NDIM + col])       = make_float2(cc[0], cc[1]);
            *reinterpret_cast<float2*>(&Tc[(size_t)(r1 + 8) * NDIM + col]) = make_float2(cc[2], cc[3]);
        }
    }
}

// ---------------------------------------------------------------------------
// Kernel 3 (HMMA): 64 rows x 64 cols per CTA, 2 CTAs/SM.
// smem: s_t fp32 [64][132] | A planes 4x8KB | W planes 4x8KB  = 99328 B
// ---------------------------------------------------------------------------
#define K3_T_OFF   0
#define K3_A_OFF   33792
#define K3_W_OFF   66560
#define K3_SMEM    99328

__global__ __launch_bounds__(256, 2)
void k3_mma(const float* __restrict__ ogb, const float* __restrict__ ln2w,
            const float* __restrict__ ln2b, const float* __restrict__ outb,
            float* __restrict__ out)
{
    extern __shared__ __align__(1024) char smc[];
    const uint32_t sbase = smem_u32(smc);
    float* s_t = reinterpret_cast<float*>(smc + K3_T_OFF);   // [64][132]

    const int tid = threadIdx.x;
    const int warp = tid >> 5;
    const uint32_t lane = tid & 31;
    const int r0 = blockIdx.x * 64;
    const int ch0 = blockIdx.y * 64;     // output-column half

    // ---- W planes via cp.async: (og,op) x kc, 64 d-rows each ----
    #pragma unroll
    for (int it = 0; it < 8; it++) {
        int u = it * 256 + tid;
        int p = u >> 9; int idx = u & 511;
        int row = idx >> 3, q = idx & 7;
        int pl = p >> 1, kc = p & 1;
        const __nv_bfloat16* src = (pl == 0 ? g_Wo_bf : g_Wp_bf) + (size_t)(ch0 + row) * 128 + kc * 64 + q * 8;
        cp16(sbase + K3_W_OFF + p * 8192 + sw128((uint32_t)(row * 128 + q * 16)), src);
    }
    CP_COMMIT();

    // ---- gather g_T [c][r] -> s_t [r][132] fp32 (64 rows) ----
    #pragma unroll 1
    for (int it = 0; it < 8; it++) {
        int u = it * 256 + tid;
        int cch = u >> 4;                 // 0..127
        int q = u & 15;                   // float4 chunk over 64 rows
        float4 v = *reinterpret_cast<const float4*>(g_T + (size_t)cch * NN + r0 + q * 4);
        s_t[(q * 4 + 0) * 132 + cch] = v.x;
        s_t[(q * 4 + 1) * 132 + cch] = v.y;
        s_t[(q * 4 + 2) * 132 + cch] = v.z;
        s_t[(q * 4 + 3) * 132 + cch] = v.w;
    }
    __syncthreads();

    // ---- LN2 per row (8 rows/warp); emit bf16 A planes ----
    {
        const int c4 = lane * 4;
        const int kc = lane >> 4;
        const uint32_t kb = (lane & 15) * 8;
        float4 w4 = *reinterpret_cast<const float4*>(ln2w + c4);
        float4 b4 = *reinterpret_cast<const float4*>(ln2b + c4);
        #pragma unroll 1
        for (int rr = 0; rr < 8; rr++) {
            int rloc = warp * 8 + rr;
            float4 v = *reinterpret_cast<float4*>(&s_t[rloc * 132 + c4]);
            float s  = v.x + v.y + v.z + v.w;
            float s2 = v.x * v.x + v.y * v.y + v.z * v.z + v.w * v.w;
            #pragma unroll
            for (int o = 16; o; o >>= 1) {
                s  += __shfl_xor_sync(0xffffffffu, s, o);
                s2 += __shfl_xor_sync(0xffffffffu, s2, o);
            }
            float m = s * 0.0078125f;
            float var = fmaf(-m, m, s2 * 0.0078125f);
            float rstd = rsqrtf(var + 1e-5f);
            float zn[4] = {
                (v.x - m) * rstd * w4.x + b4.x,
                (v.y - m) * rstd * w4.y + b4.y,
                (v.z - m) * rstd * w4.z + b4.z,
                (v.w - m) * rstd * w4.w + b4.w };
            uint32_t sw = sw128((uint32_t)(rloc * 128) + kb);
            *reinterpret_cast<uint2*>(smc + K3_A_OFF + (0*2 + kc) * 8192 + sw) =
                make_uint2(pack_bf2(v.x, v.y), pack_bf2(v.z, v.w));
            *reinterpret_cast<uint2*>(smc + K3_A_OFF + (1*2 + kc) * 8192 + sw) =
                make_uint2(pack_bf2(zn[0], zn[1]), pack_bf2(zn[2], zn[3]));
        }
    }
    CP_WAIT0();
    __syncthreads();

    // ---- MMA: 16x32 warp tile, K=128 ----
    const int wm = (warp >> 1) * 16;
    const int wn = (warp & 1) * 32;

    const uint32_t a_row = (lane & 7) + ((lane >> 3) & 1) * 8;
    const uint32_t a_kb  = (lane >> 4) * 16;
    const uint32_t b_row = (lane & 7) + ((lane >> 4) & 1) * 8;
    const uint32_t b_kb  = ((lane >> 3) & 1) * 16;

    float accg[4][4], accz[4][4];
    #pragma unroll
    for (int nt = 0; nt < 4; nt++)
        #pragma unroll
        for (int q = 0; q < 4; q++) { accg[nt][q] = 0.f; accz[nt][q] = 0.f; }

    #pragma unroll
    for (int kc = 0; kc < 2; kc++) {
        #pragma unroll
        for (int ks = 0; ks < 4; ks++) {
            uint32_t kb = ks * 32;
            uint32_t ag[4], az[4];
            uint32_t swa = sw128((uint32_t)((wm + a_row) * 128) + kb + a_kb);
            ldm_x4(ag, sbase + K3_A_OFF + (0*2 + kc) * 8192 + swa);
            ldm_x4(az, sbase + K3_A_OFF + (1*2 + kc) * 8192 + swa);
            #pragma unroll
            for (int ng = 0; ng < 2; ng++) {
                uint32_t swb = sw128((uint32_t)((wn + ng * 16 + b_row) * 128) + kb + b_kb);
                uint32_t wo[4], wp[4];
                ldm_x4(wo, sbase + K3_W_OFF + (0*2 + kc) * 8192 + swb);
                ldm_x4(wp, sbase + K3_W_OFF + (1*2 + kc) * 8192 + swb);
                #pragma unroll
                for (int h = 0; h < 2; h++) {
                    mma16816(accg[ng * 2 + h], ag, wo[h*2], wo[h*2+1]);
                    mma16816(accz[ng * 2 + h], az, wp[h*2], wp[h*2+1]);
                }
            }
        }
    }

    // ---- epilogue: out = tri + sigmoid(accg+ogb)*(accz+outb) ----
    {
        int rl0 = wm + (int)(lane >> 2);
        #pragma unroll
        for (int nt = 0; nt < 4; nt++) {
            int dl = wn + nt * 8 + 2 * (int)(lane & 3);
            int d = ch0 + dl;
            float ob0 = ogb[d],  ob1 = ogb[d + 1];
            float ub0 = outb[d], ub1 = outb[d + 1];
            float* cg = accg[nt];
            float* cz = accz[nt];
            float2 t0 = *reinterpret_cast<float2*>(&s_t[rl0 * 132 + d]);
            float2 t1 = *reinterpret_cast<float2*>(&s_t[(rl0 + 8) * 132 + d]);
            float2 o0, o1;
            o0.x = t0.x + sigmoidf_(cg[0] + ob0) * (cz[0] + ub0);
            o0.y = t0.y + sigmoidf_(cg[1] + ob1) * (cz[1] + ub1);
            o1.x = t1.x + sigmoidf_(cg[2] + ob0) * (cz[2] + ub0);
            o1.y = t1.y + sigmoidf_(cg[3] + ob1) * (cz[3] + ub1);
            *reinterpret_cast<float2*>(&out[(size_t)(r0 + rl0) * DDIM + d])     = o0;
            *reinterpret_cast<float2*>(&out[(size_t)(r0 + rl0 + 8) * DDIM + d]) = o1;
        }
    }
}

// ---------------------------------------------------------------------------
extern "C" void kernel_launch(void* const* d_in, const int* in_sizes, int n_in,
                              void* d_out, int out_size)
{
    const float* Z     = (const float*)d_in[0];
    const float* mask  = (const float*)d_in[1];
    const float* ln1w  = (const float*)d_in[2];
    const float* ln1b  = (const float*)d_in[3];
    const float* lrpw  = (const float*)d_in[4];
    const float* lrpb  = (const float*)d_in[5];
    const float* gatew = (const float*)d_in[6];
    const float* gateb = (const float*)d_in[7];
    const float* ogw   = (const float*)d_in[8];
    const float* ogb   = (const float*)d_in[9];
    const float* ln2w  = (const float*)d_in[10];
    const float* ln2b  = (const float*)d_in[11];
    const float* opw   = (const float*)d_in[12];
    const float* outb  = (const float*)d_in[13];
    float* out = (float*)d_out;

    cudaFuncSetAttribute(k1_mma,     cudaFuncAttributeMaxDynamicSharedMemorySize, K1_SMEM);
    cudaFuncSetAttribute(k2_tri_mma, cudaFuncAttributeMaxDynamicSharedMemorySize, K2_SMEM);
    cudaFuncSetAttribute(k3_mma,     cudaFuncAttributeMaxDynamicSharedMemorySize, K3_SMEM);

    k0_wprep<<<128, 256>>>(lrpw, gatew, ogw, opw);

    k1_mma<<<NN / 128, 256, K1_SMEM>>>(Z, mask, ln1w, ln1b, lrpb, gateb);

    dim3 g2(4, 4, 128);
    k2_tri_mma<<<g2, 256, K2_SMEM>>>();

    k3_mma<<<dim3(NN / 64, 2), 256, K3_SMEM>>>(ogb, ln2w, ln2b, outb, out);
}

// round 8
// speedup vs baseline: 4.4212x; 1.3982x over previous
#include <cuda_runtime.h>
#include <cuda_bf16.h>
#include <cstdint>

#define NDIM 512
#define DDIM 128
#define NN (NDIM*NDIM)

// Scratch (allocation-free rule: __device__ globals)
__device__ __nv_bfloat16 g_Lhi[(size_t)DDIM * NN];   // [c][i][k]
__device__ __nv_bfloat16 g_Llo[(size_t)DDIM * NN];
__device__ __nv_bfloat16 g_Rhi[(size_t)DDIM * NN];   // [c][j][k]
__device__ __nv_bfloat16 g_Rlo[(size_t)DDIM * NN];
__device__ float g_T[(size_t)DDIM * NN];             // [c][i][j]
// split-bf16 weights for stage-1 (prepped by k0)
__device__ __nv_bfloat16 g_Wl_hi[256 * 128];
__device__ __nv_bfloat16 g_Wl_lo[256 * 128];
__device__ __nv_bfloat16 g_Wg_hi[256 * 128];
// bf16 weights for stage-2 (og / op)
__device__ __nv_bfloat16 g_Wo_bf[128 * 128];
__device__ __nv_bfloat16 g_Wp_bf[128 * 128];

__device__ __forceinline__ float sigmoidf_(float x) {
    return 1.0f / (1.0f + __expf(-x));
}

__device__ __forceinline__ uint32_t smem_u32(const void* p) {
    uint32_t a;
    asm("{ .reg .u64 t; cvta.to.shared.u64 t, %1; cvt.u32.u64 %0, t; }" : "=r"(a) : "l"(p));
    return a;
}

__device__ __forceinline__ uint32_t sw128(uint32_t bo) {
    return bo ^ ((bo >> 3) & 0x70);
}

__device__ __forceinline__ void cp16(uint32_t dst, const void* src) {
    asm volatile("cp.async.cg.shared.global [%0], [%1], 16;" :: "r"(dst), "l"(src) : "memory");
}
#define CP_COMMIT() asm volatile("cp.async.commit_group;" ::: "memory")
#define CP_WAIT0()  asm volatile("cp.async.wait_group 0;" ::: "memory")
#define CP_WAIT1()  asm volatile("cp.async.wait_group 1;" ::: "memory")

__device__ __forceinline__ void ldm_x4(uint32_t r[4], uint32_t addr) {
    asm volatile("ldmatrix.sync.aligned.m8n8.x4.shared.b16 {%0,%1,%2,%3}, [%4];"
        : "=r"(r[0]), "=r"(r[1]), "=r"(r[2]), "=r"(r[3]) : "r"(addr));
}

__device__ __forceinline__ void mma16816(float c[4], const uint32_t a[4],
                                         uint32_t b0, uint32_t b1) {
    asm volatile("mma.sync.aligned.m16n8k16.row.col.f32.bf16.bf16.f32 "
        "{%0,%1,%2,%3}, {%4,%5,%6,%7}, {%8,%9}, {%0,%1,%2,%3};"
        : "+f"(c[0]), "+f"(c[1]), "+f"(c[2]), "+f"(c[3])
        : "r"(a[0]), "r"(a[1]), "r"(a[2]), "r"(a[3]), "r"(b0), "r"(b1));
}

__device__ __forceinline__ uint32_t pack_split(float v) {
    __nv_bfloat16 hi = __float2bfloat16(v);
    __nv_bfloat16 lo = __float2bfloat16(v - __bfloat162float(hi));
    uint32_t h = *reinterpret_cast<unsigned short*>(&hi);
    uint32_t l = *reinterpret_cast<unsigned short*>(&lo);
    return h | (l << 16);
}

__device__ __forceinline__ uint32_t pack_bf2(float a, float b) {
    __nv_bfloat16 h0 = __float2bfloat16(a);
    __nv_bfloat16 h1 = __float2bfloat16(b);
    return (uint32_t)*reinterpret_cast<unsigned short*>(&h0) |
           ((uint32_t)*reinterpret_cast<unsigned short*>(&h1) << 16);
}

// ---------------------------------------------------------------------------
// Kernel 0: weight prep (split lrp, bf16 gate/og/op)
// ---------------------------------------------------------------------------
__global__ void k0_wprep(const float* __restrict__ lrpw, const float* __restrict__ gatew,
                         const float* __restrict__ ogw,  const float* __restrict__ opw)
{
    int i = blockIdx.x * blockDim.x + threadIdx.x;
    if (i < 256 * 128) {
        float v = lrpw[i];
        __nv_bfloat16 h = __float2bfloat16(v);
        g_Wl_hi[i] = h;
        g_Wl_lo[i] = __float2bfloat16(v - __bfloat162float(h));
        g_Wg_hi[i] = __float2bfloat16(gatew[i]);
    }
    if (i < 128 * 128) {
        g_Wo_bf[i] = __float2bfloat16(ogw[i]);
        g_Wp_bf[i] = __float2bfloat16(opw[i]);
    }
}

// ---------------------------------------------------------------------------
// Kernel 1 (HMMA): LN1 + lrp (3-prod) / gate (1-prod) + gating -> split L/R
// smem: A planes 64KB | W planes 48KB (stage buffer ALIASES W region)
// 112KB -> 2 CTAs/SM
// ---------------------------------------------------------------------------
#define K1_A_OFF   0
#define K1_W_OFF   65536
#define K1_SMEM    114688

__global__ __launch_bounds__(256, 2)
void k1_mma(const float* __restrict__ Z, const float* __restrict__ mask,
            const float* __restrict__ ln1w, const float* __restrict__ ln1b,
            const float* __restrict__ lrpb, const float* __restrict__ gateb)
{
    extern __shared__ __align__(1024) char smc[];
    const uint32_t sbase = smem_u32(smc);
    uint32_t* stage = reinterpret_cast<uint32_t*>(smc + K1_W_OFF);   // aliases W planes

    const int tid = threadIdx.x;
    const int warp = tid >> 5;
    const uint32_t lane = tid & 31;
    const int r0 = blockIdx.x * 128;

    // ---- Phase A: load Z rows, LN1, split-bf16 into swizzled A planes ----
    {
        const int k4 = lane * 4;
        const int kc = lane >> 4;
        const uint32_t kb = (lane & 15) * 8;
        float4 w4 = *reinterpret_cast<const float4*>(ln1w + k4);
        float4 b4 = *reinterpret_cast<const float4*>(ln1b + k4);
        #pragma unroll 1
        for (int rr = 0; rr < 16; rr++) {
            int rloc = warp * 16 + rr;
            float4 v = *reinterpret_cast<const float4*>(Z + (size_t)(r0 + rloc) * DDIM + k4);
            float s  = v.x + v.y + v.z + v.w;
            float s2 = v.x * v.x + v.y * v.y + v.z * v.z + v.w * v.w;
            #pragma unroll
            for (int o = 16; o; o >>= 1) {
                s  += __shfl_xor_sync(0xffffffffu, s, o);
                s2 += __shfl_xor_sync(0xffffffffu, s2, o);
            }
            float m = s * 0.0078125f;
            float var = fmaf(-m, m, s2 * 0.0078125f);
            float rstd = rsqrtf(var + 1e-5f);
            float zn[4] = {
                (v.x - m) * rstd * w4.x + b4.x,
                (v.y - m) * rstd * w4.y + b4.y,
                (v.z - m) * rstd * w4.z + b4.z,
                (v.w - m) * rstd * w4.w + b4.w };
            uint32_t hip[2], lop[2];
            #pragma unroll
            for (int q = 0; q < 2; q++) {
                __nv_bfloat16 h0 = __float2bfloat16(zn[q*2]);
                __nv_bfloat16 h1 = __float2bfloat16(zn[q*2+1]);
                __nv_bfloat16 l0 = __float2bfloat16(zn[q*2]   - __bfloat162float(h0));
                __nv_bfloat16 l1 = __float2bfloat16(zn[q*2+1] - __bfloat162float(h1));
                hip[q] = (uint32_t)*reinterpret_cast<unsigned short*>(&h0) |
                         ((uint32_t)*reinterpret_cast<unsigned short*>(&h1) << 16);
                lop[q] = (uint32_t)*reinterpret_cast<unsigned short*>(&l0) |
                         ((uint32_t)*reinterpret_cast<unsigned short*>(&l1) << 16);
            }
            uint32_t sw = sw128((uint32_t)(rloc * 128) + kb);
            *reinterpret_cast<uint2*>(smc + K1_A_OFF + (0*2 + kc) * 16384 + sw) = make_uint2(hip[0], hip[1]);
            *reinterpret_cast<uint2*>(smc + K1_A_OFF + (1*2 + kc) * 16384 + sw) = make_uint2(lop[0], lop[1]);
        }
    }
    __syncthreads();

    const int wm = (warp >> 1) * 32;
    const int wn = (warp & 1) * 32;

    const uint32_t a_row = (lane & 7) + ((lane >> 3) & 1) * 8;
    const uint32_t a_kb  = (lane >> 4) * 16;
    const uint32_t b_row = (lane & 7) + ((lane >> 4) & 1) * 8;
    const uint32_t b_kb  = ((lane >> 3) & 1) * 16;

    const __nv_bfloat16* wtab[3] = { g_Wl_hi, g_Wl_lo, g_Wg_hi };

    #pragma unroll 1
    for (int ct = 0; ct < 4; ct++) {
        const int cbase = ct * 64;

        // ---- load 6 W planes (3 mats x 2 kc) via cp.async ----
        #pragma unroll
        for (int it = 0; it < 12; it++) {
            int u = it * 256 + tid;
            int p = u >> 9; int idx = u & 511;
            int row = idx >> 3, q = idx & 7;
            int shl = p >> 1, kc = p & 1;
            const __nv_bfloat16* src = wtab[shl] + (size_t)(cbase + row) * 128 + kc * 64 + q * 8;
            cp16(sbase + K1_W_OFF + p * 8192 + sw128((uint32_t)(row * 128 + q * 16)), src);
        }
        CP_COMMIT();
        CP_WAIT0();
        __syncthreads();

        float accl[2][4][4], accg[2][4][4];
        #pragma unroll
        for (int mt = 0; mt < 2; mt++)
            #pragma unroll
            for (int nt = 0; nt < 4; nt++)
                #pragma unroll
                for (int q = 0; q < 4; q++) { accl[mt][nt][q] = 0.f; accg[mt][nt][q] = 0.f; }

        #pragma unroll
        for (int kc = 0; kc < 2; kc++) {
            #pragma unroll
            for (int ks = 0; ks < 4; ks++) {
                uint32_t kb = ks * 32;
                uint32_t ah[2][4], al[2][4];
                #pragma unroll
                for (int mt = 0; mt < 2; mt++) {
                    uint32_t sw = sw128((uint32_t)((wm + mt * 16 + a_row) * 128) + kb + a_kb);
                    ldm_x4(ah[mt], sbase + K1_A_OFF + (0*2 + kc) * 16384 + sw);
                    ldm_x4(al[mt], sbase + K1_A_OFF + (1*2 + kc) * 16384 + sw);
                }
                #pragma unroll
                for (int ng = 0; ng < 2; ng++) {
                    uint32_t sw = sw128((uint32_t)((wn + ng * 16 + b_row) * 128) + kb + b_kb);
                    uint32_t wlh[4], wll[4], wgh[4];
                    ldm_x4(wlh, sbase + K1_W_OFF + (0 + kc) * 8192 + sw);
                    ldm_x4(wll, sbase + K1_W_OFF + (2 + kc) * 8192 + sw);
                    ldm_x4(wgh, sbase + K1_W_OFF + (4 + kc) * 8192 + sw);
                    #pragma unroll
                    for (int mt = 0; mt < 2; mt++) {
                        #pragma unroll
                        for (int h = 0; h < 2; h++) {
                            float* cl = accl[mt][ng * 2 + h];
                            float* cg = accg[mt][ng * 2 + h];
                            mma16816(cl, ah[mt], wlh[h*2], wlh[h*2+1]);
                            mma16816(cl, ah[mt], wll[h*2], wll[h*2+1]);
                            mma16816(cl, al[mt], wlh[h*2], wlh[h*2+1]);
                            mma16816(cg, ah[mt], wgh[h*2], wgh[h*2+1]);
                        }
                    }
                }
            }
        }
        __syncthreads();   // all warps done reading W before stage (aliased) writes

        #pragma unroll
        for (int mt = 0; mt < 2; mt++) {
            int rl0 = wm + mt * 16 + (int)(lane >> 2);
            float m0 = mask[r0 + rl0];
            float m1 = mask[r0 + rl0 + 8];
            #pragma unroll
            for (int nt = 0; nt < 4; nt++) {
                int cl0 = wn + nt * 8 + 2 * (int)(lane & 3);
                float lb0 = lrpb[cbase + cl0],  lb1 = lrpb[cbase + cl0 + 1];
                float gb0 = gateb[cbase + cl0], gb1 = gateb[cbase + cl0 + 1];
                float* vl = accl[mt][nt];
                float* vg = accg[mt][nt];
                stage[(cl0    ) * 132 + rl0    ] = pack_split((vl[0] + lb0) * m0 * sigmoidf_(vg[0] + gb0));
                stage[(cl0 + 1) * 132 + rl0    ] = pack_split((vl[1] + lb1) * m0 * sigmoidf_(vg[1] + gb1));
                stage[(cl0    ) * 132 + rl0 + 8] = pack_split((vl[2] + lb0) * m1 * sigmoidf_(vg[2] + gb0));
                stage[(cl0 + 1) * 132 + rl0 + 8] = pack_split((vl[3] + lb1) * m1 * sigmoidf_(vg[3] + gb1));
            }
        }
        __syncthreads();

        {
            int c_loc = tid >> 2;
            int seg = tid & 3;
            int cg = cbase + c_loc;
            __nv_bfloat16* hiP = (cg < 128) ? (g_Lhi + (size_t)cg * NN) : (g_Rhi + (size_t)(cg - 128) * NN);
            __nv_bfloat16* loP = (cg < 128) ? (g_Llo + (size_t)cg * NN) : (g_Rlo + (size_t)(cg - 128) * NN);
            int rb = seg * 32;
            const uint32_t* srow = &stage[c_loc * 132 + rb];
            #pragma unroll
            for (int blk = 0; blk < 4; blk++) {
                uint32_t hw[4], lw[4];
                #pragma unroll
                for (int q = 0; q < 4; q++) {
                    uint32_t p0 = srow[blk * 8 + q * 2];
                    uint32_t p1 = srow[blk * 8 + q * 2 + 1];
                    hw[q] = (p0 & 0xffffu) | (p1 << 16);
                    lw[q] = (p0 >> 16) | (p1 & 0xffff0000u);
                }
                *reinterpret_cast<uint4*>(hiP + r0 + rb + blk * 8) = make_uint4(hw[0], hw[1], hw[2], hw[3]);
                *reinterpret_cast<uint4*>(loP + r0 + rb + blk * 8) = make_uint4(lw[0], lw[1], lw[2], lw[3]);
            }
        }
        __syncthreads();
    }
}

// ---------------------------------------------------------------------------
// Kernel 2: split-bf16 mma.sync GEMM  T_c = L_c @ R_c^T   (3-stage pipeline)
// ---------------------------------------------------------------------------
#define PLANE 16384
#define STAGE (4 * PLANE)
#define K2_SMEM (3 * STAGE)   // 196608

__device__ __forceinline__ void k2_prefetch(uint32_t sbase, int stage_i,
    const __nv_bfloat16* Ah, const __nv_bfloat16* Al,
    const __nv_bfloat16* Bh, const __nv_bfloat16* Bl,
    int i0, int j0, int k0, int tid)
{
    const __nv_bfloat16* srcs[4] = {Ah, Al, Bh, Bl};
    const int bases[4] = {i0, i0, j0, j0};
    uint32_t st = sbase + stage_i * STAGE;
    #pragma unroll
    for (int p = 0; p < 4; p++) {
        const __nv_bfloat16* s = srcs[p];
        int rb = bases[p];
        #pragma unroll
        for (int it = 0; it < 4; it++) {
            int idx = it * 256 + tid;
            int r = idx >> 3, q = idx & 7;
            uint32_t dst = st + p * PLANE + sw128((uint32_t)(r * 128 + q * 16));
            cp16(dst, s + (size_t)(rb + r) * NDIM + k0 + q * 8);
        }
    }
}

__global__ __launch_bounds__(256, 1)
void k2_tri_mma()
{
    extern __shared__ __align__(1024) char smc[];
    const uint32_t sbase = smem_u32(smc);
    const int tid = threadIdx.x;
    const int warp = tid >> 5;
    const uint32_t lane = tid & 31;
    const int c = blockIdx.z;
    const int i0 = blockIdx.x * 128, j0 = blockIdx.y * 128;

    const __nv_bfloat16* __restrict__ Ah = g_Lhi + (size_t)c * NN;
    const __nv_bfloat16* __restrict__ Al = g_Llo + (size_t)c * NN;
    const __nv_bfloat16* __restrict__ Bh = g_Rhi + (size_t)c * NN;
    const __nv_bfloat16* __restrict__ Bl = g_Rlo + (size_t)c * NN;
    float* __restrict__ Tc = g_T + (size_t)c * NN;

    const int wm = (warp >> 1) * 32;
    const int wn = (warp & 1) * 64;

    const uint32_t a_row = (lane & 7) + ((lane >> 3) & 1) * 8;
    const uint32_t a_kb  = (lane >> 4) * 16;
    const uint32_t b_row = (lane & 7) + ((lane >> 4) & 1) * 8;
    const uint32_t b_kb  = ((lane >> 3) & 1) * 16;

    float acc[2][8][4];
    #pragma unroll
    for (int mt = 0; mt < 2; mt++)
        #pragma unroll
        for (int nt = 0; nt < 8; nt++)
            #pragma unroll
            for (int q = 0; q < 4; q++) acc[mt][nt][q] = 0.0f;

    k2_prefetch(sbase, 0, Ah, Al, Bh, Bl, i0, j0, 0, tid);
    CP_COMMIT();
    k2_prefetch(sbase, 1, Ah, Al, Bh, Bl, i0, j0, 64, tid);
    CP_COMMIT();

    #pragma unroll 1
    for (int ch = 0; ch < 8; ch++) {
        if (ch == 7) { CP_WAIT0(); } else { CP_WAIT1(); }
        __syncthreads();
        if (ch + 2 < 8) {
            k2_prefetch(sbase, (ch + 2) % 3, Ah, Al, Bh, Bl, i0, j0, (ch + 2) * 64, tid);
            CP_COMMIT();
        }
        uint32_t st = sbase + (ch % 3) * STAGE;
        uint32_t sAh = st, sAl = st + PLANE, sBh = st + 2 * PLANE, sBl = st + 3 * PLANE;

        #pragma unroll
        for (int ks = 0; ks < 4; ks++) {
            uint32_t kb = ks * 32;
            uint32_t ah[2][4], al[2][4];
            #pragma unroll
            for (int mt = 0; mt < 2; mt++) {
                uint32_t sw = sw128((uint32_t)((wm + mt * 16 + a_row) * 128) + kb + a_kb);
                ldm_x4(ah[mt], sAh + sw);
                ldm_x4(al[mt], sAl + sw);
            }
            #pragma unroll
            for (int ng = 0; ng < 4; ng++) {
                uint32_t sw = sw128((uint32_t)((wn + ng * 16 + b_row) * 128) + kb + b_kb);
                uint32_t bh[4], bl[4];
                ldm_x4(bh, sBh + sw);
                ldm_x4(bl, sBl + sw);
                #pragma unroll
                for (int mt = 0; mt < 2; mt++) {
                    #pragma unroll
                    for (int h = 0; h < 2; h++) {
                        float* cc = acc[mt][ng * 2 + h];
                        mma16816(cc, ah[mt], bh[h * 2], bh[h * 2 + 1]);
                        mma16816(cc, ah[mt], bl[h * 2], bl[h * 2 + 1]);
                        mma16816(cc, al[mt], bh[h * 2], bh[h * 2 + 1]);
                    }
                }
            }
        }
    }

    const int rbase = i0 + wm + (int)(lane >> 2);
    const int cbase = j0 + wn + 2 * (int)(lane & 3);
    #pragma unroll
    for (int mt = 0; mt < 2; mt++) {
        #pragma unroll
        for (int nt = 0; nt < 8; nt++) {
            float* cc = acc[mt][nt];
            int col = cbase + nt * 8;
            int r1 = rbase + mt * 16;
            *reinterpret_cast<float2*>(&Tc[(size_t)r1 * NDIM + col])       = make_float2(cc[0], cc[1]);
            *reinterpret_cast<float2*>(&Tc[(size_t)(r1 + 8) * NDIM + col]) = make_float2(cc[2], cc[3]);
        }
    }
}

// ---------------------------------------------------------------------------
// Kernel 3 (HMMA): 64 rows x 128 cols per CTA, two 64-col W passes, 2 CTAs/SM.
// smem: s_t fp32 [64][132] | A planes 4x8KB | W planes 4x8KB = 99328 B
// ---------------------------------------------------------------------------
#define K3_T_OFF   0
#define K3_A_OFF   33792
#define K3_W_OFF   66560
#define K3_SMEM    99328

__device__ __forceinline__ void k3_loadW(uint32_t sbase, int ch0, int tid) {
    #pragma unroll
    for (int it = 0; it < 8; it++) {
        int u = it * 256 + tid;
        int p = u >> 9; int idx = u & 511;
        int row = idx >> 3, q = idx & 7;
        int pl = p >> 1, kc = p & 1;
        const __nv_bfloat16* src = (pl == 0 ? g_Wo_bf : g_Wp_bf) + (size_t)(ch0 + row) * 128 + kc * 64 + q * 8;
        cp16(sbase + K3_W_OFF + p * 8192 + sw128((uint32_t)(row * 128 + q * 16)), src);
    }
    CP_COMMIT();
}

__global__ __launch_bounds__(256, 2)
void k3_mma(const float* __restrict__ ogb, const float* __restrict__ ln2w,
            const float* __restrict__ ln2b, const float* __restrict__ outb,
            float* __restrict__ out)
{
    extern __shared__ __align__(1024) char smc[];
    const uint32_t sbase = smem_u32(smc);
    float* s_t = reinterpret_cast<float*>(smc + K3_T_OFF);   // [64][132]

    const int tid = threadIdx.x;
    const int warp = tid >> 5;
    const uint32_t lane = tid & 31;
    const int r0 = blockIdx.x * 64;

    // ---- W half 0 via cp.async (overlaps gather) ----
    k3_loadW(sbase, 0, tid);

    // ---- gather g_T [c][r] -> s_t [r][132] fp32 (64 rows), MLP-unrolled ----
    #pragma unroll
    for (int it = 0; it < 8; it++) {
        int u = it * 256 + tid;
        int cch = u >> 4;
        int q = u & 15;
        float4 v = *reinterpret_cast<const float4*>(g_T + (size_t)cch * NN + r0 + q * 4);
        s_t[(q * 4 + 0) * 132 + cch] = v.x;
        s_t[(q * 4 + 1) * 132 + cch] = v.y;
        s_t[(q * 4 + 2) * 132 + cch] = v.z;
        s_t[(q * 4 + 3) * 132 + cch] = v.w;
    }
    __syncthreads();

    // ---- LN2 per row (8 rows/warp); emit bf16 A planes ----
    {
        const int c4 = lane * 4;
        const int kc = lane >> 4;
        const uint32_t kb = (lane & 15) * 8;
        float4 w4 = *reinterpret_cast<const float4*>(ln2w + c4);
        float4 b4 = *reinterpret_cast<const float4*>(ln2b + c4);
        #pragma unroll 1
        for (int rr = 0; rr < 8; rr++) {
            int rloc = warp * 8 + rr;
            float4 v = *reinterpret_cast<float4*>(&s_t[rloc * 132 + c4]);
            float s  = v.x + v.y + v.z + v.w;
            float s2 = v.x * v.x + v.y * v.y + v.z * v.z + v.w * v.w;
            #pragma unroll
            for (int o = 16; o; o >>= 1) {
                s  += __shfl_xor_sync(0xffffffffu, s, o);
                s2 += __shfl_xor_sync(0xffffffffu, s2, o);
            }
            float m = s * 0.0078125f;
            float var = fmaf(-m, m, s2 * 0.0078125f);
            float rstd = rsqrtf(var + 1e-5f);
            float zn[4] = {
                (v.x - m) * rstd * w4.x + b4.x,
                (v.y - m) * rstd * w4.y + b4.y,
                (v.z - m) * rstd * w4.z + b4.z,
                (v.w - m) * rstd * w4.w + b4.w };
            uint32_t sw = sw128((uint32_t)(rloc * 128) + kb);
            *reinterpret_cast<uint2*>(smc + K3_A_OFF + (0*2 + kc) * 8192 + sw) =
                make_uint2(pack_bf2(v.x, v.y), pack_bf2(v.z, v.w));
            *reinterpret_cast<uint2*>(smc + K3_A_OFF + (1*2 + kc) * 8192 + sw) =
                make_uint2(pack_bf2(zn[0], zn[1]), pack_bf2(zn[2], zn[3]));
        }
    }

    const int wm = (warp >> 1) * 16;
    const int wn = (warp & 1) * 32;

    const uint32_t a_row = (lane & 7) + ((lane >> 3) & 1) * 8;
    const uint32_t a_kb  = (lane >> 4) * 16;
    const uint32_t b_row = (lane & 7) + ((lane >> 4) & 1) * 8;
    const uint32_t b_kb  = ((lane >> 3) & 1) * 16;

    #pragma unroll 1
    for (int hh = 0; hh < 2; hh++) {
        const int ch0 = hh * 64;
        CP_WAIT0();
        __syncthreads();

        float accg[4][4], accz[4][4];
        #pragma unroll
        for (int nt = 0; nt < 4; nt++)
            #pragma unroll
            for (int q = 0; q < 4; q++) { accg[nt][q] = 0.f; accz[nt][q] = 0.f; }

        #pragma unroll
        for (int kc = 0; kc < 2; kc++) {
            #pragma unroll
            for (int ks = 0; ks < 4; ks++) {
                uint32_t kb = ks * 32;
                uint32_t ag[4], az[4];
                uint32_t swa = sw128((uint32_t)((wm + a_row) * 128) + kb + a_kb);
                ldm_x4(ag, sbase + K3_A_OFF + (0*2 + kc) * 8192 + swa);
                ldm_x4(az, sbase + K3_A_OFF + (1*2 + kc) * 8192 + swa);
                #pragma unroll
                for (int ng = 0; ng < 2; ng++) {
                    uint32_t swb = sw128((uint32_t)((wn + ng * 16 + b_row) * 128) + kb + b_kb);
                    uint32_t wo[4], wp[4];
                    ldm_x4(wo, sbase + K3_W_OFF + (0*2 + kc) * 8192 + swb);
                    ldm_x4(wp, sbase + K3_W_OFF + (1*2 + kc) * 8192 + swb);
                    #pragma unroll
                    for (int h = 0; h < 2; h++) {
                        mma16816(accg[ng * 2 + h], ag, wo[h*2], wo[h*2+1]);
                        mma16816(accz[ng * 2 + h], az, wp[h*2], wp[h*2+1]);
                    }
                }
            }
        }
        __syncthreads();   // all warps done with W(hh) before reload
        if (hh == 0) k3_loadW(sbase, 64, tid);   // overlap with epilogue

        // ---- epilogue: out = tri + sigmoid(accg+ogb)*(accz+outb) ----
        {
            int rl0 = wm + (int)(lane >> 2);
            #pragma unroll
            for (int nt = 0; nt < 4; nt++) {
                int dl = wn + nt * 8 + 2 * (int)(lane & 3);
                int d = ch0 + dl;
                float ob0 = ogb[d],  ob1 = ogb[d + 1];
                float ub0 = outb[d], ub1 = outb[d + 1];
                float* cg = accg[nt];
                float* cz = accz[nt];
                float2 t0 = *reinterpret_cast<float2*>(&s_t[rl0 * 132 + d]);
                float2 t1 = *reinterpret_cast<float2*>(&s_t[(rl0 + 8) * 132 + d]);
                float2 o0, o1;
                o0.x = t0.x + sigmoidf_(cg[0] + ob0) * (cz[0] + ub0);
                o0.y = t0.y + sigmoidf_(cg[1] + ob1) * (cz[1] + ub1);
                o1.x = t1.x + sigmoidf_(cg[2] + ob0) * (cz[2] + ub0);
                o1.y = t1.y + sigmoidf_(cg[3] + ob1) * (cz[3] + ub1);
                *reinterpret_cast<float2*>(&out[(size_t)(r0 + rl0) * DDIM + d])     = o0;
                *reinterpret_cast<float2*>(&out[(size_t)(r0 + rl0 + 8) * DDIM + d]) = o1;
            }
        }
    }
}

// ---------------------------------------------------------------------------
extern "C" void kernel_launch(void* const* d_in, const int* in_sizes, int n_in,
                              void* d_out, int out_size)
{
    const float* Z     = (const float*)d_in[0];
    const float* mask  = (const float*)d_in[1];
    const float* ln1w  = (const float*)d_in[2];
    const float* ln1b  = (const float*)d_in[3];
    const float* lrpw  = (const float*)d_in[4];
    const float* lrpb  = (const float*)d_in[5];
    const float* gatew = (const float*)d_in[6];
    const float* gateb = (const float*)d_in[7];
    const float* ogw   = (const float*)d_in[8];
    const float* ogb   = (const float*)d_in[9];
    const float* ln2w  = (const float*)d_in[10];
    const float* ln2b  = (const float*)d_in[11];
    const float* opw   = (const float*)d_in[12];
    const float* outb  = (const float*)d_in[13];
    float* out = (float*)d_out;

    cudaFuncSetAttribute(k1_mma,     cudaFuncAttributeMaxDynamicSharedMemorySize, K1_SMEM);
    cudaFuncSetAttribute(k2_tri_mma, cudaFuncAttributeMaxDynamicSharedMemorySize, K2_SMEM);
    cudaFuncSetAttribute(k3_mma,     cudaFuncAttributeMaxDynamicSharedMemorySize, K3_SMEM);

    k0_wprep<<<128, 256>>>(lrpw, gatew, ogw, opw);

    k1_mma<<<NN / 128, 256, K1_SMEM>>>(Z, mask, ln1w, ln1b, lrpb, gateb);

    dim3 g2(4, 4, 128);
    k2_tri_mma<<<g2, 256, K2_SMEM>>>();

    k3_mma<<<NN / 64, 256, K3_SMEM>>>(ogb, ln2w, ln2b, outb, out);
}

// round 9
// speedup vs baseline: 4.7102x; 1.0654x over previous
#include <cuda_runtime.h>
#include <cuda_bf16.h>
#include <cstdint>

#define NDIM 512
#define DDIM 128
#define NN (NDIM*NDIM)

// Scratch (allocation-free rule: __device__ globals)
__device__ __nv_bfloat16 g_Lhi[(size_t)DDIM * NN];   // [c][i][k]
__device__ __nv_bfloat16 g_Llo[(size_t)DDIM * NN];
__device__ __nv_bfloat16 g_Rhi[(size_t)DDIM * NN];   // [c][j][k]
__device__ __nv_bfloat16 g_Rlo[(size_t)DDIM * NN];
__device__ float g_T[(size_t)DDIM * NN];             // [c][i][j]
// split-bf16 weights for stage-1 (prepped by k0)
__device__ __nv_bfloat16 g_Wl_hi[256 * 128];
__device__ __nv_bfloat16 g_Wl_lo[256 * 128];
__device__ __nv_bfloat16 g_Wg_hi[256 * 128];
// bf16 weights for stage-2 (og / op)
__device__ __nv_bfloat16 g_Wo_bf[128 * 128];
__device__ __nv_bfloat16 g_Wp_bf[128 * 128];

__device__ __forceinline__ float sigmoidf_(float x) {
    return 1.0f / (1.0f + __expf(-x));
}

__device__ __forceinline__ uint32_t smem_u32(const void* p) {
    uint32_t a;
    asm("{ .reg .u64 t; cvta.to.shared.u64 t, %1; cvt.u32.u64 %0, t; }" : "=r"(a) : "l"(p));
    return a;
}

__device__ __forceinline__ uint32_t sw128(uint32_t bo) {
    return bo ^ ((bo >> 3) & 0x70);
}

__device__ __forceinline__ void cp16(uint32_t dst, const void* src) {
    asm volatile("cp.async.cg.shared.global [%0], [%1], 16;" :: "r"(dst), "l"(src) : "memory");
}
#define CP_COMMIT() asm volatile("cp.async.commit_group;" ::: "memory")
#define CP_WAIT0()  asm volatile("cp.async.wait_group 0;" ::: "memory")
#define CP_WAIT1()  asm volatile("cp.async.wait_group 1;" ::: "memory")

__device__ __forceinline__ void ldm_x4(uint32_t r[4], uint32_t addr) {
    asm volatile("ldmatrix.sync.aligned.m8n8.x4.shared.b16 {%0,%1,%2,%3}, [%4];"
        : "=r"(r[0]), "=r"(r[1]), "=r"(r[2]), "=r"(r[3]) : "r"(addr));
}

__device__ __forceinline__ void mma16816(float c[4], const uint32_t a[4],
                                         uint32_t b0, uint32_t b1) {
    asm volatile("mma.sync.aligned.m16n8k16.row.col.f32.bf16.bf16.f32 "
        "{%0,%1,%2,%3}, {%4,%5,%6,%7}, {%8,%9}, {%0,%1,%2,%3};"
        : "+f"(c[0]), "+f"(c[1]), "+f"(c[2]), "+f"(c[3])
        : "r"(a[0]), "r"(a[1]), "r"(a[2]), "r"(a[3]), "r"(b0), "r"(b1));
}

__device__ __forceinline__ uint32_t pack_split(float v) {
    __nv_bfloat16 hi = __float2bfloat16(v);
    __nv_bfloat16 lo = __float2bfloat16(v - __bfloat162float(hi));
    uint32_t h = *reinterpret_cast<unsigned short*>(&hi);
    uint32_t l = *reinterpret_cast<unsigned short*>(&lo);
    return h | (l << 16);
}

__device__ __forceinline__ uint32_t pack_bf2(float a, float b) {
    __nv_bfloat16 h0 = __float2bfloat16(a);
    __nv_bfloat16 h1 = __float2bfloat16(b);
    return (uint32_t)*reinterpret_cast<unsigned short*>(&h0) |
           ((uint32_t)*reinterpret_cast<unsigned short*>(&h1) << 16);
}

// ---------------------------------------------------------------------------
// Kernel 0: weight prep (split lrp, bf16 gate/og/op)
// ---------------------------------------------------------------------------
__global__ void k0_wprep(const float* __restrict__ lrpw, const float* __restrict__ gatew,
                         const float* __restrict__ ogw,  const float* __restrict__ opw)
{
    int i = blockIdx.x * blockDim.x + threadIdx.x;
    if (i < 256 * 128) {
        float v = lrpw[i];
        __nv_bfloat16 h = __float2bfloat16(v);
        g_Wl_hi[i] = h;
        g_Wl_lo[i] = __float2bfloat16(v - __bfloat162float(h));
        g_Wg_hi[i] = __float2bfloat16(gatew[i]);
    }
    if (i < 128 * 128) {
        g_Wo_bf[i] = __float2bfloat16(ogw[i]);
        g_Wp_bf[i] = __float2bfloat16(opw[i]);
    }
}

// ---------------------------------------------------------------------------
// Kernel 1 (HMMA): LN1 + lrp (3-prod) / gate (1-prod) + gating -> split L/R
// smem: A planes 64KB | W planes 48KB (stage buffer ALIASES W region)
// 112KB -> 2 CTAs/SM
// ---------------------------------------------------------------------------
#define K1_A_OFF   0
#define K1_W_OFF   65536
#define K1_SMEM    114688

__global__ __launch_bounds__(256, 2)
void k1_mma(const float* __restrict__ Z, const float* __restrict__ mask,
            const float* __restrict__ ln1w, const float* __restrict__ ln1b,
            const float* __restrict__ lrpb, const float* __restrict__ gateb)
{
    extern __shared__ __align__(1024) char smc[];
    const uint32_t sbase = smem_u32(smc);
    uint32_t* stage = reinterpret_cast<uint32_t*>(smc + K1_W_OFF);   // aliases W planes

    const int tid = threadIdx.x;
    const int warp = tid >> 5;
    const uint32_t lane = tid & 31;
    const int r0 = blockIdx.x * 128;

    // ---- Phase A: load Z rows, LN1, split-bf16 into swizzled A planes ----
    {
        const int k4 = lane * 4;
        const int kc = lane >> 4;
        const uint32_t kb = (lane & 15) * 8;
        float4 w4 = *reinterpret_cast<const float4*>(ln1w + k4);
        float4 b4 = *reinterpret_cast<const float4*>(ln1b + k4);
        #pragma unroll 2
        for (int rr = 0; rr < 16; rr++) {
            int rloc = warp * 16 + rr;
            float4 v = *reinterpret_cast<const float4*>(Z + (size_t)(r0 + rloc) * DDIM + k4);
            float s  = v.x + v.y + v.z + v.w;
            float s2 = v.x * v.x + v.y * v.y + v.z * v.z + v.w * v.w;
            #pragma unroll
            for (int o = 16; o; o >>= 1) {
                s  += __shfl_xor_sync(0xffffffffu, s, o);
                s2 += __shfl_xor_sync(0xffffffffu, s2, o);
            }
            float m = s * 0.0078125f;
            float var = fmaf(-m, m, s2 * 0.0078125f);
            float rstd = rsqrtf(var + 1e-5f);
            float zn[4] = {
                (v.x - m) * rstd * w4.x + b4.x,
                (v.y - m) * rstd * w4.y + b4.y,
                (v.z - m) * rstd * w4.z + b4.z,
                (v.w - m) * rstd * w4.w + b4.w };
            uint32_t hip[2], lop[2];
            #pragma unroll
            for (int q = 0; q < 2; q++) {
                __nv_bfloat16 h0 = __float2bfloat16(zn[q*2]);
                __nv_bfloat16 h1 = __float2bfloat16(zn[q*2+1]);
                __nv_bfloat16 l0 = __float2bfloat16(zn[q*2]   - __bfloat162float(h0));
                __nv_bfloat16 l1 = __float2bfloat16(zn[q*2+1] - __bfloat162float(h1));
                hip[q] = (uint32_t)*reinterpret_cast<unsigned short*>(&h0) |
                         ((uint32_t)*reinterpret_cast<unsigned short*>(&h1) << 16);
                lop[q] = (uint32_t)*reinterpret_cast<unsigned short*>(&l0) |
                         ((uint32_t)*reinterpret_cast<unsigned short*>(&l1) << 16);
            }
            uint32_t sw = sw128((uint32_t)(rloc * 128) + kb);
            *reinterpret_cast<uint2*>(smc + K1_A_OFF + (0*2 + kc) * 16384 + sw) = make_uint2(hip[0], hip[1]);
            *reinterpret_cast<uint2*>(smc + K1_A_OFF + (1*2 + kc) * 16384 + sw) = make_uint2(lop[0], lop[1]);
        }
    }
    __syncthreads();

    const int wm = (warp >> 1) * 32;
    const int wn = (warp & 1) * 32;

    const uint32_t a_row = (lane & 7) + ((lane >> 3) & 1) * 8;
    const uint32_t a_kb  = (lane >> 4) * 16;
    const uint32_t b_row = (lane & 7) + ((lane >> 4) & 1) * 8;
    const uint32_t b_kb  = ((lane >> 3) & 1) * 16;

    const __nv_bfloat16* wtab[3] = { g_Wl_hi, g_Wl_lo, g_Wg_hi };

    #pragma unroll 1
    for (int ct = 0; ct < 4; ct++) {
        const int cbase = ct * 64;

        // ---- load 6 W planes (3 mats x 2 kc) via cp.async ----
        #pragma unroll
        for (int it = 0; it < 12; it++) {
            int u = it * 256 + tid;
            int p = u >> 9; int idx = u & 511;
            int row = idx >> 3, q = idx & 7;
            int shl = p >> 1, kc = p & 1;
            const __nv_bfloat16* src = wtab[shl] + (size_t)(cbase + row) * 128 + kc * 64 + q * 8;
            cp16(sbase + K1_W_OFF + p * 8192 + sw128((uint32_t)(row * 128 + q * 16)), src);
        }
        CP_COMMIT();
        CP_WAIT0();
        __syncthreads();

        float accl[2][4][4], accg[2][4][4];
        #pragma unroll
        for (int mt = 0; mt < 2; mt++)
            #pragma unroll
            for (int nt = 0; nt < 4; nt++)
                #pragma unroll
                for (int q = 0; q < 4; q++) { accl[mt][nt][q] = 0.f; accg[mt][nt][q] = 0.f; }

        #pragma unroll
        for (int kc = 0; kc < 2; kc++) {
            #pragma unroll
            for (int ks = 0; ks < 4; ks++) {
                uint32_t kb = ks * 32;
                uint32_t ah[2][4], al[2][4];
                #pragma unroll
                for (int mt = 0; mt < 2; mt++) {
                    uint32_t sw = sw128((uint32_t)((wm + mt * 16 + a_row) * 128) + kb + a_kb);
                    ldm_x4(ah[mt], sbase + K1_A_OFF + (0*2 + kc) * 16384 + sw);
                    ldm_x4(al[mt], sbase + K1_A_OFF + (1*2 + kc) * 16384 + sw);
                }
                #pragma unroll
                for (int ng = 0; ng < 2; ng++) {
                    uint32_t sw = sw128((uint32_t)((wn + ng * 16 + b_row) * 128) + kb + b_kb);
                    uint32_t wlh[4], wll[4], wgh[4];
                    ldm_x4(wlh, sbase + K1_W_OFF + (0 + kc) * 8192 + sw);
                    ldm_x4(wll, sbase + K1_W_OFF + (2 + kc) * 8192 + sw);
                    ldm_x4(wgh, sbase + K1_W_OFF + (4 + kc) * 8192 + sw);
                    #pragma unroll
                    for (int mt = 0; mt < 2; mt++) {
                        #pragma unroll
                        for (int h = 0; h < 2; h++) {
                            float* cl = accl[mt][ng * 2 + h];
                            float* cg = accg[mt][ng * 2 + h];
                            mma16816(cl, ah[mt], wlh[h*2], wlh[h*2+1]);
                            mma16816(cl, ah[mt], wll[h*2], wll[h*2+1]);
                            mma16816(cl, al[mt], wlh[h*2], wlh[h*2+1]);
                            mma16816(cg, ah[mt], wgh[h*2], wgh[h*2+1]);
                        }
                    }
                }
            }
        }
        __syncthreads();   // all warps done reading W before stage (aliased) writes

        #pragma unroll
        for (int mt = 0; mt < 2; mt++) {
            int rl0 = wm + mt * 16 + (int)(lane >> 2);
            float m0 = mask[r0 + rl0];
            float m1 = mask[r0 + rl0 + 8];
            #pragma unroll
            for (int nt = 0; nt < 4; nt++) {
                int cl0 = wn + nt * 8 + 2 * (int)(lane & 3);
                float lb0 = lrpb[cbase + cl0],  lb1 = lrpb[cbase + cl0 + 1];
                float gb0 = gateb[cbase + cl0], gb1 = gateb[cbase + cl0 + 1];
                float* vl = accl[mt][nt];
                float* vg = accg[mt][nt];
                stage[(cl0    ) * 132 + rl0    ] = pack_split((vl[0] + lb0) * m0 * sigmoidf_(vg[0] + gb0));
                stage[(cl0 + 1) * 132 + rl0    ] = pack_split((vl[1] + lb1) * m0 * sigmoidf_(vg[1] + gb1));
                stage[(cl0    ) * 132 + rl0 + 8] = pack_split((vl[2] + lb0) * m1 * sigmoidf_(vg[2] + gb0));
                stage[(cl0 + 1) * 132 + rl0 + 8] = pack_split((vl[3] + lb1) * m1 * sigmoidf_(vg[3] + gb1));
            }
        }
        __syncthreads();

        {
            int c_loc = tid >> 2;
            int seg = tid & 3;
            int cg = cbase + c_loc;
            __nv_bfloat16* hiP = (cg < 128) ? (g_Lhi + (size_t)cg * NN) : (g_Rhi + (size_t)(cg - 128) * NN);
            __nv_bfloat16* loP = (cg < 128) ? (g_Llo + (size_t)cg * NN) : (g_Rlo + (size_t)(cg - 128) * NN);
            int rb = seg * 32;
            const uint32_t* srow = &stage[c_loc * 132 + rb];
            #pragma unroll
            for (int blk = 0; blk < 4; blk++) {
                uint32_t hw[4], lw[4];
                #pragma unroll
                for (int q = 0; q < 4; q++) {
                    uint32_t p0 = srow[blk * 8 + q * 2];
                    uint32_t p1 = srow[blk * 8 + q * 2 + 1];
                    hw[q] = (p0 & 0xffffu) | (p1 << 16);
                    lw[q] = (p0 >> 16) | (p1 & 0xffff0000u);
                }
                *reinterpret_cast<uint4*>(hiP + r0 + rb + blk * 8) = make_uint4(hw[0], hw[1], hw[2], hw[3]);
                *reinterpret_cast<uint4*>(loP + r0 + rb + blk * 8) = make_uint4(lw[0], lw[1], lw[2], lw[3]);
            }
        }
        __syncthreads();
    }
}

// ---------------------------------------------------------------------------
// Kernel 2: split-bf16 mma.sync GEMM  T_c = L_c @ R_c^T
// CTA tile 128(i) x 64(j), K-chunk 64, 2-stage, 2 CTAs/SM.
// smem/stage: Ah 16K | Al 16K | Bh 8K | Bl 8K = 48KB; x2 = 96KB
// ---------------------------------------------------------------------------
#define K2_AP 16384
#define K2_BP 8192
#define K2_STG (2 * K2_AP + 2 * K2_BP)   // 49152
#define K2_SMEM (2 * K2_STG)             // 98304

__device__ __forceinline__ void k2_prefetch(uint32_t sbase, int stage_i,
    const __nv_bfloat16* Ah, const __nv_bfloat16* Al,
    const __nv_bfloat16* Bh, const __nv_bfloat16* Bl,
    int i0, int j0, int k0, int tid)
{
    uint32_t st = sbase + stage_i * K2_STG;
    // A planes: 128 rows x 128B each
    #pragma unroll
    for (int it = 0; it < 4; it++) {
        int idx = it * 256 + tid;
        int r = idx >> 3, q = idx & 7;
        uint32_t sw = sw128((uint32_t)(r * 128 + q * 16));
        cp16(st + sw,          Ah + (size_t)(i0 + r) * NDIM + k0 + q * 8);
        cp16(st + K2_AP + sw,  Al + (size_t)(i0 + r) * NDIM + k0 + q * 8);
    }
    // B planes: 64 rows x 128B each
    #pragma unroll
    for (int it = 0; it < 2; it++) {
        int idx = it * 256 + tid;
        int r = idx >> 3, q = idx & 7;
        uint32_t sw = sw128((uint32_t)(r * 128 + q * 16));
        cp16(st + 2 * K2_AP + sw,          Bh + (size_t)(j0 + r) * NDIM + k0 + q * 8);
        cp16(st + 2 * K2_AP + K2_BP + sw,  Bl + (size_t)(j0 + r) * NDIM + k0 + q * 8);
    }
    CP_COMMIT();
}

__global__ __launch_bounds__(256, 2)
void k2_tri_mma()
{
    extern __shared__ __align__(1024) char smc[];
    const uint32_t sbase = smem_u32(smc);
    const int tid = threadIdx.x;
    const int warp = tid >> 5;
    const uint32_t lane = tid & 31;
    const int c = blockIdx.z;
    const int i0 = blockIdx.x * 128, j0 = blockIdx.y * 64;

    const __nv_bfloat16* __restrict__ Ah = g_Lhi + (size_t)c * NN;
    const __nv_bfloat16* __restrict__ Al = g_Llo + (size_t)c * NN;
    const __nv_bfloat16* __restrict__ Bh = g_Rhi + (size_t)c * NN;
    const __nv_bfloat16* __restrict__ Bl = g_Rlo + (size_t)c * NN;
    float* __restrict__ Tc = g_T + (size_t)c * NN;

    const int wm = (warp >> 1) * 32;    // 0..96
    const int wn = (warp & 1) * 32;     // 0/32

    const uint32_t a_row = (lane & 7) + ((lane >> 3) & 1) * 8;
    const uint32_t a_kb  = (lane >> 4) * 16;
    const uint32_t b_row = (lane & 7) + ((lane >> 4) & 1) * 8;
    const uint32_t b_kb  = ((lane >> 3) & 1) * 16;

    float acc[2][4][4];
    #pragma unroll
    for (int mt = 0; mt < 2; mt++)
        #pragma unroll
        for (int nt = 0; nt < 4; nt++)
            #pragma unroll
            for (int q = 0; q < 4; q++) acc[mt][nt][q] = 0.0f;

    k2_prefetch(sbase, 0, Ah, Al, Bh, Bl, i0, j0, 0, tid);

    #pragma unroll 1
    for (int ch = 0; ch < 8; ch++) {
        if (ch + 1 < 8) {
            k2_prefetch(sbase, (ch + 1) & 1, Ah, Al, Bh, Bl, i0, j0, (ch + 1) * 64, tid);
            CP_WAIT1();
        } else {
            CP_WAIT0();
        }
        __syncthreads();

        uint32_t st = sbase + (ch & 1) * K2_STG;
        uint32_t sAh = st, sAl = st + K2_AP, sBh = st + 2 * K2_AP, sBl = st + 2 * K2_AP + K2_BP;

        #pragma unroll
        for (int ks = 0; ks < 4; ks++) {
            uint32_t kb = ks * 32;
            uint32_t ah[2][4], al[2][4];
            #pragma unroll
            for (int mt = 0; mt < 2; mt++) {
                uint32_t sw = sw128((uint32_t)((wm + mt * 16 + a_row) * 128) + kb + a_kb);
                ldm_x4(ah[mt], sAh + sw);
                ldm_x4(al[mt], sAl + sw);
            }
            #pragma unroll
            for (int ng = 0; ng < 2; ng++) {
                uint32_t sw = sw128((uint32_t)((wn + ng * 16 + b_row) * 128) + kb + b_kb);
                uint32_t bh[4], bl[4];
                ldm_x4(bh, sBh + sw);
                ldm_x4(bl, sBl + sw);
                #pragma unroll
                for (int mt = 0; mt < 2; mt++) {
                    #pragma unroll
                    for (int h = 0; h < 2; h++) {
                        float* cc = acc[mt][ng * 2 + h];
                        mma16816(cc, ah[mt], bh[h * 2], bh[h * 2 + 1]);
                        mma16816(cc, ah[mt], bl[h * 2], bl[h * 2 + 1]);
                        mma16816(cc, al[mt], bh[h * 2], bh[h * 2 + 1]);
                    }
                }
            }
        }
        __syncthreads();
    }

    const int rbase = i0 + wm + (int)(lane >> 2);
    const int cbase = j0 + wn + 2 * (int)(lane & 3);
    #pragma unroll
    for (int mt = 0; mt < 2; mt++) {
        #pragma unroll
        for (int nt = 0; nt < 4; nt++) {
            float* cc = acc[mt][nt];
            int col = cbase + nt * 8;
            int r1 = rbase + mt * 16;
            *reinterpret_cast<float2*>(&Tc[(size_t)r1 * NDIM + col])       = make_float2(cc[0], cc[1]);
            *reinterpret_cast<float2*>(&Tc[(size_t)(r1 + 8) * NDIM + col]) = make_float2(cc[2], cc[3]);
        }
    }
}

// ---------------------------------------------------------------------------
// Kernel 3 (HMMA): 64 rows x 128 cols per CTA, two 64-col W passes, 2 CTAs/SM.
// smem: s_t fp32 [64][132] | A planes 4x8KB | W planes 4x8KB = 99328 B
// ---------------------------------------------------------------------------
#define K3_T_OFF   0
#define K3_A_OFF   33792
#define K3_W_OFF   66560
#define K3_SMEM    99328

__device__ __forceinline__ void k3_loadW(uint32_t sbase, int ch0, int tid) {
    #pragma unroll
    for (int it = 0; it < 8; it++) {
        int u = it * 256 + tid;
        int p = u >> 9; int idx = u & 511;
        int row = idx >> 3, q = idx & 7;
        int pl = p >> 1, kc = p & 1;
        const __nv_bfloat16* src = (pl == 0 ? g_Wo_bf : g_Wp_bf) + (size_t)(ch0 + row) * 128 + kc * 64 + q * 8;
        cp16(sbase + K3_W_OFF + p * 8192 + sw128((uint32_t)(row * 128 + q * 16)), src);
    }
    CP_COMMIT();
}

__global__ __launch_bounds__(256, 2)
void k3_mma(const float* __restrict__ ogb, const float* __restrict__ ln2w,
            const float* __restrict__ ln2b, const float* __restrict__ outb,
            float* __restrict__ out)
{
    extern __shared__ __align__(1024) char smc[];
    const uint32_t sbase = smem_u32(smc);
    float* s_t = reinterpret_cast<float*>(smc + K3_T_OFF);   // [64][132]

    const int tid = threadIdx.x;
    const int warp = tid >> 5;
    const uint32_t lane = tid & 31;
    const int r0 = blockIdx.x * 64;

    // ---- W half 0 via cp.async (overlaps gather) ----
    k3_loadW(sbase, 0, tid);

    // ---- gather g_T [c][r] -> s_t [r][132] fp32 (64 rows), MLP-unrolled ----
    #pragma unroll
    for (int it = 0; it < 8; it++) {
        int u = it * 256 + tid;
        int cch = u >> 4;
        int q = u & 15;
        float4 v = *reinterpret_cast<const float4*>(g_T + (size_t)cch * NN + r0 + q * 4);
        s_t[(q * 4 + 0) * 132 + cch] = v.x;
        s_t[(q * 4 + 1) * 132 + cch] = v.y;
        s_t[(q * 4 + 2) * 132 + cch] = v.z;
        s_t[(q * 4 + 3) * 132 + cch] = v.w;
    }
    __syncthreads();

    // ---- LN2 per row (8 rows/warp); emit bf16 A planes ----
    {
        const int c4 = lane * 4;
        const int kc = lane >> 4;
        const uint32_t kb = (lane & 15) * 8;
        float4 w4 = *reinterpret_cast<const float4*>(ln2w + c4);
        float4 b4 = *reinterpret_cast<const float4*>(ln2b + c4);
        #pragma unroll 1
        for (int rr = 0; rr < 8; rr++) {
            int rloc = warp * 8 + rr;
            float4 v = *reinterpret_cast<float4*>(&s_t[rloc * 132 + c4]);
            float s  = v.x + v.y + v.z + v.w;
            float s2 = v.x * v.x + v.y * v.y + v.z * v.z + v.w * v.w;
            #pragma unroll
            for (int o = 16; o; o >>= 1) {
                s  += __shfl_xor_sync(0xffffffffu, s, o);
                s2 += __shfl_xor_sync(0xffffffffu, s2, o);
            }
            float m = s * 0.0078125f;
            float var = fmaf(-m, m, s2 * 0.0078125f);
            float rstd = rsqrtf(var + 1e-5f);
            float zn[4] = {
                (v.x - m) * rstd * w4.x + b4.x,
                (v.y - m) * rstd * w4.y + b4.y,
                (v.z - m) * rstd * w4.z + b4.z,
                (v.w - m) * rstd * w4.w + b4.w };
            uint32_t sw = sw128((uint32_t)(rloc * 128) + kb);
            *reinterpret_cast<uint2*>(smc + K3_A_OFF + (0*2 + kc) * 8192 + sw) =
                make_uint2(pack_bf2(v.x, v.y), pack_bf2(v.z, v.w));
            *reinterpret_cast<uint2*>(smc + K3_A_OFF + (1*2 + kc) * 8192 + sw) =
                make_uint2(pack_bf2(zn[0], zn[1]), pack_bf2(zn[2], zn[3]));
        }
    }

    const int wm = (warp >> 1) * 16;
    const int wn = (warp & 1) * 32;

    const uint32_t a_row = (lane & 7) + ((lane >> 3) & 1) * 8;
    const uint32_t a_kb  = (lane >> 4) * 16;
    const uint32_t b_row = (lane & 7) + ((lane >> 4) & 1) * 8;
    const uint32_t b_kb  = ((lane >> 3) & 1) * 16;

    #pragma unroll 1
    for (int hh = 0; hh < 2; hh++) {
        const int ch0 = hh * 64;
        CP_WAIT0();
        __syncthreads();

        float accg[4][4], accz[4][4];
        #pragma unroll
        for (int nt = 0; nt < 4; nt++)
            #pragma unroll
            for (int q = 0; q < 4; q++) { accg[nt][q] = 0.f; accz[nt][q] = 0.f; }

        #pragma unroll
        for (int kc = 0; kc < 2; kc++) {
            #pragma unroll
            for (int ks = 0; ks < 4; ks++) {
                uint32_t kb = ks * 32;
                uint32_t ag[4], az[4];
                uint32_t swa = sw128((uint32_t)((wm + a_row) * 128) + kb + a_kb);
                ldm_x4(ag, sbase + K3_A_OFF + (0*2 + kc) * 8192 + swa);
                ldm_x4(az, sbase + K3_A_OFF + (1*2 + kc) * 8192 + swa);
                #pragma unroll
                for (int ng = 0; ng < 2; ng++) {
                    uint32_t swb = sw128((uint32_t)((wn + ng * 16 + b_row) * 128) + kb + b_kb);
                    uint32_t wo[4], wp[4];
                    ldm_x4(wo, sbase + K3_W_OFF + (0*2 + kc) * 8192 + swb);
                    ldm_x4(wp, sbase + K3_W_OFF + (1*2 + kc) * 8192 + swb);
                    #pragma unroll
                    for (int h = 0; h < 2; h++) {
                        mma16816(accg[ng * 2 + h], ag, wo[h*2], wo[h*2+1]);
                        mma16816(accz[ng * 2 + h], az, wp[h*2], wp[h*2+1]);
                    }
                }
            }
        }
        __syncthreads();   // all warps done with W(hh) before reload
        if (hh == 0) k3_loadW(sbase, 64, tid);   // overlap with epilogue

        // ---- epilogue: out = tri + sigmoid(accg+ogb)*(accz+outb) ----
        {
            int rl0 = wm + (int)(lane >> 2);
            #pragma unroll
            for (int nt = 0; nt < 4; nt++) {
                int dl = wn + nt * 8 + 2 * (int)(lane & 3);
                int d = ch0 + dl;
                float ob0 = ogb[d],  ob1 = ogb[d + 1];
                float ub0 = outb[d], ub1 = outb[d + 1];
                float* cg = accg[nt];
                float* cz = accz[nt];
                float2 t0 = *reinterpret_cast<float2*>(&s_t[rl0 * 132 + d]);
                float2 t1 = *reinterpret_cast<float2*>(&s_t[(rl0 + 8) * 132 + d]);
                float2 o0, o1;
                o0.x = t0.x + sigmoidf_(cg[0] + ob0) * (cz[0] + ub0);
                o0.y = t0.y + sigmoidf_(cg[1] + ob1) * (cz[1] + ub1);
                o1.x = t1.x + sigmoidf_(cg[2] + ob0) * (cz[2] + ub0);
                o1.y = t1.y + sigmoidf_(cg[3] + ob1) * (cz[3] + ub1);
                *reinterpret_cast<float2*>(&out[(size_t)(r0 + rl0) * DDIM + d])     = o0;
                *reinterpret_cast<float2*>(&out[(size_t)(r0 + rl0 + 8) * DDIM + d]) = o1;
            }
        }
    }
}

// ---------------------------------------------------------------------------
extern "C" void kernel_launch(void* const* d_in, const int* in_sizes, int n_in,
                              void* d_out, int out_size)
{
    const float* Z     = (const float*)d_in[0];
    const float* mask  = (const float*)d_in[1];
    const float* ln1w  = (const float*)d_in[2];
    const float* ln1b  = (const float*)d_in[3];
    const float* lrpw  = (const float*)d_in[4];
    const float* lrpb  = (const float*)d_in[5];
    const float* gatew = (const float*)d_in[6];
    const float* gateb = (const float*)d_in[7];
    const float* ogw   = (const float*)d_in[8];
    const float* ogb   = (const float*)d_in[9];
    const float* ln2w  = (const float*)d_in[10];
    const float* ln2b  = (const float*)d_in[11];
    const float* opw   = (const float*)d_in[12];
    const float* outb  = (const float*)d_in[13];
    float* out = (float*)d_out;

    cudaFuncSetAttribute(k1_mma,     cudaFuncAttributeMaxDynamicSharedMemorySize, K1_SMEM);
    cudaFuncSetAttribute(k2_tri_mma, cudaFuncAttributeMaxDynamicSharedMemorySize, K2_SMEM);
    cudaFuncSetAttribute(k3_mma,     cudaFuncAttributeMaxDynamicSharedMemorySize, K3_SMEM);

    k0_wprep<<<128, 256>>>(lrpw, gatew, ogw, opw);

    k1_mma<<<NN / 128, 256, K1_SMEM>>>(Z, mask, ln1w, ln1b, lrpb, gateb);

    dim3 g2(4, 8, 128);
    k2_tri_mma<<<g2, 256, K2_SMEM>>>();

    k3_mma<<<NN / 64, 256, K3_SMEM>>>(ogb, ln2w, ln2b, outb, out);
}

// round 10
// speedup vs baseline: 5.3361x; 1.1329x over previous
#include <cuda_runtime.h>
#include <cuda_bf16.h>
#include <cuda_fp16.h>
#include <cstdint>

#define NDIM 512
#define DDIM 128
#define NN (NDIM*NDIM)

// Scratch (allocation-free rule: __device__ globals)
__device__ __half g_L16 [(size_t)DDIM * NN];   // [c][i][k] fp16 (single plane)
__device__ __half g_Rh16[(size_t)DDIM * NN];   // [c][j][k] fp16 hi
__device__ __half g_Rl16[(size_t)DDIM * NN];   // [c][j][k] fp16 lo
__device__ float g_T[(size_t)DDIM * NN];       // [c][i][j]
// split-bf16 weights for stage-1 (prepped by k0)
__device__ __nv_bfloat16 g_Wl_hi[256 * 128];
__device__ __nv_bfloat16 g_Wl_lo[256 * 128];
__device__ __nv_bfloat16 g_Wg_hi[256 * 128];
// bf16 weights for stage-2 (og / op)
__device__ __nv_bfloat16 g_Wo_bf[128 * 128];
__device__ __nv_bfloat16 g_Wp_bf[128 * 128];

__device__ __forceinline__ float sigmoidf_(float x) {
    return 1.0f / (1.0f + __expf(-x));
}

__device__ __forceinline__ uint32_t smem_u32(const void* p) {
    uint32_t a;
    asm("{ .reg .u64 t; cvta.to.shared.u64 t, %1; cvt.u32.u64 %0, t; }" : "=r"(a) : "l"(p));
    return a;
}

__device__ __forceinline__ uint32_t sw128(uint32_t bo) {
    return bo ^ ((bo >> 3) & 0x70);
}

__device__ __forceinline__ void cp16(uint32_t dst, const void* src) {
    asm volatile("cp.async.cg.shared.global [%0], [%1], 16;" :: "r"(dst), "l"(src) : "memory");
}
#define CP_COMMIT() asm volatile("cp.async.commit_group;" ::: "memory")
#define CP_WAIT0()  asm volatile("cp.async.wait_group 0;" ::: "memory")
#define CP_WAIT1()  asm volatile("cp.async.wait_group 1;" ::: "memory")

__device__ __forceinline__ void ldm_x4(uint32_t r[4], uint32_t addr) {
    asm volatile("ldmatrix.sync.aligned.m8n8.x4.shared.b16 {%0,%1,%2,%3}, [%4];"
        : "=r"(r[0]), "=r"(r[1]), "=r"(r[2]), "=r"(r[3]) : "r"(addr));
}

// bf16 MMA (k1/k3)
__device__ __forceinline__ void mma16816(float c[4], const uint32_t a[4],
                                         uint32_t b0, uint32_t b1) {
    asm volatile("mma.sync.aligned.m16n8k16.row.col.f32.bf16.bf16.f32 "
        "{%0,%1,%2,%3}, {%4,%5,%6,%7}, {%8,%9}, {%0,%1,%2,%3};"
        : "+f"(c[0]), "+f"(c[1]), "+f"(c[2]), "+f"(c[3])
        : "r"(a[0]), "r"(a[1]), "r"(a[2]), "r"(a[3]), "r"(b0), "r"(b1));
}

// fp16 MMA (k2)
__device__ __forceinline__ void mma16816h(float c[4], const uint32_t a[4],
                                          uint32_t b0, uint32_t b1) {
    asm volatile("mma.sync.aligned.m16n8k16.row.col.f32.f16.f16.f32 "
        "{%0,%1,%2,%3}, {%4,%5,%6,%7}, {%8,%9}, {%0,%1,%2,%3};"
        : "+f"(c[0]), "+f"(c[1]), "+f"(c[2]), "+f"(c[3])
        : "r"(a[0]), "r"(a[1]), "r"(a[2]), "r"(a[3]), "r"(b0), "r"(b1));
}

// fp16 hi|lo split pack (hi in low 16 bits, lo in high 16 bits)
__device__ __forceinline__ uint32_t pack_split_h(float v) {
    __half hi = __float2half(v);
    __half lo = __float2half(v - __half2float(hi));
    uint32_t h = *reinterpret_cast<unsigned short*>(&hi);
    uint32_t l = *reinterpret_cast<unsigned short*>(&lo);
    return h | (l << 16);
}

__device__ __forceinline__ uint32_t pack_bf2(float a, float b) {
    __nv_bfloat16 h0 = __float2bfloat16(a);
    __nv_bfloat16 h1 = __float2bfloat16(b);
    return (uint32_t)*reinterpret_cast<unsigned short*>(&h0) |
           ((uint32_t)*reinterpret_cast<unsigned short*>(&h1) << 16);
}

// ---------------------------------------------------------------------------
// Kernel 0: weight prep (split lrp, bf16 gate/og/op)
// ---------------------------------------------------------------------------
__global__ void k0_wprep(const float* __restrict__ lrpw, const float* __restrict__ gatew,
                         const float* __restrict__ ogw,  const float* __restrict__ opw)
{
    int i = blockIdx.x * blockDim.x + threadIdx.x;
    if (i < 256 * 128) {
        float v = lrpw[i];
        __nv_bfloat16 h = __float2bfloat16(v);
        g_Wl_hi[i] = h;
        g_Wl_lo[i] = __float2bfloat16(v - __bfloat162float(h));
        g_Wg_hi[i] = __float2bfloat16(gatew[i]);
    }
    if (i < 128 * 128) {
        g_Wo_bf[i] = __float2bfloat16(ogw[i]);
        g_Wp_bf[i] = __float2bfloat16(opw[i]);
    }
}

// ---------------------------------------------------------------------------
// Kernel 1 (HMMA): LN1 + lrp (3-prod bf16) / gate (1-prod) -> fp16 L / split R
// smem: A planes 64KB | W planes 48KB (stage buffer ALIASES W region)
// 112KB -> 2 CTAs/SM
// ---------------------------------------------------------------------------
#define K1_A_OFF   0
#define K1_W_OFF   65536
#define K1_SMEM    114688

__global__ __launch_bounds__(256, 2)
void k1_mma(const float* __restrict__ Z, const float* __restrict__ mask,
            const float* __restrict__ ln1w, const float* __restrict__ ln1b,
            const float* __restrict__ lrpb, const float* __restrict__ gateb)
{
    extern __shared__ __align__(1024) char smc[];
    const uint32_t sbase = smem_u32(smc);
    uint32_t* stage = reinterpret_cast<uint32_t*>(smc + K1_W_OFF);   // aliases W planes

    const int tid = threadIdx.x;
    const int warp = tid >> 5;
    const uint32_t lane = tid & 31;
    const int r0 = blockIdx.x * 128;

    // ---- Phase A: load Z rows, LN1, split-bf16 into swizzled A planes ----
    {
        const int k4 = lane * 4;
        const int kc = lane >> 4;
        const uint32_t kb = (lane & 15) * 8;
        float4 w4 = *reinterpret_cast<const float4*>(ln1w + k4);
        float4 b4 = *reinterpret_cast<const float4*>(ln1b + k4);
        #pragma unroll 2
        for (int rr = 0; rr < 16; rr++) {
            int rloc = warp * 16 + rr;
            float4 v = *reinterpret_cast<const float4*>(Z + (size_t)(r0 + rloc) * DDIM + k4);
            float s  = v.x + v.y + v.z + v.w;
            float s2 = v.x * v.x + v.y * v.y + v.z * v.z + v.w * v.w;
            #pragma unroll
            for (int o = 16; o; o >>= 1) {
                s  += __shfl_xor_sync(0xffffffffu, s, o);
                s2 += __shfl_xor_sync(0xffffffffu, s2, o);
            }
            float m = s * 0.0078125f;
            float var = fmaf(-m, m, s2 * 0.0078125f);
            float rstd = rsqrtf(var + 1e-5f);
            float zn[4] = {
                (v.x - m) * rstd * w4.x + b4.x,
                (v.y - m) * rstd * w4.y + b4.y,
                (v.z - m) * rstd * w4.z + b4.z,
                (v.w - m) * rstd * w4.w + b4.w };
            uint32_t hip[2], lop[2];
            #pragma unroll
            for (int q = 0; q < 2; q++) {
                __nv_bfloat16 h0 = __float2bfloat16(zn[q*2]);
                __nv_bfloat16 h1 = __float2bfloat16(zn[q*2+1]);
                __nv_bfloat16 l0 = __float2bfloat16(zn[q*2]   - __bfloat162float(h0));
                __nv_bfloat16 l1 = __float2bfloat16(zn[q*2+1] - __bfloat162float(h1));
                hip[q] = (uint32_t)*reinterpret_cast<unsigned short*>(&h0) |
                         ((uint32_t)*reinterpret_cast<unsigned short*>(&h1) << 16);
                lop[q] = (uint32_t)*reinterpret_cast<unsigned short*>(&l0) |
                         ((uint32_t)*reinterpret_cast<unsigned short*>(&l1) << 16);
            }
            uint32_t sw = sw128((uint32_t)(rloc * 128) + kb);
            *reinterpret_cast<uint2*>(smc + K1_A_OFF + (0*2 + kc) * 16384 + sw) = make_uint2(hip[0], hip[1]);
            *reinterpret_cast<uint2*>(smc + K1_A_OFF + (1*2 + kc) * 16384 + sw) = make_uint2(lop[0], lop[1]);
        }
    }
    __syncthreads();

    const int wm = (warp >> 1) * 32;
    const int wn = (warp & 1) * 32;

    const uint32_t a_row = (lane & 7) + ((lane >> 3) & 1) * 8;
    const uint32_t a_kb  = (lane >> 4) * 16;
    const uint32_t b_row = (lane & 7) + ((lane >> 4) & 1) * 8;
    const uint32_t b_kb  = ((lane >> 3) & 1) * 16;

    const __nv_bfloat16* wtab[3] = { g_Wl_hi, g_Wl_lo, g_Wg_hi };

    #pragma unroll 1
    for (int ct = 0; ct < 4; ct++) {
        const int cbase = ct * 64;

        // ---- load 6 W planes (3 mats x 2 kc) via cp.async ----
        #pragma unroll
        for (int it = 0; it < 12; it++) {
            int u = it * 256 + tid;
            int p = u >> 9; int idx = u & 511;
            int row = idx >> 3, q = idx & 7;
            int shl = p >> 1, kc = p & 1;
            const __nv_bfloat16* src = wtab[shl] + (size_t)(cbase + row) * 128 + kc * 64 + q * 8;
            cp16(sbase + K1_W_OFF + p * 8192 + sw128((uint32_t)(row * 128 + q * 16)), src);
        }
        CP_COMMIT();
        CP_WAIT0();
        __syncthreads();

        float accl[2][4][4], accg[2][4][4];
        #pragma unroll
        for (int mt = 0; mt < 2; mt++)
            #pragma unroll
            for (int nt = 0; nt < 4; nt++)
                #pragma unroll
                for (int q = 0; q < 4; q++) { accl[mt][nt][q] = 0.f; accg[mt][nt][q] = 0.f; }

        #pragma unroll
        for (int kc = 0; kc < 2; kc++) {
            #pragma unroll
            for (int ks = 0; ks < 4; ks++) {
                uint32_t kb = ks * 32;
                uint32_t ah[2][4], al[2][4];
                #pragma unroll
                for (int mt = 0; mt < 2; mt++) {
                    uint32_t sw = sw128((uint32_t)((wm + mt * 16 + a_row) * 128) + kb + a_kb);
                    ldm_x4(ah[mt], sbase + K1_A_OFF + (0*2 + kc) * 16384 + sw);
                    ldm_x4(al[mt], sbase + K1_A_OFF + (1*2 + kc) * 16384 + sw);
                }
                #pragma unroll
                for (int ng = 0; ng < 2; ng++) {
                    uint32_t sw = sw128((uint32_t)((wn + ng * 16 + b_row) * 128) + kb + b_kb);
                    uint32_t wlh[4], wll[4], wgh[4];
                    ldm_x4(wlh, sbase + K1_W_OFF + (0 + kc) * 8192 + sw);
                    ldm_x4(wll, sbase + K1_W_OFF + (2 + kc) * 8192 + sw);
                    ldm_x4(wgh, sbase + K1_W_OFF + (4 + kc) * 8192 + sw);
                    #pragma unroll
                    for (int mt = 0; mt < 2; mt++) {
                        #pragma unroll
                        for (int h = 0; h < 2; h++) {
                            float* cl = accl[mt][ng * 2 + h];
                            float* cg = accg[mt][ng * 2 + h];
                            mma16816(cl, ah[mt], wlh[h*2], wlh[h*2+1]);
                            mma16816(cl, ah[mt], wll[h*2], wll[h*2+1]);
                            mma16816(cl, al[mt], wlh[h*2], wlh[h*2+1]);
                            mma16816(cg, ah[mt], wgh[h*2], wgh[h*2+1]);
                        }
                    }
                }
            }
        }
        __syncthreads();   // all warps done reading W before stage (aliased) writes

        #pragma unroll
        for (int mt = 0; mt < 2; mt++) {
            int rl0 = wm + mt * 16 + (int)(lane >> 2);
            float m0 = mask[r0 + rl0];
            float m1 = mask[r0 + rl0 + 8];
            #pragma unroll
            for (int nt = 0; nt < 4; nt++) {
                int cl0 = wn + nt * 8 + 2 * (int)(lane & 3);
                float lb0 = lrpb[cbase + cl0],  lb1 = lrpb[cbase + cl0 + 1];
                float gb0 = gateb[cbase + cl0], gb1 = gateb[cbase + cl0 + 1];
                float* vl = accl[mt][nt];
                float* vg = accg[mt][nt];
                stage[(cl0    ) * 132 + rl0    ] = pack_split_h((vl[0] + lb0) * m0 * sigmoidf_(vg[0] + gb0));
                stage[(cl0 + 1) * 132 + rl0    ] = pack_split_h((vl[1] + lb1) * m0 * sigmoidf_(vg[1] + gb1));
                stage[(cl0    ) * 132 + rl0 + 8] = pack_split_h((vl[2] + lb0) * m1 * sigmoidf_(vg[2] + gb0));
                stage[(cl0 + 1) * 132 + rl0 + 8] = pack_split_h((vl[3] + lb1) * m1 * sigmoidf_(vg[3] + gb1));
            }
        }
        __syncthreads();

        {
            int c_loc = tid >> 2;
            int seg = tid & 3;
            int cg = cbase + c_loc;
            int rb = seg * 32;
            const uint32_t* srow = &stage[c_loc * 132 + rb];
            #pragma unroll
            for (int blk = 0; blk < 4; blk++) {
                uint32_t hw[4], lw[4];
                #pragma unroll
                for (int q = 0; q < 4; q++) {
                    uint32_t p0 = srow[blk * 8 + q * 2];
                    uint32_t p1 = srow[blk * 8 + q * 2 + 1];
                    hw[q] = (p0 & 0xffffu) | (p1 << 16);
                    lw[q] = (p0 >> 16) | (p1 & 0xffff0000u);
                }
                if (cg < 128) {
                    *reinterpret_cast<uint4*>(g_L16 + (size_t)cg * NN + r0 + rb + blk * 8) =
                        make_uint4(hw[0], hw[1], hw[2], hw[3]);
                } else {
                    *reinterpret_cast<uint4*>(g_Rh16 + (size_t)(cg - 128) * NN + r0 + rb + blk * 8) =
                        make_uint4(hw[0], hw[1], hw[2], hw[3]);
                    *reinterpret_cast<uint4*>(g_Rl16 + (size_t)(cg - 128) * NN + r0 + rb + blk * 8) =
                        make_uint4(lw[0], lw[1], lw[2], lw[3]);
                }
            }
        }
        __syncthreads();
    }
}

// ---------------------------------------------------------------------------
// Kernel 2: fp16 2-product mma.sync GEMM  T_c = L_c @ R_c^T
// CTA tile 128(i) x 64(j), K-chunk 64, 3-stage, 2 CTAs/SM.
// smem/stage: A 16K | Bh 8K | Bl 8K = 32KB; x3 = 96KB
// ---------------------------------------------------------------------------
#define K2_AP 16384
#define K2_BP 8192
#define K2_STG (K2_AP + 2 * K2_BP)   // 32768
#define K2_SMEM (3 * K2_STG)         // 98304

__device__ __forceinline__ void k2_prefetch(uint32_t sbase, int stage_i,
    const __half* A, const __half* Bh, const __half* Bl,
    int i0, int j0, int k0, int tid)
{
    uint32_t st = sbase + stage_i * K2_STG;
    // A plane: 128 rows x 128B
    #pragma unroll
    for (int it = 0; it < 4; it++) {
        int idx = it * 256 + tid;
        int r = idx >> 3, q = idx & 7;
        uint32_t sw = sw128((uint32_t)(r * 128 + q * 16));
        cp16(st + sw, A + (size_t)(i0 + r) * NDIM + k0 + q * 8);
    }
    // B planes: 64 rows x 128B each
    #pragma unroll
    for (int it = 0; it < 2; it++) {
        int idx = it * 256 + tid;
        int r = idx >> 3, q = idx & 7;
        uint32_t sw = sw128((uint32_t)(r * 128 + q * 16));
        cp16(st + K2_AP + sw,          Bh + (size_t)(j0 + r) * NDIM + k0 + q * 8);
        cp16(st + K2_AP + K2_BP + sw,  Bl + (size_t)(j0 + r) * NDIM + k0 + q * 8);
    }
    CP_COMMIT();
}

__global__ __launch_bounds__(256, 2)
void k2_tri_mma()
{
    extern __shared__ __align__(1024) char smc[];
    const uint32_t sbase = smem_u32(smc);
    const int tid = threadIdx.x;
    const int warp = tid >> 5;
    const uint32_t lane = tid & 31;
    const int c = blockIdx.z;
    const int i0 = blockIdx.x * 128, j0 = blockIdx.y * 64;

    const __half* __restrict__ A  = g_L16  + (size_t)c * NN;
    const __half* __restrict__ Bh = g_Rh16 + (size_t)c * NN;
    const __half* __restrict__ Bl = g_Rl16 + (size_t)c * NN;
    float* __restrict__ Tc = g_T + (size_t)c * NN;

    const int wm = (warp >> 1) * 32;    // 0..96
    const int wn = (warp & 1) * 32;     // 0/32

    const uint32_t a_row = (lane & 7) + ((lane >> 3) & 1) * 8;
    const uint32_t a_kb  = (lane >> 4) * 16;
    const uint32_t b_row = (lane & 7) + ((lane >> 4) & 1) * 8;
    const uint32_t b_kb  = ((lane >> 3) & 1) * 16;

    float acc[2][4][4];
    #pragma unroll
    for (int mt = 0; mt < 2; mt++)
        #pragma unroll
        for (int nt = 0; nt < 4; nt++)
            #pragma unroll
            for (int q = 0; q < 4; q++) acc[mt][nt][q] = 0.0f;

    k2_prefetch(sbase, 0, A, Bh, Bl, i0, j0, 0, tid);
    k2_prefetch(sbase, 1, A, Bh, Bl, i0, j0, 64, tid);

    #pragma unroll 1
    for (int ch = 0; ch < 8; ch++) {
        if (ch == 7) { CP_WAIT0(); } else { CP_WAIT1(); }
        __syncthreads();
        if (ch + 2 < 8)
            k2_prefetch(sbase, (ch + 2) % 3, A, Bh, Bl, i0, j0, (ch + 2) * 64, tid);

        uint32_t st = sbase + (ch % 3) * K2_STG;
        uint32_t sA = st, sBh = st + K2_AP, sBl = st + K2_AP + K2_BP;

        #pragma unroll
        for (int ks = 0; ks < 4; ks++) {
            uint32_t kb = ks * 32;
            uint32_t a[2][4];
            #pragma unroll
            for (int mt = 0; mt < 2; mt++) {
                uint32_t sw = sw128((uint32_t)((wm + mt * 16 + a_row) * 128) + kb + a_kb);
                ldm_x4(a[mt], sA + sw);
            }
            #pragma unroll
            for (int ng = 0; ng < 2; ng++) {
                uint32_t sw = sw128((uint32_t)((wn + ng * 16 + b_row) * 128) + kb + b_kb);
                uint32_t bh[4], bl[4];
                ldm_x4(bh, sBh + sw);
                ldm_x4(bl, sBl + sw);
                #pragma unroll
                for (int mt = 0; mt < 2; mt++) {
                    #pragma unroll
                    for (int h = 0; h < 2; h++) {
                        float* cc = acc[mt][ng * 2 + h];
                        mma16816h(cc, a[mt], bh[h * 2], bh[h * 2 + 1]);
                        mma16816h(cc, a[mt], bl[h * 2], bl[h * 2 + 1]);
                    }
                }
            }
        }
        __syncthreads();
    }

    const int rbase = i0 + wm + (int)(lane >> 2);
    const int cbase = j0 + wn + 2 * (int)(lane & 3);
    #pragma unroll
    for (int mt = 0; mt < 2; mt++) {
        #pragma unroll
        for (int nt = 0; nt < 4; nt++) {
            float* cc = acc[mt][nt];
            int col = cbase + nt * 8;
            int r1 = rbase + mt * 16;
            *reinterpret_cast<float2*>(&Tc[(size_t)r1 * NDIM + col])       = make_float2(cc[0], cc[1]);
            *reinterpret_cast<float2*>(&Tc[(size_t)(r1 + 8) * NDIM + col]) = make_float2(cc[2], cc[3]);
        }
    }
}

// ---------------------------------------------------------------------------
// Kernel 3 (HMMA): 64 rows x 128 cols per CTA, two 64-col W passes, 2 CTAs/SM.
// smem: s_t fp32 [64][132] | A planes 4x8KB | W planes 4x8KB = 99328 B
// ---------------------------------------------------------------------------
#define K3_T_OFF   0
#define K3_A_OFF   33792
#define K3_W_OFF   66560
#define K3_SMEM    99328

__device__ __forceinline__ void k3_loadW(uint32_t sbase, int ch0, int tid) {
    #pragma unroll
    for (int it = 0; it < 8; it++) {
        int u = it * 256 + tid;
        int p = u >> 9; int idx = u & 511;
        int row = idx >> 3, q = idx & 7;
        int pl = p >> 1, kc = p & 1;
        const __nv_bfloat16* src = (pl == 0 ? g_Wo_bf : g_Wp_bf) + (size_t)(ch0 + row) * 128 + kc * 64 + q * 8;
        cp16(sbase + K3_W_OFF + p * 8192 + sw128((uint32_t)(row * 128 + q * 16)), src);
    }
    CP_COMMIT();
}

__global__ __launch_bounds__(256, 2)
void k3_mma(const float* __restrict__ ogb, const float* __restrict__ ln2w,
            const float* __restrict__ ln2b, const float* __restrict__ outb,
            float* __restrict__ out)
{
    extern __shared__ __align__(1024) char smc[];
    const uint32_t sbase = smem_u32(smc);
    float* s_t = reinterpret_cast<float*>(smc + K3_T_OFF);   // [64][132]

    const int tid = threadIdx.x;
    const int warp = tid >> 5;
    const uint32_t lane = tid & 31;
    const int r0 = blockIdx.x * 64;

    // ---- W half 0 via cp.async (overlaps gather) ----
    k3_loadW(sbase, 0, tid);

    // ---- gather g_T [c][r] -> s_t [r][132] fp32 (64 rows), MLP-unrolled ----
    #pragma unroll
    for (int it = 0; it < 8; it++) {
        int u = it * 256 + tid;
        int cch = u >> 4;
        int q = u & 15;
        float4 v = *reinterpret_cast<const float4*>(g_T + (size_t)cch * NN + r0 + q * 4);
        s_t[(q * 4 + 0) * 132 + cch] = v.x;
        s_t[(q * 4 + 1) * 132 + cch] = v.y;
        s_t[(q * 4 + 2) * 132 + cch] = v.z;
        s_t[(q * 4 + 3) * 132 + cch] = v.w;
    }
    __syncthreads();

    // ---- LN2 per row (8 rows/warp); emit bf16 A planes ----
    {
        const int c4 = lane * 4;
        const int kc = lane >> 4;
        const uint32_t kb = (lane & 15) * 8;
        float4 w4 = *reinterpret_cast<const float4*>(ln2w + c4);
        float4 b4 = *reinterpret_cast<const float4*>(ln2b + c4);
        #pragma unroll 1
        for (int rr = 0; rr < 8; rr++) {
            int rloc = warp * 8 + rr;
            float4 v = *reinterpret_cast<float4*>(&s_t[rloc * 132 + c4]);
            float s  = v.x + v.y + v.z + v.w;
            float s2 = v.x * v.x + v.y * v.y + v.z * v.z + v.w * v.w;
            #pragma unroll
            for (int o = 16; o; o >>= 1) {
                s  += __shfl_xor_sync(0xffffffffu, s, o);
                s2 += __shfl_xor_sync(0xffffffffu, s2, o);
            }
            float m = s * 0.0078125f;
            float var = fmaf(-m, m, s2 * 0.0078125f);
            float rstd = rsqrtf(var + 1e-5f);
            float zn[4] = {
                (v.x - m) * rstd * w4.x + b4.x,
                (v.y - m) * rstd * w4.y + b4.y,
                (v.z - m) * rstd * w4.z + b4.z,
                (v.w - m) * rstd * w4.w + b4.w };
            uint32_t sw = sw128((uint32_t)(rloc * 128) + kb);
            *reinterpret_cast<uint2*>(smc + K3_A_OFF + (0*2 + kc) * 8192 + sw) =
                make_uint2(pack_bf2(v.x, v.y), pack_bf2(v.z, v.w));
            *reinterpret_cast<uint2*>(smc + K3_A_OFF + (1*2 + kc) * 8192 + sw) =
                make_uint2(pack_bf2(zn[0], zn[1]), pack_bf2(zn[2], zn[3]));
        }
    }

    const int wm = (warp >> 1) * 16;
    const int wn = (warp & 1) * 32;

    const uint32_t a_row = (lane & 7) + ((lane >> 3) & 1) * 8;
    const uint32_t a_kb  = (lane >> 4) * 16;
    const uint32_t b_row = (lane & 7) + ((lane >> 4) & 1) * 8;
    const uint32_t b_kb  = ((lane >> 3) & 1) * 16;

    #pragma unroll 1
    for (int hh = 0; hh < 2; hh++) {
        const int ch0 = hh * 64;
        CP_WAIT0();
        __syncthreads();

        float accg[4][4], accz[4][4];
        #pragma unroll
        for (int nt = 0; nt < 4; nt++)
            #pragma unroll
            for (int q = 0; q < 4; q++) { accg[nt][q] = 0.f; accz[nt][q] = 0.f; }

        #pragma unroll
        for (int kc = 0; kc < 2; kc++) {
            #pragma unroll
            for (int ks = 0; ks < 4; ks++) {
                uint32_t kb = ks * 32;
                uint32_t ag[4], az[4];
                uint32_t swa = sw128((uint32_t)((wm + a_row) * 128) + kb + a_kb);
                ldm_x4(ag, sbase + K3_A_OFF + (0*2 + kc) * 8192 + swa);
                ldm_x4(az, sbase + K3_A_OFF + (1*2 + kc) * 8192 + swa);
                #pragma unroll
                for (int ng = 0; ng < 2; ng++) {
                    uint32_t swb = sw128((uint32_t)((wn + ng * 16 + b_row) * 128) + kb + b_kb);
                    uint32_t wo[4], wp[4];
                    ldm_x4(wo, sbase + K3_W_OFF + (0*2 + kc) * 8192 + swb);
                    ldm_x4(wp, sbase + K3_W_OFF + (1*2 + kc) * 8192 + swb);
                    #pragma unroll
                    for (int h = 0; h < 2; h++) {
                        mma16816(accg[ng * 2 + h], ag, wo[h*2], wo[h*2+1]);
                        mma16816(accz[ng * 2 + h], az, wp[h*2], wp[h*2+1]);
                    }
                }
            }
        }
        __syncthreads();   // all warps done with W(hh) before reload
        if (hh == 0) k3_loadW(sbase, 64, tid);   // overlap with epilogue

        // ---- epilogue: out = tri + sigmoid(accg+ogb)*(accz+outb) ----
        {
            int rl0 = wm + (int)(lane >> 2);
            #pragma unroll
            for (int nt = 0; nt < 4; nt++) {
                int dl = wn + nt * 8 + 2 * (int)(lane & 3);
                int d = ch0 + dl;
                float ob0 = ogb[d],  ob1 = ogb[d + 1];
                float ub0 = outb[d], ub1 = outb[d + 1];
                float* cg = accg[nt];
                float* cz = accz[nt];
                float2 t0 = *reinterpret_cast<float2*>(&s_t[rl0 * 132 + d]);
                float2 t1 = *reinterpret_cast<float2*>(&s_t[(rl0 + 8) * 132 + d]);
                float2 o0, o1;
                o0.x = t0.x + sigmoidf_(cg[0] + ob0) * (cz[0] + ub0);
                o0.y = t0.y + sigmoidf_(cg[1] + ob1) * (cz[1] + ub1);
                o1.x = t1.x + sigmoidf_(cg[2] + ob0) * (cz[2] + ub0);
                o1.y = t1.y + sigmoidf_(cg[3] + ob1) * (cz[3] + ub1);
                *reinterpret_cast<float2*>(&out[(size_t)(r0 + rl0) * DDIM + d])     = o0;
                *reinterpret_cast<float2*>(&out[(size_t)(r0 + rl0 + 8) * DDIM + d]) = o1;
            }
        }
    }
}

// ---------------------------------------------------------------------------
extern "C" void kernel_launch(void* const* d_in, const int* in_sizes, int n_in,
                              void* d_out, int out_size)
{
    const float* Z     = (const float*)d_in[0];
    const float* mask  = (const float*)d_in[1];
    const float* ln1w  = (const float*)d_in[2];
    const float* ln1b  = (const float*)d_in[3];
    const float* lrpw  = (const float*)d_in[4];
    const float* lrpb  = (const float*)d_in[5];
    const float* gatew = (const float*)d_in[6];
    const float* gateb = (const float*)d_in[7];
    const float* ogw   = (const float*)d_in[8];
    const float* ogb   = (const float*)d_in[9];
    const float* ln2w  = (const float*)d_in[10];
    const float* ln2b  = (const float*)d_in[11];
    const float* opw   = (const float*)d_in[12];
    const float* outb  = (const float*)d_in[13];
    float* out = (float*)d_out;

    cudaFuncSetAttribute(k1_mma,     cudaFuncAttributeMaxDynamicSharedMemorySize, K1_SMEM);
    cudaFuncSetAttribute(k2_tri_mma, cudaFuncAttributeMaxDynamicSharedMemorySize, K2_SMEM);
    cudaFuncSetAttribute(k3_mma,     cudaFuncAttributeMaxDynamicSharedMemorySize, K3_SMEM);

    k0_wprep<<<128, 256>>>(lrpw, gatew, ogw, opw);

    k1_mma<<<NN / 128, 256, K1_SMEM>>>(Z, mask, ln1w, ln1b, lrpb, gateb);

    dim3 g2(4, 8, 128);
    k2_tri_mma<<<g2, 256, K2_SMEM>>>();

    k3_mma<<<NN / 64, 256, K3_SMEM>>>(ogb, ln2w, ln2b, outb, out);
}

// round 11
// speedup vs baseline: 5.4877x; 1.0284x over previous
#include <cuda_runtime.h>
#include <cuda_bf16.h>
#include <cuda_fp16.h>
#include <cstdint>

#define NDIM 512
#define DDIM 128
#define NN (NDIM*NDIM)

// Scratch (allocation-free rule: __device__ globals)
__device__ __half g_L16 [(size_t)DDIM * NN];   // [c][i][k] fp16 (single plane)
__device__ __half g_Rh16[(size_t)DDIM * NN];   // [c][j][k] fp16 hi
__device__ __half g_Rl16[(size_t)DDIM * NN];   // [c][j][k] fp16 lo
__device__ float g_T[(size_t)DDIM * NN];       // [c][i][j]
// fp16 weights for stage-1 (prepped by k0): lrp split hi/lo, gate single
__device__ __half g_Wl_h16[256 * 128];
__device__ __half g_Wl_l16[256 * 128];
__device__ __half g_Wg_16 [256 * 128];
// bf16 weights for stage-2 (og / op)
__device__ __nv_bfloat16 g_Wo_bf[128 * 128];
__device__ __nv_bfloat16 g_Wp_bf[128 * 128];

__device__ __forceinline__ float sigmoidf_(float x) {
    return 1.0f / (1.0f + __expf(-x));
}

__device__ __forceinline__ uint32_t smem_u32(const void* p) {
    uint32_t a;
    asm("{ .reg .u64 t; cvta.to.shared.u64 t, %1; cvt.u32.u64 %0, t; }" : "=r"(a) : "l"(p));
    return a;
}

__device__ __forceinline__ uint32_t sw128(uint32_t bo) {
    return bo ^ ((bo >> 3) & 0x70);
}

__device__ __forceinline__ void cp16(uint32_t dst, const void* src) {
    asm volatile("cp.async.cg.shared.global [%0], [%1], 16;" :: "r"(dst), "l"(src) : "memory");
}
#define CP_COMMIT() asm volatile("cp.async.commit_group;" ::: "memory")
#define CP_WAIT0()  asm volatile("cp.async.wait_group 0;" ::: "memory")
#define CP_WAIT1()  asm volatile("cp.async.wait_group 1;" ::: "memory")

__device__ __forceinline__ void ldm_x4(uint32_t r[4], uint32_t addr) {
    asm volatile("ldmatrix.sync.aligned.m8n8.x4.shared.b16 {%0,%1,%2,%3}, [%4];"
        : "=r"(r[0]), "=r"(r[1]), "=r"(r[2]), "=r"(r[3]) : "r"(addr));
}

// bf16 MMA (k3)
__device__ __forceinline__ void mma16816(float c[4], const uint32_t a[4],
                                         uint32_t b0, uint32_t b1) {
    asm volatile("mma.sync.aligned.m16n8k16.row.col.f32.bf16.bf16.f32 "
        "{%0,%1,%2,%3}, {%4,%5,%6,%7}, {%8,%9}, {%0,%1,%2,%3};"
        : "+f"(c[0]), "+f"(c[1]), "+f"(c[2]), "+f"(c[3])
        : "r"(a[0]), "r"(a[1]), "r"(a[2]), "r"(a[3]), "r"(b0), "r"(b1));
}

// fp16 MMA (k1/k2)
__device__ __forceinline__ void mma16816h(float c[4], const uint32_t a[4],
                                          uint32_t b0, uint32_t b1) {
    asm volatile("mma.sync.aligned.m16n8k16.row.col.f32.f16.f16.f32 "
        "{%0,%1,%2,%3}, {%4,%5,%6,%7}, {%8,%9}, {%0,%1,%2,%3};"
        : "+f"(c[0]), "+f"(c[1]), "+f"(c[2]), "+f"(c[3])
        : "r"(a[0]), "r"(a[1]), "r"(a[2]), "r"(a[3]), "r"(b0), "r"(b1));
}

// fp16 hi|lo split pack (hi in low 16 bits, lo in high 16 bits)
__device__ __forceinline__ uint32_t pack_split_h(float v) {
    __half hi = __float2half(v);
    __half lo = __float2half(v - __half2float(hi));
    uint32_t h = *reinterpret_cast<unsigned short*>(&hi);
    uint32_t l = *reinterpret_cast<unsigned short*>(&lo);
    return h | (l << 16);
}

__device__ __forceinline__ uint32_t pack_h2(float a, float b) {
    __half2 h = __floats2half2_rn(a, b);
    return *reinterpret_cast<uint32_t*>(&h);
}

__device__ __forceinline__ uint32_t pack_bf2(float a, float b) {
    __nv_bfloat16 h0 = __float2bfloat16(a);
    __nv_bfloat16 h1 = __float2bfloat16(b);
    return (uint32_t)*reinterpret_cast<unsigned short*>(&h0) |
           ((uint32_t)*reinterpret_cast<unsigned short*>(&h1) << 16);
}

// ---------------------------------------------------------------------------
// Kernel 0: weight prep (fp16 split lrp, fp16 gate, bf16 og/op)
// ---------------------------------------------------------------------------
__global__ void k0_wprep(const float* __restrict__ lrpw, const float* __restrict__ gatew,
                         const float* __restrict__ ogw,  const float* __restrict__ opw)
{
    int i = blockIdx.x * blockDim.x + threadIdx.x;
    if (i < 256 * 128) {
        float v = lrpw[i];
        __half h = __float2half(v);
        g_Wl_h16[i] = h;
        g_Wl_l16[i] = __float2half(v - __half2float(h));
        g_Wg_16[i] = __float2half(gatew[i]);
    }
    if (i < 128 * 128) {
        g_Wo_bf[i] = __float2bfloat16(ogw[i]);
        g_Wp_bf[i] = __float2bfloat16(opw[i]);
    }
}

// ---------------------------------------------------------------------------
// Kernel 1 (fp16 HMMA): LN1 + lrp (2-prod) / gate (1-prod) -> fp16 L / split R
// smem: A plane 32KB (z fp16, 2 kc) | W planes 48KB (stage ALIASES W)
// 80KB -> 2 CTAs/SM
// ---------------------------------------------------------------------------
#define K1_A_OFF   0
#define K1_W_OFF   32768
#define K1_SMEM    81920

__global__ __launch_bounds__(256, 2)
void k1_mma(const float* __restrict__ Z, const float* __restrict__ mask,
            const float* __restrict__ ln1w, const float* __restrict__ ln1b,
            const float* __restrict__ lrpb, const float* __restrict__ gateb)
{
    extern __shared__ __align__(1024) char smc[];
    const uint32_t sbase = smem_u32(smc);
    uint32_t* stage = reinterpret_cast<uint32_t*>(smc + K1_W_OFF);   // aliases W planes

    const int tid = threadIdx.x;
    const int warp = tid >> 5;
    const uint32_t lane = tid & 31;
    const int r0 = blockIdx.x * 128;

    // ---- Phase A: load Z rows, LN1, single fp16 plane (2 k-chunks) ----
    {
        const int k4 = lane * 4;
        const int kc = lane >> 4;
        const uint32_t kb = (lane & 15) * 8;
        float4 w4 = *reinterpret_cast<const float4*>(ln1w + k4);
        float4 b4 = *reinterpret_cast<const float4*>(ln1b + k4);
        #pragma unroll 2
        for (int rr = 0; rr < 16; rr++) {
            int rloc = warp * 16 + rr;
            float4 v = *reinterpret_cast<const float4*>(Z + (size_t)(r0 + rloc) * DDIM + k4);
            float s  = v.x + v.y + v.z + v.w;
            float s2 = v.x * v.x + v.y * v.y + v.z * v.z + v.w * v.w;
            #pragma unroll
            for (int o = 16; o; o >>= 1) {
                s  += __shfl_xor_sync(0xffffffffu, s, o);
                s2 += __shfl_xor_sync(0xffffffffu, s2, o);
            }
            float m = s * 0.0078125f;
            float var = fmaf(-m, m, s2 * 0.0078125f);
            float rstd = rsqrtf(var + 1e-5f);
            float zn[4] = {
                (v.x - m) * rstd * w4.x + b4.x,
                (v.y - m) * rstd * w4.y + b4.y,
                (v.z - m) * rstd * w4.z + b4.z,
                (v.w - m) * rstd * w4.w + b4.w };
            uint32_t sw = sw128((uint32_t)(rloc * 128) + kb);
            *reinterpret_cast<uint2*>(smc + K1_A_OFF + kc * 16384 + sw) =
                make_uint2(pack_h2(zn[0], zn[1]), pack_h2(zn[2], zn[3]));
        }
    }
    __syncthreads();

    const int wm = (warp >> 1) * 32;
    const int wn = (warp & 1) * 32;

    const uint32_t a_row = (lane & 7) + ((lane >> 3) & 1) * 8;
    const uint32_t a_kb  = (lane >> 4) * 16;
    const uint32_t b_row = (lane & 7) + ((lane >> 4) & 1) * 8;
    const uint32_t b_kb  = ((lane >> 3) & 1) * 16;

    const __half* wtab[3] = { g_Wl_h16, g_Wl_l16, g_Wg_16 };

    #pragma unroll 1
    for (int ct = 0; ct < 4; ct++) {
        const int cbase = ct * 64;

        // ---- load 6 W planes (3 mats x 2 kc) via cp.async ----
        #pragma unroll
        for (int it = 0; it < 12; it++) {
            int u = it * 256 + tid;
            int p = u >> 9; int idx = u & 511;
            int row = idx >> 3, q = idx & 7;
            int shl = p >> 1, kc = p & 1;
            const __half* src = wtab[shl] + (size_t)(cbase + row) * 128 + kc * 64 + q * 8;
            cp16(sbase + K1_W_OFF + p * 8192 + sw128((uint32_t)(row * 128 + q * 16)), src);
        }
        CP_COMMIT();
        CP_WAIT0();
        __syncthreads();

        float accl[2][4][4], accg[2][4][4];
        #pragma unroll
        for (int mt = 0; mt < 2; mt++)
            #pragma unroll
            for (int nt = 0; nt < 4; nt++)
                #pragma unroll
                for (int q = 0; q < 4; q++) { accl[mt][nt][q] = 0.f; accg[mt][nt][q] = 0.f; }

        #pragma unroll
        for (int kc = 0; kc < 2; kc++) {
            #pragma unroll
            for (int ks = 0; ks < 4; ks++) {
                uint32_t kb = ks * 32;
                uint32_t a[2][4];
                #pragma unroll
                for (int mt = 0; mt < 2; mt++) {
                    uint32_t sw = sw128((uint32_t)((wm + mt * 16 + a_row) * 128) + kb + a_kb);
                    ldm_x4(a[mt], sbase + K1_A_OFF + kc * 16384 + sw);
                }
                #pragma unroll
                for (int ng = 0; ng < 2; ng++) {
                    uint32_t sw = sw128((uint32_t)((wn + ng * 16 + b_row) * 128) + kb + b_kb);
                    uint32_t wlh[4], wll[4], wg[4];
                    ldm_x4(wlh, sbase + K1_W_OFF + (0 + kc) * 8192 + sw);
                    ldm_x4(wll, sbase + K1_W_OFF + (2 + kc) * 8192 + sw);
                    ldm_x4(wg,  sbase + K1_W_OFF + (4 + kc) * 8192 + sw);
                    #pragma unroll
                    for (int mt = 0; mt < 2; mt++) {
                        #pragma unroll
                        for (int h = 0; h < 2; h++) {
                            float* cl = accl[mt][ng * 2 + h];
                            float* cg = accg[mt][ng * 2 + h];
                            mma16816h(cl, a[mt], wlh[h*2], wlh[h*2+1]);
                            mma16816h(cl, a[mt], wll[h*2], wll[h*2+1]);
                            mma16816h(cg, a[mt], wg[h*2],  wg[h*2+1]);
                        }
                    }
                }
            }
        }
        __syncthreads();   // all warps done reading W before stage (aliased) writes

        #pragma unroll
        for (int mt = 0; mt < 2; mt++) {
            int rl0 = wm + mt * 16 + (int)(lane >> 2);
            float m0 = mask[r0 + rl0];
            float m1 = mask[r0 + rl0 + 8];
            #pragma unroll
            for (int nt = 0; nt < 4; nt++) {
                int cl0 = wn + nt * 8 + 2 * (int)(lane & 3);
                float lb0 = lrpb[cbase + cl0],  lb1 = lrpb[cbase + cl0 + 1];
                float gb0 = gateb[cbase + cl0], gb1 = gateb[cbase + cl0 + 1];
                float* vl = accl[mt][nt];
                float* vg = accg[mt][nt];
                stage[(cl0    ) * 132 + rl0    ] = pack_split_h((vl[0] + lb0) * m0 * sigmoidf_(vg[0] + gb0));
                stage[(cl0 + 1) * 132 + rl0    ] = pack_split_h((vl[1] + lb1) * m0 * sigmoidf_(vg[1] + gb1));
                stage[(cl0    ) * 132 + rl0 + 8] = pack_split_h((vl[2] + lb0) * m1 * sigmoidf_(vg[2] + gb0));
                stage[(cl0 + 1) * 132 + rl0 + 8] = pack_split_h((vl[3] + lb1) * m1 * sigmoidf_(vg[3] + gb1));
            }
        }
        __syncthreads();

        {
            int c_loc = tid >> 2;
            int seg = tid & 3;
            int cg = cbase + c_loc;
            int rb = seg * 32;
            const uint32_t* srow = &stage[c_loc * 132 + rb];
            #pragma unroll
            for (int blk = 0; blk < 4; blk++) {
                uint32_t hw[4], lw[4];
                #pragma unroll
                for (int q = 0; q < 4; q++) {
                    uint32_t p0 = srow[blk * 8 + q * 2];
                    uint32_t p1 = srow[blk * 8 + q * 2 + 1];
                    hw[q] = (p0 & 0xffffu) | (p1 << 16);
                    lw[q] = (p0 >> 16) | (p1 & 0xffff0000u);
                }
                if (cg < 128) {
                    *reinterpret_cast<uint4*>(g_L16 + (size_t)cg * NN + r0 + rb + blk * 8) =
                        make_uint4(hw[0], hw[1], hw[2], hw[3]);
                } else {
                    *reinterpret_cast<uint4*>(g_Rh16 + (size_t)(cg - 128) * NN + r0 + rb + blk * 8) =
                        make_uint4(hw[0], hw[1], hw[2], hw[3]);
                    *reinterpret_cast<uint4*>(g_Rl16 + (size_t)(cg - 128) * NN + r0 + rb + blk * 8) =
                        make_uint4(lw[0], lw[1], lw[2], lw[3]);
                }
            }
        }
        __syncthreads();
    }
}

// ---------------------------------------------------------------------------
// Kernel 2: fp16 2-product mma.sync GEMM  T_c = L_c @ R_c^T
// CTA tile 128(i) x 64(j), K-chunk 64, 3-stage, 2 CTAs/SM.
// ---------------------------------------------------------------------------
#define K2_AP 16384
#define K2_BP 8192
#define K2_STG (K2_AP + 2 * K2_BP)   // 32768
#define K2_SMEM (3 * K2_STG)         // 98304

__device__ __forceinline__ void k2_prefetch(uint32_t sbase, int stage_i,
    const __half* A, const __half* Bh, const __half* Bl,
    int i0, int j0, int k0, int tid)
{
    uint32_t st = sbase + stage_i * K2_STG;
    #pragma unroll
    for (int it = 0; it < 4; it++) {
        int idx = it * 256 + tid;
        int r = idx >> 3, q = idx & 7;
        uint32_t sw = sw128((uint32_t)(r * 128 + q * 16));
        cp16(st + sw, A + (size_t)(i0 + r) * NDIM + k0 + q * 8);
    }
    #pragma unroll
    for (int it = 0; it < 2; it++) {
        int idx = it * 256 + tid;
        int r = idx >> 3, q = idx & 7;
        uint32_t sw = sw128((uint32_t)(r * 128 + q * 16));
        cp16(st + K2_AP + sw,          Bh + (size_t)(j0 + r) * NDIM + k0 + q * 8);
        cp16(st + K2_AP + K2_BP + sw,  Bl + (size_t)(j0 + r) * NDIM + k0 + q * 8);
    }
    CP_COMMIT();
}

__global__ __launch_bounds__(256, 2)
void k2_tri_mma()
{
    extern __shared__ __align__(1024) char smc[];
    const uint32_t sbase = smem_u32(smc);
    const int tid = threadIdx.x;
    const int warp = tid >> 5;
    const uint32_t lane = tid & 31;
    const int c = blockIdx.z;
    const int i0 = blockIdx.x * 128, j0 = blockIdx.y * 64;

    const __half* __restrict__ A  = g_L16  + (size_t)c * NN;
    const __half* __restrict__ Bh = g_Rh16 + (size_t)c * NN;
    const __half* __restrict__ Bl = g_Rl16 + (size_t)c * NN;
    float* __restrict__ Tc = g_T + (size_t)c * NN;

    const int wm = (warp >> 1) * 32;
    const int wn = (warp & 1) * 32;

    const uint32_t a_row = (lane & 7) + ((lane >> 3) & 1) * 8;
    const uint32_t a_kb  = (lane >> 4) * 16;
    const uint32_t b_row = (lane & 7) + ((lane >> 4) & 1) * 8;
    const uint32_t b_kb  = ((lane >> 3) & 1) * 16;

    float acc[2][4][4];
    #pragma unroll
    for (int mt = 0; mt < 2; mt++)
        #pragma unroll
        for (int nt = 0; nt < 4; nt++)
            #pragma unroll
            for (int q = 0; q < 4; q++) acc[mt][nt][q] = 0.0f;

    k2_prefetch(sbase, 0, A, Bh, Bl, i0, j0, 0, tid);
    k2_prefetch(sbase, 1, A, Bh, Bl, i0, j0, 64, tid);

    #pragma unroll 1
    for (int ch = 0; ch < 8; ch++) {
        if (ch == 7) { CP_WAIT0(); } else { CP_WAIT1(); }
        __syncthreads();
        if (ch + 2 < 8)
            k2_prefetch(sbase, (ch + 2) % 3, A, Bh, Bl, i0, j0, (ch + 2) * 64, tid);

        uint32_t st = sbase + (ch % 3) * K2_STG;
        uint32_t sA = st, sBh = st + K2_AP, sBl = st + K2_AP + K2_BP;

        #pragma unroll
        for (int ks = 0; ks < 4; ks++) {
            uint32_t kb = ks * 32;
            uint32_t a[2][4];
            #pragma unroll
            for (int mt = 0; mt < 2; mt++) {
                uint32_t sw = sw128((uint32_t)((wm + mt * 16 + a_row) * 128) + kb + a_kb);
                ldm_x4(a[mt], sA + sw);
            }
            #pragma unroll
            for (int ng = 0; ng < 2; ng++) {
                uint32_t sw = sw128((uint32_t)((wn + ng * 16 + b_row) * 128) + kb + b_kb);
                uint32_t bh[4], bl[4];
                ldm_x4(bh, sBh + sw);
                ldm_x4(bl, sBl + sw);
                #pragma unroll
                for (int mt = 0; mt < 2; mt++) {
                    #pragma unroll
                    for (int h = 0; h < 2; h++) {
                        float* cc = acc[mt][ng * 2 + h];
                        mma16816h(cc, a[mt], bh[h * 2], bh[h * 2 + 1]);
                        mma16816h(cc, a[mt], bl[h * 2], bl[h * 2 + 1]);
                    }
                }
            }
        }
        __syncthreads();
    }

    const int rbase = i0 + wm + (int)(lane >> 2);
    const int cbase = j0 + wn + 2 * (int)(lane & 3);
    #pragma unroll
    for (int mt = 0; mt < 2; mt++) {
        #pragma unroll
        for (int nt = 0; nt < 4; nt++) {
            float* cc = acc[mt][nt];
            int col = cbase + nt * 8;
            int r1 = rbase + mt * 16;
            *reinterpret_cast<float2*>(&Tc[(size_t)r1 * NDIM + col])       = make_float2(cc[0], cc[1]);
            *reinterpret_cast<float2*>(&Tc[(size_t)(r1 + 8) * NDIM + col]) = make_float2(cc[2], cc[3]);
        }
    }
}

// ---------------------------------------------------------------------------
// Kernel 3 (HMMA): 64 rows x 128 cols per CTA, two 64-col W passes, 2 CTAs/SM.
// ---------------------------------------------------------------------------
#define K3_T_OFF   0
#define K3_A_OFF   33792
#define K3_W_OFF   66560
#define K3_SMEM    99328

__device__ __forceinline__ void k3_loadW(uint32_t sbase, int ch0, int tid) {
    #pragma unroll
    for (int it = 0; it < 8; it++) {
        int u = it * 256 + tid;
        int p = u >> 9; int idx = u & 511;
        int row = idx >> 3, q = idx & 7;
        int pl = p >> 1, kc = p & 1;
        const __nv_bfloat16* src = (pl == 0 ? g_Wo_bf : g_Wp_bf) + (size_t)(ch0 + row) * 128 + kc * 64 + q * 8;
        cp16(sbase + K3_W_OFF + p * 8192 + sw128((uint32_t)(row * 128 + q * 16)), src);
    }
    CP_COMMIT();
}

__global__ __launch_bounds__(256, 2)
void k3_mma(const float* __restrict__ ogb, const float* __restrict__ ln2w,
            const float* __restrict__ ln2b, const float* __restrict__ outb,
            float* __restrict__ out)
{
    extern __shared__ __align__(1024) char smc[];
    const uint32_t sbase = smem_u32(smc);
    float* s_t = reinterpret_cast<float*>(smc + K3_T_OFF);   // [64][132]

    const int tid = threadIdx.x;
    const int warp = tid >> 5;
    const uint32_t lane = tid & 31;
    const int r0 = blockIdx.x * 64;

    k3_loadW(sbase, 0, tid);

    #pragma unroll
    for (int it = 0; it < 8; it++) {
        int u = it * 256 + tid;
        int cch = u >> 4;
        int q = u & 15;
        float4 v = *reinterpret_cast<const float4*>(g_T + (size_t)cch * NN + r0 + q * 4);
        s_t[(q * 4 + 0) * 132 + cch] = v.x;
        s_t[(q * 4 + 1) * 132 + cch] = v.y;
        s_t[(q * 4 + 2) * 132 + cch] = v.z;
        s_t[(q * 4 + 3) * 132 + cch] = v.w;
    }
    __syncthreads();

    {
        const int c4 = lane * 4;
        const int kc = lane >> 4;
        const uint32_t kb = (lane & 15) * 8;
        float4 w4 = *reinterpret_cast<const float4*>(ln2w + c4);
        float4 b4 = *reinterpret_cast<const float4*>(ln2b + c4);
        #pragma unroll 1
        for (int rr = 0; rr < 8; rr++) {
            int rloc = warp * 8 + rr;
            float4 v = *reinterpret_cast<float4*>(&s_t[rloc * 132 + c4]);
            float s  = v.x + v.y + v.z + v.w;
            float s2 = v.x * v.x + v.y * v.y + v.z * v.z + v.w * v.w;
            #pragma unroll
            for (int o = 16; o; o >>= 1) {
                s  += __shfl_xor_sync(0xffffffffu, s, o);
                s2 += __shfl_xor_sync(0xffffffffu, s2, o);
            }
            float m = s * 0.0078125f;
            float var = fmaf(-m, m, s2 * 0.0078125f);
            float rstd = rsqrtf(var + 1e-5f);
            float zn[4] = {
                (v.x - m) * rstd * w4.x + b4.x,
                (v.y - m) * rstd * w4.y + b4.y,
                (v.z - m) * rstd * w4.z + b4.z,
                (v.w - m) * rstd * w4.w + b4.w };
            uint32_t sw = sw128((uint32_t)(rloc * 128) + kb);
            *reinterpret_cast<uint2*>(smc + K3_A_OFF + (0*2 + kc) * 8192 + sw) =
                make_uint2(pack_bf2(v.x, v.y), pack_bf2(v.z, v.w));
            *reinterpret_cast<uint2*>(smc + K3_A_OFF + (1*2 + kc) * 8192 + sw) =
                make_uint2(pack_bf2(zn[0], zn[1]), pack_bf2(zn[2], zn[3]));
        }
    }

    const int wm = (warp >> 1) * 16;
    const int wn = (warp & 1) * 32;

    const uint32_t a_row = (lane & 7) + ((lane >> 3) & 1) * 8;
    const uint32_t a_kb  = (lane >> 4) * 16;
    const uint32_t b_row = (lane & 7) + ((lane >> 4) & 1) * 8;
    const uint32_t b_kb  = ((lane >> 3) & 1) * 16;

    #pragma unroll 1
    for (int hh = 0; hh < 2; hh++) {
        const int ch0 = hh * 64;
        CP_WAIT0();
        __syncthreads();

        float accg[4][4], accz[4][4];
        #pragma unroll
        for (int nt = 0; nt < 4; nt++)
            #pragma unroll
            for (int q = 0; q < 4; q++) { accg[nt][q] = 0.f; accz[nt][q] = 0.f; }

        #pragma unroll
        for (int kc = 0; kc < 2; kc++) {
            #pragma unroll
            for (int ks = 0; ks < 4; ks++) {
                uint32_t kb = ks * 32;
                uint32_t ag[4], az[4];
                uint32_t swa = sw128((uint32_t)((wm + a_row) * 128) + kb + a_kb);
                ldm_x4(ag, sbase + K3_A_OFF + (0*2 + kc) * 8192 + swa);
                ldm_x4(az, sbase + K3_A_OFF + (1*2 + kc) * 8192 + swa);
                #pragma unroll
                for (int ng = 0; ng < 2; ng++) {
                    uint32_t swb = sw128((uint32_t)((wn + ng * 16 + b_row) * 128) + kb + b_kb);
                    uint32_t wo[4], wp[4];
                    ldm_x4(wo, sbase + K3_W_OFF + (0*2 + kc) * 8192 + swb);
                    ldm_x4(wp, sbase + K3_W_OFF + (1*2 + kc) * 8192 + swb);
                    #pragma unroll
                    for (int h = 0; h < 2; h++) {
                        mma16816(accg[ng * 2 + h], ag, wo[h*2], wo[h*2+1]);
                        mma16816(accz[ng * 2 + h], az, wp[h*2], wp[h*2+1]);
                    }
                }
            }
        }
        __syncthreads();
        if (hh == 0) k3_loadW(sbase, 64, tid);

        {
            int rl0 = wm + (int)(lane >> 2);
            #pragma unroll
            for (int nt = 0; nt < 4; nt++) {
                int dl = wn + nt * 8 + 2 * (int)(lane & 3);
                int d = ch0 + dl;
                float ob0 = ogb[d],  ob1 = ogb[d + 1];
                float ub0 = outb[d], ub1 = outb[d + 1];
                float* cg = accg[nt];
                float* cz = accz[nt];
                float2 t0 = *reinterpret_cast<float2*>(&s_t[rl0 * 132 + d]);
                float2 t1 = *reinterpret_cast<float2*>(&s_t[(rl0 + 8) * 132 + d]);
                float2 o0, o1;
                o0.x = t0.x + sigmoidf_(cg[0] + ob0) * (cz[0] + ub0);
                o0.y = t0.y + sigmoidf_(cg[1] + ob1) * (cz[1] + ub1);
                o1.x = t1.x + sigmoidf_(cg[2] + ob0) * (cz[2] + ub0);
                o1.y = t1.y + sigmoidf_(cg[3] + ob1) * (cz[3] + ub1);
                *reinterpret_cast<float2*>(&out[(size_t)(r0 + rl0) * DDIM + d])     = o0;
                *reinterpret_cast<float2*>(&out[(size_t)(r0 + rl0 + 8) * DDIM + d]) = o1;
            }
        }
    }
}

// ---------------------------------------------------------------------------
extern "C" void kernel_launch(void* const* d_in, const int* in_sizes, int n_in,
                              void* d_out, int out_size)
{
    const float* Z     = (const float*)d_in[0];
    const float* mask  = (const float*)d_in[1];
    const float* ln1w  = (const float*)d_in[2];
    const float* ln1b  = (const float*)d_in[3];
    const float* lrpw  = (const float*)d_in[4];
    const float* lrpb  = (const float*)d_in[5];
    const float* gatew = (const float*)d_in[6];
    const float* gateb = (const float*)d_in[7];
    const float* ogw   = (const float*)d_in[8];
    const float* ogb   = (const float*)d_in[9];
    const float* ln2w  = (const float*)d_in[10];
    const float* ln2b  = (const float*)d_in[11];
    const float* opw   = (const float*)d_in[12];
    const float* outb  = (const float*)d_in[13];
    float* out = (float*)d_out;

    cudaFuncSetAttribute(k1_mma,     cudaFuncAttributeMaxDynamicSharedMemorySize, K1_SMEM);
    cudaFuncSetAttribute(k2_tri_mma, cudaFuncAttributeMaxDynamicSharedMemorySize, K2_SMEM);
    cudaFuncSetAttribute(k3_mma,     cudaFuncAttributeMaxDynamicSharedMemorySize, K3_SMEM);

    k0_wprep<<<128, 256>>>(lrpw, gatew, ogw, opw);

    k1_mma<<<NN / 128, 256, K1_SMEM>>>(Z, mask, ln1w, ln1b, lrpb, gateb);

    dim3 g2(4, 8, 128);
    k2_tri_mma<<<g2, 256, K2_SMEM>>>();

    k3_mma<<<NN / 64, 256, K3_SMEM>>>(ogb, ln2w, ln2b, outb, out);
}

// round 12
// speedup vs baseline: 6.2461x; 1.1382x over previous
#include <cuda_runtime.h>
#include <cuda_bf16.h>
#include <cuda_fp16.h>
#include <cstdint>

#define NDIM 512
#define DDIM 128
#define NN (NDIM*NDIM)

// Scratch (allocation-free rule: __device__ globals)
__device__ __half g_L16[(size_t)DDIM * NN];    // [c][i][k] fp16
__device__ __half g_R16[(size_t)DDIM * NN];    // [c][j][k] fp16
__device__ float g_T[(size_t)DDIM * NN];       // [c][i][j]
// fp16 weights for stage-1 (prepped by k0): lrp split hi/lo, gate single
__device__ __half g_Wl_h16[256 * 128];
__device__ __half g_Wl_l16[256 * 128];
__device__ __half g_Wg_16 [256 * 128];
// bf16 weights for stage-2 (og / op)
__device__ __nv_bfloat16 g_Wo_bf[128 * 128];
__device__ __nv_bfloat16 g_Wp_bf[128 * 128];

__device__ __forceinline__ float sigmoidf_(float x) {
    return 1.0f / (1.0f + __expf(-x));
}

__device__ __forceinline__ uint32_t smem_u32(const void* p) {
    uint32_t a;
    asm("{ .reg .u64 t; cvta.to.shared.u64 t, %1; cvt.u32.u64 %0, t; }" : "=r"(a) : "l"(p));
    return a;
}

__device__ __forceinline__ uint32_t sw128(uint32_t bo) {
    return bo ^ ((bo >> 3) & 0x70);
}

__device__ __forceinline__ void cp16(uint32_t dst, const void* src) {
    asm volatile("cp.async.cg.shared.global [%0], [%1], 16;" :: "r"(dst), "l"(src) : "memory");
}
#define CP_COMMIT() asm volatile("cp.async.commit_group;" ::: "memory")
#define CP_WAIT0()  asm volatile("cp.async.wait_group 0;" ::: "memory")
#define CP_WAIT1()  asm volatile("cp.async.wait_group 1;" ::: "memory")

__device__ __forceinline__ void ldm_x4(uint32_t r[4], uint32_t addr) {
    asm volatile("ldmatrix.sync.aligned.m8n8.x4.shared.b16 {%0,%1,%2,%3}, [%4];"
        : "=r"(r[0]), "=r"(r[1]), "=r"(r[2]), "=r"(r[3]) : "r"(addr));
}

// bf16 MMA (k3)
__device__ __forceinline__ void mma16816(float c[4], const uint32_t a[4],
                                         uint32_t b0, uint32_t b1) {
    asm volatile("mma.sync.aligned.m16n8k16.row.col.f32.bf16.bf16.f32 "
        "{%0,%1,%2,%3}, {%4,%5,%6,%7}, {%8,%9}, {%0,%1,%2,%3};"
        : "+f"(c[0]), "+f"(c[1]), "+f"(c[2]), "+f"(c[3])
        : "r"(a[0]), "r"(a[1]), "r"(a[2]), "r"(a[3]), "r"(b0), "r"(b1));
}

// fp16 MMA (k1/k2)
__device__ __forceinline__ void mma16816h(float c[4], const uint32_t a[4],
                                          uint32_t b0, uint32_t b1) {
    asm volatile("mma.sync.aligned.m16n8k16.row.col.f32.f16.f16.f32 "
        "{%0,%1,%2,%3}, {%4,%5,%6,%7}, {%8,%9}, {%0,%1,%2,%3};"
        : "+f"(c[0]), "+f"(c[1]), "+f"(c[2]), "+f"(c[3])
        : "r"(a[0]), "r"(a[1]), "r"(a[2]), "r"(a[3]), "r"(b0), "r"(b1));
}

// single fp16 pack (bits in low 16)
__device__ __forceinline__ uint32_t pack_h1(float v) {
    __half h = __float2half(v);
    return (uint32_t)*reinterpret_cast<unsigned short*>(&h);
}

__device__ __forceinline__ uint32_t pack_h2(float a, float b) {
    __half2 h = __floats2half2_rn(a, b);
    return *reinterpret_cast<uint32_t*>(&h);
}

__device__ __forceinline__ uint32_t pack_bf2(float a, float b) {
    __nv_bfloat16 h0 = __float2bfloat16(a);
    __nv_bfloat16 h1 = __float2bfloat16(b);
    return (uint32_t)*reinterpret_cast<unsigned short*>(&h0) |
           ((uint32_t)*reinterpret_cast<unsigned short*>(&h1) << 16);
}

// ---------------------------------------------------------------------------
// Kernel 0: weight prep (fp16 split lrp, fp16 gate, bf16 og/op)
// ---------------------------------------------------------------------------
__global__ void k0_wprep(const float* __restrict__ lrpw, const float* __restrict__ gatew,
                         const float* __restrict__ ogw,  const float* __restrict__ opw)
{
    int i = blockIdx.x * blockDim.x + threadIdx.x;
    if (i < 256 * 128) {
        float v = lrpw[i];
        __half h = __float2half(v);
        g_Wl_h16[i] = h;
        g_Wl_l16[i] = __float2half(v - __half2float(h));
        g_Wg_16[i] = __float2half(gatew[i]);
    }
    if (i < 128 * 128) {
        g_Wo_bf[i] = __float2bfloat16(ogw[i]);
        g_Wp_bf[i] = __float2bfloat16(opw[i]);
    }
}

// ---------------------------------------------------------------------------
// Kernel 1 (fp16 HMMA): LN1 + lrp (2-prod) / gate (1-prod) -> fp16 L / R
// smem: A plane 32KB (z fp16, 2 kc) | W planes 48KB (stage ALIASES W)
// 80KB -> 2 CTAs/SM
// ---------------------------------------------------------------------------
#define K1_A_OFF   0
#define K1_W_OFF   32768
#define K1_SMEM    81920

__global__ __launch_bounds__(256, 2)
void k1_mma(const float* __restrict__ Z, const float* __restrict__ mask,
            const float* __restrict__ ln1w, const float* __restrict__ ln1b,
            const float* __restrict__ lrpb, const float* __restrict__ gateb)
{
    extern __shared__ __align__(1024) char smc[];
    const uint32_t sbase = smem_u32(smc);
    uint32_t* stage = reinterpret_cast<uint32_t*>(smc + K1_W_OFF);   // aliases W planes

    const int tid = threadIdx.x;
    const int warp = tid >> 5;
    const uint32_t lane = tid & 31;
    const int r0 = blockIdx.x * 128;

    // ---- Phase A: load Z rows, LN1, single fp16 plane (2 k-chunks) ----
    {
        const int k4 = lane * 4;
        const int kc = lane >> 4;
        const uint32_t kb = (lane & 15) * 8;
        float4 w4 = *reinterpret_cast<const float4*>(ln1w + k4);
        float4 b4 = *reinterpret_cast<const float4*>(ln1b + k4);
        #pragma unroll 2
        for (int rr = 0; rr < 16; rr++) {
            int rloc = warp * 16 + rr;
            float4 v = *reinterpret_cast<const float4*>(Z + (size_t)(r0 + rloc) * DDIM + k4);
            float s  = v.x + v.y + v.z + v.w;
            float s2 = v.x * v.x + v.y * v.y + v.z * v.z + v.w * v.w;
            #pragma unroll
            for (int o = 16; o; o >>= 1) {
                s  += __shfl_xor_sync(0xffffffffu, s, o);
                s2 += __shfl_xor_sync(0xffffffffu, s2, o);
            }
            float m = s * 0.0078125f;
            float var = fmaf(-m, m, s2 * 0.0078125f);
            float rstd = rsqrtf(var + 1e-5f);
            float zn[4] = {
                (v.x - m) * rstd * w4.x + b4.x,
                (v.y - m) * rstd * w4.y + b4.y,
                (v.z - m) * rstd * w4.z + b4.z,
                (v.w - m) * rstd * w4.w + b4.w };
            uint32_t sw = sw128((uint32_t)(rloc * 128) + kb);
            *reinterpret_cast<uint2*>(smc + K1_A_OFF + kc * 16384 + sw) =
                make_uint2(pack_h2(zn[0], zn[1]), pack_h2(zn[2], zn[3]));
        }
    }
    __syncthreads();

    const int wm = (warp >> 1) * 32;
    const int wn = (warp & 1) * 32;

    const uint32_t a_row = (lane & 7) + ((lane >> 3) & 1) * 8;
    const uint32_t a_kb  = (lane >> 4) * 16;
    const uint32_t b_row = (lane & 7) + ((lane >> 4) & 1) * 8;
    const uint32_t b_kb  = ((lane >> 3) & 1) * 16;

    const __half* wtab[3] = { g_Wl_h16, g_Wl_l16, g_Wg_16 };

    #pragma unroll 1
    for (int ct = 0; ct < 4; ct++) {
        const int cbase = ct * 64;

        // ---- load 6 W planes (3 mats x 2 kc) via cp.async ----
        #pragma unroll
        for (int it = 0; it < 12; it++) {
            int u = it * 256 + tid;
            int p = u >> 9; int idx = u & 511;
            int row = idx >> 3, q = idx & 7;
            int shl = p >> 1, kc = p & 1;
            const __half* src = wtab[shl] + (size_t)(cbase + row) * 128 + kc * 64 + q * 8;
            cp16(sbase + K1_W_OFF + p * 8192 + sw128((uint32_t)(row * 128 + q * 16)), src);
        }
        CP_COMMIT();
        CP_WAIT0();
        __syncthreads();

        float accl[2][4][4], accg[2][4][4];
        #pragma unroll
        for (int mt = 0; mt < 2; mt++)
            #pragma unroll
            for (int nt = 0; nt < 4; nt++)
                #pragma unroll
                for (int q = 0; q < 4; q++) { accl[mt][nt][q] = 0.f; accg[mt][nt][q] = 0.f; }

        #pragma unroll
        for (int kc = 0; kc < 2; kc++) {
            #pragma unroll
            for (int ks = 0; ks < 4; ks++) {
                uint32_t kb = ks * 32;
                uint32_t a[2][4];
                #pragma unroll
                for (int mt = 0; mt < 2; mt++) {
                    uint32_t sw = sw128((uint32_t)((wm + mt * 16 + a_row) * 128) + kb + a_kb);
                    ldm_x4(a[mt], sbase + K1_A_OFF + kc * 16384 + sw);
                }
                #pragma unroll
                for (int ng = 0; ng < 2; ng++) {
                    uint32_t sw = sw128((uint32_t)((wn + ng * 16 + b_row) * 128) + kb + b_kb);
                    uint32_t wlh[4], wll[4], wg[4];
                    ldm_x4(wlh, sbase + K1_W_OFF + (0 + kc) * 8192 + sw);
                    ldm_x4(wll, sbase + K1_W_OFF + (2 + kc) * 8192 + sw);
                    ldm_x4(wg,  sbase + K1_W_OFF + (4 + kc) * 8192 + sw);
                    #pragma unroll
                    for (int mt = 0; mt < 2; mt++) {
                        #pragma unroll
                        for (int h = 0; h < 2; h++) {
                            float* cl = accl[mt][ng * 2 + h];
                            float* cg = accg[mt][ng * 2 + h];
                            mma16816h(cl, a[mt], wlh[h*2], wlh[h*2+1]);
                            mma16816h(cl, a[mt], wll[h*2], wll[h*2+1]);
                            mma16816h(cg, a[mt], wg[h*2],  wg[h*2+1]);
                        }
                    }
                }
            }
        }
        __syncthreads();   // all warps done reading W before stage (aliased) writes

        #pragma unroll
        for (int mt = 0; mt < 2; mt++) {
            int rl0 = wm + mt * 16 + (int)(lane >> 2);
            float m0 = mask[r0 + rl0];
            float m1 = mask[r0 + rl0 + 8];
            #pragma unroll
            for (int nt = 0; nt < 4; nt++) {
                int cl0 = wn + nt * 8 + 2 * (int)(lane & 3);
                float lb0 = lrpb[cbase + cl0],  lb1 = lrpb[cbase + cl0 + 1];
                float gb0 = gateb[cbase + cl0], gb1 = gateb[cbase + cl0 + 1];
                float* vl = accl[mt][nt];
                float* vg = accg[mt][nt];
                stage[(cl0    ) * 132 + rl0    ] = pack_h1((vl[0] + lb0) * m0 * sigmoidf_(vg[0] + gb0));
                stage[(cl0 + 1) * 132 + rl0    ] = pack_h1((vl[1] + lb1) * m0 * sigmoidf_(vg[1] + gb1));
                stage[(cl0    ) * 132 + rl0 + 8] = pack_h1((vl[2] + lb0) * m1 * sigmoidf_(vg[2] + gb0));
                stage[(cl0 + 1) * 132 + rl0 + 8] = pack_h1((vl[3] + lb1) * m1 * sigmoidf_(vg[3] + gb1));
            }
        }
        __syncthreads();

        {
            int c_loc = tid >> 2;
            int seg = tid & 3;
            int cg = cbase + c_loc;
            __half* dst = (cg < 128) ? (g_L16 + (size_t)cg * NN) : (g_R16 + (size_t)(cg - 128) * NN);
            int rb = seg * 32;
            const uint32_t* srow = &stage[c_loc * 132 + rb];
            #pragma unroll
            for (int blk = 0; blk < 4; blk++) {
                uint32_t hw[4];
                #pragma unroll
                for (int q = 0; q < 4; q++) {
                    uint32_t p0 = srow[blk * 8 + q * 2];
                    uint32_t p1 = srow[blk * 8 + q * 2 + 1];
                    hw[q] = (p0 & 0xffffu) | (p1 << 16);
                }
                *reinterpret_cast<uint4*>(dst + r0 + rb + blk * 8) = make_uint4(hw[0], hw[1], hw[2], hw[3]);
            }
        }
        __syncthreads();
    }
}

// ---------------------------------------------------------------------------
// Kernel 2: fp16 1-product mma.sync GEMM  T_c = L_c @ R_c^T
// CTA tile 128(i) x 64(j), K-chunk 64, 3-stage, 3 CTAs/SM.
// smem/stage: A 16K | B 8K = 24KB; x3 = 72KB
// ---------------------------------------------------------------------------
#define K2_AP 16384
#define K2_BP 8192
#define K2_STG (K2_AP + K2_BP)       // 24576
#define K2_SMEM (3 * K2_STG)         // 73728

__device__ __forceinline__ void k2_prefetch(uint32_t sbase, int stage_i,
    const __half* A, const __half* B,
    int i0, int j0, int k0, int tid)
{
    uint32_t st = sbase + stage_i * K2_STG;
    #pragma unroll
    for (int it = 0; it < 4; it++) {
        int idx = it * 256 + tid;
        int r = idx >> 3, q = idx & 7;
        uint32_t sw = sw128((uint32_t)(r * 128 + q * 16));
        cp16(st + sw, A + (size_t)(i0 + r) * NDIM + k0 + q * 8);
    }
    #pragma unroll
    for (int it = 0; it < 2; it++) {
        int idx = it * 256 + tid;
        int r = idx >> 3, q = idx & 7;
        uint32_t sw = sw128((uint32_t)(r * 128 + q * 16));
        cp16(st + K2_AP + sw, B + (size_t)(j0 + r) * NDIM + k0 + q * 8);
    }
    CP_COMMIT();
}

__global__ __launch_bounds__(256, 3)
void k2_tri_mma()
{
    extern __shared__ __align__(1024) char smc[];
    const uint32_t sbase = smem_u32(smc);
    const int tid = threadIdx.x;
    const int warp = tid >> 5;
    const uint32_t lane = tid & 31;
    const int c = blockIdx.z;
    const int i0 = blockIdx.x * 128, j0 = blockIdx.y * 64;

    const __half* __restrict__ A = g_L16 + (size_t)c * NN;
    const __half* __restrict__ B = g_R16 + (size_t)c * NN;
    float* __restrict__ Tc = g_T + (size_t)c * NN;

    const int wm = (warp >> 1) * 32;
    const int wn = (warp & 1) * 32;

    const uint32_t a_row = (lane & 7) + ((lane >> 3) & 1) * 8;
    const uint32_t a_kb  = (lane >> 4) * 16;
    const uint32_t b_row = (lane & 7) + ((lane >> 4) & 1) * 8;
    const uint32_t b_kb  = ((lane >> 3) & 1) * 16;

    float acc[2][4][4];
    #pragma unroll
    for (int mt = 0; mt < 2; mt++)
        #pragma unroll
        for (int nt = 0; nt < 4; nt++)
            #pragma unroll
            for (int q = 0; q < 4; q++) acc[mt][nt][q] = 0.0f;

    k2_prefetch(sbase, 0, A, B, i0, j0, 0, tid);
    k2_prefetch(sbase, 1, A, B, i0, j0, 64, tid);

    #pragma unroll 1
    for (int ch = 0; ch < 8; ch++) {
        if (ch == 7) { CP_WAIT0(); } else { CP_WAIT1(); }
        __syncthreads();
        if (ch + 2 < 8)
            k2_prefetch(sbase, (ch + 2) % 3, A, B, i0, j0, (ch + 2) * 64, tid);

        uint32_t st = sbase + (ch % 3) * K2_STG;
        uint32_t sA = st, sB = st + K2_AP;

        #pragma unroll
        for (int ks = 0; ks < 4; ks++) {
            uint32_t kb = ks * 32;
            uint32_t a[2][4];
            #pragma unroll
            for (int mt = 0; mt < 2; mt++) {
                uint32_t sw = sw128((uint32_t)((wm + mt * 16 + a_row) * 128) + kb + a_kb);
                ldm_x4(a[mt], sA + sw);
            }
            #pragma unroll
            for (int ng = 0; ng < 2; ng++) {
                uint32_t sw = sw128((uint32_t)((wn + ng * 16 + b_row) * 128) + kb + b_kb);
                uint32_t b[4];
                ldm_x4(b, sB + sw);
                #pragma unroll
                for (int mt = 0; mt < 2; mt++) {
                    #pragma unroll
                    for (int h = 0; h < 2; h++) {
                        mma16816h(acc[mt][ng * 2 + h], a[mt], b[h * 2], b[h * 2 + 1]);
                    }
                }
            }
        }
        __syncthreads();
    }

    const int rbase = i0 + wm + (int)(lane >> 2);
    const int cbase = j0 + wn + 2 * (int)(lane & 3);
    #pragma unroll
    for (int mt = 0; mt < 2; mt++) {
        #pragma unroll
        for (int nt = 0; nt < 4; nt++) {
            float* cc = acc[mt][nt];
            int col = cbase + nt * 8;
            int r1 = rbase + mt * 16;
            *reinterpret_cast<float2*>(&Tc[(size_t)r1 * NDIM + col])       = make_float2(cc[0], cc[1]);
            *reinterpret_cast<float2*>(&Tc[(size_t)(r1 + 8) * NDIM + col]) = make_float2(cc[2], cc[3]);
        }
    }
}

// ---------------------------------------------------------------------------
// Kernel 3 (HMMA): 64 rows x 128 cols per CTA, two 64-col W passes, 2 CTAs/SM.
// ---------------------------------------------------------------------------
#define K3_T_OFF   0
#define K3_A_OFF   33792
#define K3_W_OFF   66560
#define K3_SMEM    99328

__device__ __forceinline__ void k3_loadW(uint32_t sbase, int ch0, int tid) {
    #pragma unroll
    for (int it = 0; it < 8; it++) {
        int u = it * 256 + tid;
        int p = u >> 9; int idx = u & 511;
        int row = idx >> 3, q = idx & 7;
        int pl = p >> 1, kc = p & 1;
        const __nv_bfloat16* src = (pl == 0 ? g_Wo_bf : g_Wp_bf) + (size_t)(ch0 + row) * 128 + kc * 64 + q * 8;
        cp16(sbase + K3_W_OFF + p * 8192 + sw128((uint32_t)(row * 128 + q * 16)), src);
    }
    CP_COMMIT();
}

__global__ __launch_bounds__(256, 2)
void k3_mma(const float* __restrict__ ogb, const float* __restrict__ ln2w,
            const float* __restrict__ ln2b, const float* __restrict__ outb,
            float* __restrict__ out)
{
    extern __shared__ __align__(1024) char smc[];
    const uint32_t sbase = smem_u32(smc);
    float* s_t = reinterpret_cast<float*>(smc + K3_T_OFF);   // [64][132]

    const int tid = threadIdx.x;
    const int warp = tid >> 5;
    const uint32_t lane = tid & 31;
    const int r0 = blockIdx.x * 64;

    k3_loadW(sbase, 0, tid);

    #pragma unroll
    for (int it = 0; it < 8; it++) {
        int u = it * 256 + tid;
        int cch = u >> 4;
        int q = u & 15;
        float4 v = *reinterpret_cast<const float4*>(g_T + (size_t)cch * NN + r0 + q * 4);
        s_t[(q * 4 + 0) * 132 + cch] = v.x;
        s_t[(q * 4 + 1) * 132 + cch] = v.y;
        s_t[(q * 4 + 2) * 132 + cch] = v.z;
        s_t[(q * 4 + 3) * 132 + cch] = v.w;
    }
    __syncthreads();

    {
        const int c4 = lane * 4;
        const int kc = lane >> 4;
        const uint32_t kb = (lane & 15) * 8;
        float4 w4 = *reinterpret_cast<const float4*>(ln2w + c4);
        float4 b4 = *reinterpret_cast<const float4*>(ln2b + c4);
        #pragma unroll 1
        for (int rr = 0; rr < 8; rr++) {
            int rloc = warp * 8 + rr;
            float4 v = *reinterpret_cast<float4*>(&s_t[rloc * 132 + c4]);
            float s  = v.x + v.y + v.z + v.w;
            float s2 = v.x * v.x + v.y * v.y + v.z * v.z + v.w * v.w;
            #pragma unroll
            for (int o = 16; o; o >>= 1) {
                s  += __shfl_xor_sync(0xffffffffu, s, o);
                s2 += __shfl_xor_sync(0xffffffffu, s2, o);
            }
            float m = s * 0.0078125f;
            float var = fmaf(-m, m, s2 * 0.0078125f);
            float rstd = rsqrtf(var + 1e-5f);
            float zn[4] = {
                (v.x - m) * rstd * w4.x + b4.x,
                (v.y - m) * rstd * w4.y + b4.y,
                (v.z - m) * rstd * w4.z + b4.z,
                (v.w - m) * rstd * w4.w + b4.w };
            uint32_t sw = sw128((uint32_t)(rloc * 128) + kb);
            *reinterpret_cast<uint2*>(smc + K3_A_OFF + (0*2 + kc) * 8192 + sw) =
                make_uint2(pack_bf2(v.x, v.y), pack_bf2(v.z, v.w));
            *reinterpret_cast<uint2*>(smc + K3_A_OFF + (1*2 + kc) * 8192 + sw) =
                make_uint2(pack_bf2(zn[0], zn[1]), pack_bf2(zn[2], zn[3]));
        }
    }

    const int wm = (warp >> 1) * 16;
    const int wn = (warp & 1) * 32;

    const uint32_t a_row = (lane & 7) + ((lane >> 3) & 1) * 8;
    const uint32_t a_kb  = (lane >> 4) * 16;
    const uint32_t b_row = (lane & 7) + ((lane >> 4) & 1) * 8;
    const uint32_t b_kb  = ((lane >> 3) & 1) * 16;

    #pragma unroll 1
    for (int hh = 0; hh < 2; hh++) {
        const int ch0 = hh * 64;
        CP_WAIT0();
        __syncthreads();

        float accg[4][4], accz[4][4];
        #pragma unroll
        for (int nt = 0; nt < 4; nt++)
            #pragma unroll
            for (int q = 0; q < 4; q++) { accg[nt][q] = 0.f; accz[nt][q] = 0.f; }

        #pragma unroll
        for (int kc = 0; kc < 2; kc++) {
            #pragma unroll
            for (int ks = 0; ks < 4; ks++) {
                uint32_t kb = ks * 32;
                uint32_t ag[4], az[4];
                uint32_t swa = sw128((uint32_t)((wm + a_row) * 128) + kb + a_kb);
                ldm_x4(ag, sbase + K3_A_OFF + (0*2 + kc) * 8192 + swa);
                ldm_x4(az, sbase + K3_A_OFF + (1*2 + kc) * 8192 + swa);
                #pragma unroll
                for (int ng = 0; ng < 2; ng++) {
                    uint32_t swb = sw128((uint32_t)((wn + ng * 16 + b_row) * 128) + kb + b_kb);
                    uint32_t wo[4], wp[4];
                    ldm_x4(wo, sbase + K3_W_OFF + (0*2 + kc) * 8192 + swb);
                    ldm_x4(wp, sbase + K3_W_OFF + (1*2 + kc) * 8192 + swb);
                    #pragma unroll
                    for (int h = 0; h < 2; h++) {
                        mma16816(accg[ng * 2 + h], ag, wo[h*2], wo[h*2+1]);
                        mma16816(accz[ng * 2 + h], az, wp[h*2], wp[h*2+1]);
                    }
                }
            }
        }
        __syncthreads();
        if (hh == 0) k3_loadW(sbase, 64, tid);

        {
            int rl0 = wm + (int)(lane >> 2);
            #pragma unroll
            for (int nt = 0; nt < 4; nt++) {
                int dl = wn + nt * 8 + 2 * (int)(lane & 3);
                int d = ch0 + dl;
                float ob0 = ogb[d],  ob1 = ogb[d + 1];
                float ub0 = outb[d], ub1 = outb[d + 1];
                float* cg = accg[nt];
                float* cz = accz[nt];
                float2 t0 = *reinterpret_cast<float2*>(&s_t[rl0 * 132 + d]);
                float2 t1 = *reinterpret_cast<float2*>(&s_t[(rl0 + 8) * 132 + d]);
                float2 o0, o1;
                o0.x = t0.x + sigmoidf_(cg[0] + ob0) * (cz[0] + ub0);
                o0.y = t0.y + sigmoidf_(cg[1] + ob1) * (cz[1] + ub1);
                o1.x = t1.x + sigmoidf_(cg[2] + ob0) * (cz[2] + ub0);
                o1.y = t1.y + sigmoidf_(cg[3] + ob1) * (cz[3] + ub1);
                *reinterpret_cast<float2*>(&out[(size_t)(r0 + rl0) * DDIM + d])     = o0;
                *reinterpret_cast<float2*>(&out[(size_t)(r0 + rl0 + 8) * DDIM + d]) = o1;
            }
        }
    }
}

// ---------------------------------------------------------------------------
extern "C" void kernel_launch(void* const* d_in, const int* in_sizes, int n_in,
                              void* d_out, int out_size)
{
    const float* Z     = (const float*)d_in[0];
    const float* mask  = (const float*)d_in[1];
    const float* ln1w  = (const float*)d_in[2];
    const float* ln1b  = (const float*)d_in[3];
    const float* lrpw  = (const float*)d_in[4];
    const float* lrpb  = (const float*)d_in[5];
    const float* gatew = (const float*)d_in[6];
    const float* gateb = (const float*)d_in[7];
    const float* ogw   = (const float*)d_in[8];
    const float* ogb   = (const float*)d_in[9];
    const float* ln2w  = (const float*)d_in[10];
    const float* ln2b  = (const float*)d_in[11];
    const float* opw   = (const float*)d_in[12];
    const float* outb  = (const float*)d_in[13];
    float* out = (float*)d_out;

    cudaFuncSetAttribute(k1_mma,     cudaFuncAttributeMaxDynamicSharedMemorySize, K1_SMEM);
    cudaFuncSetAttribute(k2_tri_mma, cudaFuncAttributeMaxDynamicSharedMemorySize, K2_SMEM);
    cudaFuncSetAttribute(k3_mma,     cudaFuncAttributeMaxDynamicSharedMemorySize, K3_SMEM);

    k0_wprep<<<128, 256>>>(lrpw, gatew, ogw, opw);

    k1_mma<<<NN / 128, 256, K1_SMEM>>>(Z, mask, ln1w, ln1b, lrpb, gateb);

    dim3 g2(4, 8, 128);
    k2_tri_mma<<<g2, 256, K2_SMEM>>>();

    k3_mma<<<NN / 64, 256, K3_SMEM>>>(ogb, ln2w, ln2b, outb, out);
}

// round 13
// speedup vs baseline: 7.1045x; 1.1374x over previous
#include <cuda_runtime.h>
#include <cuda_bf16.h>
#include <cuda_fp16.h>
#include <cstdint>

#define NDIM 512
#define DDIM 128
#define NN (NDIM*NDIM)

// Scratch (allocation-free rule: __device__ globals)
__device__ __half g_L16[(size_t)DDIM * NN];    // [c][i][k] fp16
__device__ __half g_R16[(size_t)DDIM * NN];    // [c][j][k] fp16
__device__ float g_T[(size_t)DDIM * NN];       // [c][i][j]
// fp16 weights for stage-1 (prepped by k0): lrp split hi/lo, gate single
__device__ __half g_Wl_h16[256 * 128];
__device__ __half g_Wl_l16[256 * 128];
__device__ __half g_Wg_16 [256 * 128];
// bf16 weights for stage-2 (og / op)
__device__ __nv_bfloat16 g_Wo_bf[128 * 128];
__device__ __nv_bfloat16 g_Wp_bf[128 * 128];

__device__ __forceinline__ float sigmoidf_(float x) {
    return 1.0f / (1.0f + __expf(-x));
}

__device__ __forceinline__ uint32_t smem_u32(const void* p) {
    uint32_t a;
    asm("{ .reg .u64 t; cvta.to.shared.u64 t, %1; cvt.u32.u64 %0, t; }" : "=r"(a) : "l"(p));
    return a;
}

__device__ __forceinline__ uint32_t sw128(uint32_t bo) {
    return bo ^ ((bo >> 3) & 0x70);
}

__device__ __forceinline__ void cp16(uint32_t dst, const void* src) {
    asm volatile("cp.async.cg.shared.global [%0], [%1], 16;" :: "r"(dst), "l"(src) : "memory");
}
#define CP_COMMIT() asm volatile("cp.async.commit_group;" ::: "memory")
#define CP_WAIT0()  asm volatile("cp.async.wait_group 0;" ::: "memory")
#define CP_WAIT1()  asm volatile("cp.async.wait_group 1;" ::: "memory")

__device__ __forceinline__ void ldm_x4(uint32_t r[4], uint32_t addr) {
    asm volatile("ldmatrix.sync.aligned.m8n8.x4.shared.b16 {%0,%1,%2,%3}, [%4];"
        : "=r"(r[0]), "=r"(r[1]), "=r"(r[2]), "=r"(r[3]) : "r"(addr));
}

// bf16 MMA (k3)
__device__ __forceinline__ void mma16816(float c[4], const uint32_t a[4],
                                         uint32_t b0, uint32_t b1) {
    asm volatile("mma.sync.aligned.m16n8k16.row.col.f32.bf16.bf16.f32 "
        "{%0,%1,%2,%3}, {%4,%5,%6,%7}, {%8,%9}, {%0,%1,%2,%3};"
        : "+f"(c[0]), "+f"(c[1]), "+f"(c[2]), "+f"(c[3])
        : "r"(a[0]), "r"(a[1]), "r"(a[2]), "r"(a[3]), "r"(b0), "r"(b1));
}

// fp16 MMA (k1/k2)
__device__ __forceinline__ void mma16816h(float c[4], const uint32_t a[4],
                                          uint32_t b0, uint32_t b1) {
    asm volatile("mma.sync.aligned.m16n8k16.row.col.f32.f16.f16.f32 "
        "{%0,%1,%2,%3}, {%4,%5,%6,%7}, {%8,%9}, {%0,%1,%2,%3};"
        : "+f"(c[0]), "+f"(c[1]), "+f"(c[2]), "+f"(c[3])
        : "r"(a[0]), "r"(a[1]), "r"(a[2]), "r"(a[3]), "r"(b0), "r"(b1));
}

// single fp16 pack (bits in low 16)
__device__ __forceinline__ uint32_t pack_h1(float v) {
    __half h = __float2half(v);
    return (uint32_t)*reinterpret_cast<unsigned short*>(&h);
}

__device__ __forceinline__ uint32_t pack_h2(float a, float b) {
    __half2 h = __floats2half2_rn(a, b);
    return *reinterpret_cast<uint32_t*>(&h);
}

__device__ __forceinline__ uint32_t pack_bf2(float a, float b) {
    __nv_bfloat16 h0 = __float2bfloat16(a);
    __nv_bfloat16 h1 = __float2bfloat16(b);
    return (uint32_t)*reinterpret_cast<unsigned short*>(&h0) |
           ((uint32_t)*reinterpret_cast<unsigned short*>(&h1) << 16);
}

// ---------------------------------------------------------------------------
// Kernel 0: weight prep (fp16 split lrp, fp16 gate, bf16 og/op)
// ---------------------------------------------------------------------------
__global__ void k0_wprep(const float* __restrict__ lrpw, const float* __restrict__ gatew,
                         const float* __restrict__ ogw,  const float* __restrict__ opw)
{
    int i = blockIdx.x * blockDim.x + threadIdx.x;
    if (i < 256 * 128) {
        float v = lrpw[i];
        __half h = __float2half(v);
        g_Wl_h16[i] = h;
        g_Wl_l16[i] = __float2half(v - __half2float(h));
        g_Wg_16[i] = __float2half(gatew[i]);
    }
    if (i < 128 * 128) {
        g_Wo_bf[i] = __float2bfloat16(ogw[i]);
        g_Wp_bf[i] = __float2bfloat16(opw[i]);
    }
}

// ---------------------------------------------------------------------------
// Kernel 1 (fp16 HMMA): LN1 + lrp (2-prod) / gate (1-prod) -> fp16 L / R
// 32-channel c-tiles (8 tiles). smem: A 32KB | W 24KB (stage 16.9K aliases W)
// 56KB -> 3 CTAs/SM
// ---------------------------------------------------------------------------
#define K1_A_OFF   0
#define K1_W_OFF   32768
#define K1_SMEM    57344

__global__ __launch_bounds__(256, 3)
void k1_mma(const float* __restrict__ Z, const float* __restrict__ mask,
            const float* __restrict__ ln1w, const float* __restrict__ ln1b,
            const float* __restrict__ lrpb, const float* __restrict__ gateb)
{
    extern __shared__ __align__(1024) char smc[];
    const uint32_t sbase = smem_u32(smc);
    uint32_t* stage = reinterpret_cast<uint32_t*>(smc + K1_W_OFF);   // aliases W planes

    const int tid = threadIdx.x;
    const int warp = tid >> 5;
    const uint32_t lane = tid & 31;
    const int r0 = blockIdx.x * 128;

    // ---- Phase A: load Z rows, LN1, single fp16 plane (2 k-chunks) ----
    {
        const int k4 = lane * 4;
        const int kc = lane >> 4;
        const uint32_t kb = (lane & 15) * 8;
        float4 w4 = *reinterpret_cast<const float4*>(ln1w + k4);
        float4 b4 = *reinterpret_cast<const float4*>(ln1b + k4);
        #pragma unroll 2
        for (int rr = 0; rr < 16; rr++) {
            int rloc = warp * 16 + rr;
            float4 v = *reinterpret_cast<const float4*>(Z + (size_t)(r0 + rloc) * DDIM + k4);
            float s  = v.x + v.y + v.z + v.w;
            float s2 = v.x * v.x + v.y * v.y + v.z * v.z + v.w * v.w;
            #pragma unroll
            for (int o = 16; o; o >>= 1) {
                s  += __shfl_xor_sync(0xffffffffu, s, o);
                s2 += __shfl_xor_sync(0xffffffffu, s2, o);
            }
            float m = s * 0.0078125f;
            float var = fmaf(-m, m, s2 * 0.0078125f);
            float rstd = rsqrtf(var + 1e-5f);
            float zn[4] = {
                (v.x - m) * rstd * w4.x + b4.x,
                (v.y - m) * rstd * w4.y + b4.y,
                (v.z - m) * rstd * w4.z + b4.z,
                (v.w - m) * rstd * w4.w + b4.w };
            uint32_t sw = sw128((uint32_t)(rloc * 128) + kb);
            *reinterpret_cast<uint2*>(smc + K1_A_OFF + kc * 16384 + sw) =
                make_uint2(pack_h2(zn[0], zn[1]), pack_h2(zn[2], zn[3]));
        }
    }
    __syncthreads();

    const int wm = (warp >> 1) * 32;     // 0..96
    const int wn = (warp & 1) * 16;      // 0/16 within 32-channel tile

    const uint32_t a_row = (lane & 7) + ((lane >> 3) & 1) * 8;
    const uint32_t a_kb  = (lane >> 4) * 16;
    const uint32_t b_row = (lane & 7) + ((lane >> 4) & 1) * 8;
    const uint32_t b_kb  = ((lane >> 3) & 1) * 16;

    const __half* wtab[3] = { g_Wl_h16, g_Wl_l16, g_Wg_16 };

    #pragma unroll 1
    for (int ct = 0; ct < 8; ct++) {
        const int cbase = ct * 32;

        // ---- load 6 W planes (3 mats x 2 kc), 32 rows x 128B each ----
        #pragma unroll
        for (int it = 0; it < 6; it++) {
            int u = it * 256 + tid;
            int p = u >> 8; int idx = u & 255;
            int row = idx >> 3, q = idx & 7;
            int shl = p >> 1, kc = p & 1;
            const __half* src = wtab[shl] + (size_t)(cbase + row) * 128 + kc * 64 + q * 8;
            cp16(sbase + K1_W_OFF + p * 4096 + sw128((uint32_t)(row * 128 + q * 16)), src);
        }
        CP_COMMIT();
        CP_WAIT0();
        __syncthreads();

        float accl[2][2][4], accg[2][2][4];
        #pragma unroll
        for (int mt = 0; mt < 2; mt++)
            #pragma unroll
            for (int nt = 0; nt < 2; nt++)
                #pragma unroll
                for (int q = 0; q < 4; q++) { accl[mt][nt][q] = 0.f; accg[mt][nt][q] = 0.f; }

        #pragma unroll
        for (int kc = 0; kc < 2; kc++) {
            #pragma unroll
            for (int ks = 0; ks < 4; ks++) {
                uint32_t kb = ks * 32;
                uint32_t a[2][4];
                #pragma unroll
                for (int mt = 0; mt < 2; mt++) {
                    uint32_t sw = sw128((uint32_t)((wm + mt * 16 + a_row) * 128) + kb + a_kb);
                    ldm_x4(a[mt], sbase + K1_A_OFF + kc * 16384 + sw);
                }
                uint32_t swb = sw128((uint32_t)((wn + b_row) * 128) + kb + b_kb);
                uint32_t wlh[4], wll[4], wg[4];
                ldm_x4(wlh, sbase + K1_W_OFF + (0 + kc) * 4096 + swb);
                ldm_x4(wll, sbase + K1_W_OFF + (2 + kc) * 4096 + swb);
                ldm_x4(wg,  sbase + K1_W_OFF + (4 + kc) * 4096 + swb);
                #pragma unroll
                for (int mt = 0; mt < 2; mt++) {
                    #pragma unroll
                    for (int h = 0; h < 2; h++) {
                        float* cl = accl[mt][h];
                        float* cg = accg[mt][h];
                        mma16816h(cl, a[mt], wlh[h*2], wlh[h*2+1]);
                        mma16816h(cl, a[mt], wll[h*2], wll[h*2+1]);
                        mma16816h(cg, a[mt], wg[h*2],  wg[h*2+1]);
                    }
                }
            }
        }
        __syncthreads();   // all warps done reading W before stage (aliased) writes

        #pragma unroll
        for (int mt = 0; mt < 2; mt++) {
            int rl0 = wm + mt * 16 + (int)(lane >> 2);
            float m0 = mask[r0 + rl0];
            float m1 = mask[r0 + rl0 + 8];
            #pragma unroll
            for (int nt = 0; nt < 2; nt++) {
                int cl0 = wn + nt * 8 + 2 * (int)(lane & 3);
                float lb0 = lrpb[cbase + cl0],  lb1 = lrpb[cbase + cl0 + 1];
                float gb0 = gateb[cbase + cl0], gb1 = gateb[cbase + cl0 + 1];
                float* vl = accl[mt][nt];
                float* vg = accg[mt][nt];
                stage[(cl0    ) * 132 + rl0    ] = pack_h1((vl[0] + lb0) * m0 * sigmoidf_(vg[0] + gb0));
                stage[(cl0 + 1) * 132 + rl0    ] = pack_h1((vl[1] + lb1) * m0 * sigmoidf_(vg[1] + gb1));
                stage[(cl0    ) * 132 + rl0 + 8] = pack_h1((vl[2] + lb0) * m1 * sigmoidf_(vg[2] + gb0));
                stage[(cl0 + 1) * 132 + rl0 + 8] = pack_h1((vl[3] + lb1) * m1 * sigmoidf_(vg[3] + gb1));
            }
        }
        __syncthreads();

        {
            int c_loc = tid >> 3;            // 0..31
            int seg = tid & 7;               // 8 segments of 16 rows
            int cg = cbase + c_loc;
            __half* dst = (cg < 128) ? (g_L16 + (size_t)cg * NN) : (g_R16 + (size_t)(cg - 128) * NN);
            int rb = seg * 16;
            const uint32_t* srow = &stage[c_loc * 132 + rb];
            #pragma unroll
            for (int blk = 0; blk < 2; blk++) {
                uint32_t hw[4];
                #pragma unroll
                for (int q = 0; q < 4; q++) {
                    uint32_t p0 = srow[blk * 8 + q * 2];
                    uint32_t p1 = srow[blk * 8 + q * 2 + 1];
                    hw[q] = (p0 & 0xffffu) | (p1 << 16);
                }
                *reinterpret_cast<uint4*>(dst + r0 + rb + blk * 8) = make_uint4(hw[0], hw[1], hw[2], hw[3]);
            }
        }
        __syncthreads();
    }
}

// ---------------------------------------------------------------------------
// Kernel 2: fp16 1-product mma.sync GEMM  T_c = L_c @ R_c^T
// CTA tile 128(i) x 64(j), K-chunk 64, 3-stage, 3 CTAs/SM.
// ---------------------------------------------------------------------------
#define K2_AP 16384
#define K2_BP 8192
#define K2_STG (K2_AP + K2_BP)       // 24576
#define K2_SMEM (3 * K2_STG)         // 73728

__device__ __forceinline__ void k2_prefetch(uint32_t sbase, int stage_i,
    const __half* A, const __half* B,
    int i0, int j0, int k0, int tid)
{
    uint32_t st = sbase + stage_i * K2_STG;
    #pragma unroll
    for (int it = 0; it < 4; it++) {
        int idx = it * 256 + tid;
        int r = idx >> 3, q = idx & 7;
        uint32_t sw = sw128((uint32_t)(r * 128 + q * 16));
        cp16(st + sw, A + (size_t)(i0 + r) * NDIM + k0 + q * 8);
    }
    #pragma unroll
    for (int it = 0; it < 2; it++) {
        int idx = it * 256 + tid;
        int r = idx >> 3, q = idx & 7;
        uint32_t sw = sw128((uint32_t)(r * 128 + q * 16));
        cp16(st + K2_AP + sw, B + (size_t)(j0 + r) * NDIM + k0 + q * 8);
    }
    CP_COMMIT();
}

__global__ __launch_bounds__(256, 3)
void k2_tri_mma()
{
    extern __shared__ __align__(1024) char smc[];
    const uint32_t sbase = smem_u32(smc);
    const int tid = threadIdx.x;
    const int warp = tid >> 5;
    const uint32_t lane = tid & 31;
    const int c = blockIdx.z;
    const int i0 = blockIdx.x * 128, j0 = blockIdx.y * 64;

    const __half* __restrict__ A = g_L16 + (size_t)c * NN;
    const __half* __restrict__ B = g_R16 + (size_t)c * NN;
    float* __restrict__ Tc = g_T + (size_t)c * NN;

    const int wm = (warp >> 1) * 32;
    const int wn = (warp & 1) * 32;

    const uint32_t a_row = (lane & 7) + ((lane >> 3) & 1) * 8;
    const uint32_t a_kb  = (lane >> 4) * 16;
    const uint32_t b_row = (lane & 7) + ((lane >> 4) & 1) * 8;
    const uint32_t b_kb  = ((lane >> 3) & 1) * 16;

    float acc[2][4][4];
    #pragma unroll
    for (int mt = 0; mt < 2; mt++)
        #pragma unroll
        for (int nt = 0; nt < 4; nt++)
            #pragma unroll
            for (int q = 0; q < 4; q++) acc[mt][nt][q] = 0.0f;

    k2_prefetch(sbase, 0, A, B, i0, j0, 0, tid);
    k2_prefetch(sbase, 1, A, B, i0, j0, 64, tid);

    #pragma unroll 1
    for (int ch = 0; ch < 8; ch++) {
        if (ch == 7) { CP_WAIT0(); } else { CP_WAIT1(); }
        __syncthreads();
        if (ch + 2 < 8)
            k2_prefetch(sbase, (ch + 2) % 3, A, B, i0, j0, (ch + 2) * 64, tid);

        uint32_t st = sbase + (ch % 3) * K2_STG;
        uint32_t sA = st, sB = st + K2_AP;

        #pragma unroll
        for (int ks = 0; ks < 4; ks++) {
            uint32_t kb = ks * 32;
            uint32_t a[2][4];
            #pragma unroll
            for (int mt = 0; mt < 2; mt++) {
                uint32_t sw = sw128((uint32_t)((wm + mt * 16 + a_row) * 128) + kb + a_kb);
                ldm_x4(a[mt], sA + sw);
            }
            #pragma unroll
            for (int ng = 0; ng < 2; ng++) {
                uint32_t sw = sw128((uint32_t)((wn + ng * 16 + b_row) * 128) + kb + b_kb);
                uint32_t b[4];
                ldm_x4(b, sB + sw);
                #pragma unroll
                for (int mt = 0; mt < 2; mt++) {
                    #pragma unroll
                    for (int h = 0; h < 2; h++) {
                        mma16816h(acc[mt][ng * 2 + h], a[mt], b[h * 2], b[h * 2 + 1]);
                    }
                }
            }
        }
        __syncthreads();
    }

    const int rbase = i0 + wm + (int)(lane >> 2);
    const int cbase = j0 + wn + 2 * (int)(lane & 3);
    #pragma unroll
    for (int mt = 0; mt < 2; mt++) {
        #pragma unroll
        for (int nt = 0; nt < 4; nt++) {
            float* cc = acc[mt][nt];
            int col = cbase + nt * 8;
            int r1 = rbase + mt * 16;
            *reinterpret_cast<float2*>(&Tc[(size_t)r1 * NDIM + col])       = make_float2(cc[0], cc[1]);
            *reinterpret_cast<float2*>(&Tc[(size_t)(r1 + 8) * NDIM + col]) = make_float2(cc[2], cc[3]);
        }
    }
}

// ---------------------------------------------------------------------------
// Kernel 3 (HMMA): 64 rows x 128 cols per CTA, two 64-col W passes, 2 CTAs/SM.
// ---------------------------------------------------------------------------
#define K3_T_OFF   0
#define K3_A_OFF   33792
#define K3_W_OFF   66560
#define K3_SMEM    99328

__device__ __forceinline__ void k3_loadW(uint32_t sbase, int ch0, int tid) {
    #pragma unroll
    for (int it = 0; it < 8; it++) {
        int u = it * 256 + tid;
        int p = u >> 9; int idx = u & 511;
        int row = idx >> 3, q = idx & 7;
        int pl = p >> 1, kc = p & 1;
        const __nv_bfloat16* src = (pl == 0 ? g_Wo_bf : g_Wp_bf) + (size_t)(ch0 + row) * 128 + kc * 64 + q * 8;
        cp16(sbase + K3_W_OFF + p * 8192 + sw128((uint32_t)(row * 128 + q * 16)), src);
    }
    CP_COMMIT();
}

__global__ __launch_bounds__(256, 2)
void k3_mma(const float* __restrict__ ogb, const float* __restrict__ ln2w,
            const float* __restrict__ ln2b, const float* __restrict__ outb,
            float* __restrict__ out)
{
    extern __shared__ __align__(1024) char smc[];
    const uint32_t sbase = smem_u32(smc);
    float* s_t = reinterpret_cast<float*>(smc + K3_T_OFF);   // [64][132]

    const int tid = threadIdx.x;
    const int warp = tid >> 5;
    const uint32_t lane = tid & 31;
    const int r0 = blockIdx.x * 64;

    k3_loadW(sbase, 0, tid);

    #pragma unroll
    for (int it = 0; it < 8; it++) {
        int u = it * 256 + tid;
        int cch = u >> 4;
        int q = u & 15;
        float4 v = *reinterpret_cast<const float4*>(g_T + (size_t)cch * NN + r0 + q * 4);
        s_t[(q * 4 + 0) * 132 + cch] = v.x;
        s_t[(q * 4 + 1) * 132 + cch] = v.y;
        s_t[(q * 4 + 2) * 132 + cch] = v.z;
        s_t[(q * 4 + 3) * 132 + cch] = v.w;
    }
    __syncthreads();

    {
        const int c4 = lane * 4;
        const int kc = lane >> 4;
        const uint32_t kb = (lane & 15) * 8;
        float4 w4 = *reinterpret_cast<const float4*>(ln2w + c4);
        float4 b4 = *reinterpret_cast<const float4*>(ln2b + c4);
        #pragma unroll 1
        for (int rr = 0; rr < 8; rr++) {
            int rloc = warp * 8 + rr;
            float4 v = *reinterpret_cast<float4*>(&s_t[rloc * 132 + c4]);
            float s  = v.x + v.y + v.z + v.w;
            float s2 = v.x * v.x + v.y * v.y + v.z * v.z + v.w * v.w;
            #pragma unroll
            for (int o = 16; o; o >>= 1) {
                s  += __shfl_xor_sync(0xffffffffu, s, o);
                s2 += __shfl_xor_sync(0xffffffffu, s2, o);
            }
            float m = s * 0.0078125f;
            float var = fmaf(-m, m, s2 * 0.0078125f);
            float rstd = rsqrtf(var + 1e-5f);
            float zn[4] = {
                (v.x - m) * rstd * w4.x + b4.x,
                (v.y - m) * rstd * w4.y + b4.y,
                (v.z - m) * rstd * w4.z + b4.z,
                (v.w - m) * rstd * w4.w + b4.w };
            uint32_t sw = sw128((uint32_t)(rloc * 128) + kb);
            *reinterpret_cast<uint2*>(smc + K3_A_OFF + (0*2 + kc) * 8192 + sw) =
                make_uint2(pack_bf2(v.x, v.y), pack_bf2(v.z, v.w));
            *reinterpret_cast<uint2*>(smc + K3_A_OFF + (1*2 + kc) * 8192 + sw) =
                make_uint2(pack_bf2(zn[0], zn[1]), pack_bf2(zn[2], zn[3]));
        }
    }

    const int wm = (warp >> 1) * 16;
    const int wn = (warp & 1) * 32;

    const uint32_t a_row = (lane & 7) + ((lane >> 3) & 1) * 8;
    const uint32_t a_kb  = (lane >> 4) * 16;
    const uint32_t b_row = (lane & 7) + ((lane >> 4) & 1) * 8;
    const uint32_t b_kb  = ((lane >> 3) & 1) * 16;

    #pragma unroll 1
    for (int hh = 0; hh < 2; hh++) {
        const int ch0 = hh * 64;
        CP_WAIT0();
        __syncthreads();

        float accg[4][4], accz[4][4];
        #pragma unroll
        for (int nt = 0; nt < 4; nt++)
            #pragma unroll
            for (int q = 0; q < 4; q++) { accg[nt][q] = 0.f; accz[nt][q] = 0.f; }

        #pragma unroll
        for (int kc = 0; kc < 2; kc++) {
            #pragma unroll
            for (int ks = 0; ks < 4; ks++) {
                uint32_t kb = ks * 32;
                uint32_t ag[4], az[4];
                uint32_t swa = sw128((uint32_t)((wm + a_row) * 128) + kb + a_kb);
                ldm_x4(ag, sbase + K3_A_OFF + (0*2 + kc) * 8192 + swa);
                ldm_x4(az, sbase + K3_A_OFF + (1*2 + kc) * 8192 + swa);
                #pragma unroll
                for (int ng = 0; ng < 2; ng++) {
                    uint32_t swb = sw128((uint32_t)((wn + ng * 16 + b_row) * 128) + kb + b_kb);
                    uint32_t wo[4], wp[4];
                    ldm_x4(wo, sbase + K3_W_OFF + (0*2 + kc) * 8192 + swb);
                    ldm_x4(wp, sbase + K3_W_OFF + (1*2 + kc) * 8192 + swb);
                    #pragma unroll
                    for (int h = 0; h < 2; h++) {
                        mma16816(accg[ng * 2 + h], ag, wo[h*2], wo[h*2+1]);
                        mma16816(accz[ng * 2 + h], az, wp[h*2], wp[h*2+1]);
                    }
                }
            }
        }
        __syncthreads();
        if (hh == 0) k3_loadW(sbase, 64, tid);

        {
            int rl0 = wm + (int)(lane >> 2);
            #pragma unroll
            for (int nt = 0; nt < 4; nt++) {
                int dl = wn + nt * 8 + 2 * (int)(lane & 3);
                int d = ch0 + dl;
                float ob0 = ogb[d],  ob1 = ogb[d + 1];
                float ub0 = outb[d], ub1 = outb[d + 1];
                float* cg = accg[nt];
                float* cz = accz[nt];
                float2 t0 = *reinterpret_cast<float2*>(&s_t[rl0 * 132 + d]);
                float2 t1 = *reinterpret_cast<float2*>(&s_t[(rl0 + 8) * 132 + d]);
                float2 o0, o1;
                o0.x = t0.x + sigmoidf_(cg[0] + ob0) * (cz[0] + ub0);
                o0.y = t0.y + sigmoidf_(cg[1] + ob1) * (cz[1] + ub1);
                o1.x = t1.x + sigmoidf_(cg[2] + ob0) * (cz[2] + ub0);
                o1.y = t1.y + sigmoidf_(cg[3] + ob1) * (cz[3] + ub1);
                *reinterpret_cast<float2*>(&out[(size_t)(r0 + rl0) * DDIM + d])     = o0;
                *reinterpret_cast<float2*>(&out[(size_t)(r0 + rl0 + 8) * DDIM + d]) = o1;
            }
        }
    }
}

// ---------------------------------------------------------------------------
extern "C" void kernel_launch(void* const* d_in, const int* in_sizes, int n_in,
                              void* d_out, int out_size)
{
    const float* Z     = (const float*)d_in[0];
    const float* mask  = (const float*)d_in[1];
    const float* ln1w  = (const float*)d_in[2];
    const float* ln1b  = (const float*)d_in[3];
    const float* lrpw  = (const float*)d_in[4];
    const float* lrpb  = (const float*)d_in[5];
    const float* gatew = (const float*)d_in[6];
    const float* gateb = (const float*)d_in[7];
    const float* ogw   = (const float*)d_in[8];
    const float* ogb   = (const float*)d_in[9];
    const float* ln2w  = (const float*)d_in[10];
    const float* ln2b  = (const float*)d_in[11];
    const float* opw   = (const float*)d_in[12];
    const float* outb  = (const float*)d_in[13];
    float* out = (float*)d_out;

    cudaFuncSetAttribute(k1_mma,     cudaFuncAttributeMaxDynamicSharedMemorySize, K1_SMEM);
    cudaFuncSetAttribute(k2_tri_mma, cudaFuncAttributeMaxDynamicSharedMemorySize, K2_SMEM);
    cudaFuncSetAttribute(k3_mma,     cudaFuncAttributeMaxDynamicSharedMemorySize, K3_SMEM);

    k0_wprep<<<128, 256>>>(lrpw, gatew, ogw, opw);

    k1_mma<<<NN / 128, 256, K1_SMEM>>>(Z, mask, ln1w, ln1b, lrpb, gateb);

    dim3 g2(4, 8, 128);
    k2_tri_mma<<<g2, 256, K2_SMEM>>>();

    k3_mma<<<NN / 64, 256, K3_SMEM>>>(ogb, ln2w, ln2b, outb, out);
}